// round 1
// baseline (speedup 1.0000x reference)
#include <cuda_runtime.h>
#include <math.h>

#define EMBD   1024
#define NH     16
#define DH     64
#define BATCH  2
#define SEQ    2048
#define M_TOT  (BATCH * SEQ)   // 4096
#define QKV_N  (3 * EMBD)      // 3072

// Scratch (allocation-free rule: __device__ globals)
__device__ float g_qkv [M_TOT * QKV_N];   // [B*S, 3*EMBD]
__device__ float g_attn[M_TOT * EMBD];    // [B*S, EMBD]

// ---------------------------------------------------------------------------
// NT GEMM with bias:  C[m,n] = sum_k A[m,k] * Bm[n,k] + bias[n]
// Both A and Bm are K-contiguous (row-major [M,K] / [N,K]).
// 128x128 block tile, BK=16, 256 threads, 8x8 per-thread micro-tile.
// Requires M%128==0, N%128==0, K%16==0 (true for all our shapes).
// ---------------------------------------------------------------------------
__global__ __launch_bounds__(256, 2)
void gemm_nt_bias(const float* __restrict__ A,
                  const float* __restrict__ Bm,
                  const float* __restrict__ bias,
                  float* __restrict__ C,
                  int M, int N, int K)
{
    __shared__ float As[16][128 + 4];
    __shared__ float Bs[16][128 + 4];

    const int tid = threadIdx.x;
    const int block_m = blockIdx.y * 128;
    const int block_n = blockIdx.x * 128;
    const int tx = tid & 15;          // 0..15  -> N direction
    const int ty = tid >> 4;          // 0..15  -> M direction

    float acc[8][8];
    #pragma unroll
    for (int i = 0; i < 8; i++)
        #pragma unroll
        for (int j = 0; j < 8; j++) acc[i][j] = 0.0f;

    for (int k0 = 0; k0 < K; k0 += 16) {
        // Load 128 rows x 16 k of A and Bm (512 float4 each); 2 float4/thread each.
        #pragma unroll
        for (int i = 0; i < 2; i++) {
            int idx = tid + i * 256;     // float4 index 0..511
            int row = idx >> 2;          // 4 float4 per row
            int k4  = idx & 3;
            float4 av = *reinterpret_cast<const float4*>(
                &A[(size_t)(block_m + row) * K + k0 + k4 * 4]);
            As[k4 * 4 + 0][row] = av.x;
            As[k4 * 4 + 1][row] = av.y;
            As[k4 * 4 + 2][row] = av.z;
            As[k4 * 4 + 3][row] = av.w;
            float4 bv = *reinterpret_cast<const float4*>(
                &Bm[(size_t)(block_n + row) * K + k0 + k4 * 4]);
            Bs[k4 * 4 + 0][row] = bv.x;
            Bs[k4 * 4 + 1][row] = bv.y;
            Bs[k4 * 4 + 2][row] = bv.z;
            Bs[k4 * 4 + 3][row] = bv.w;
        }
        __syncthreads();

        #pragma unroll
        for (int kk = 0; kk < 16; kk++) {
            float a[8], b[8];
            float4 a0 = *reinterpret_cast<const float4*>(&As[kk][ty * 8]);
            float4 a1 = *reinterpret_cast<const float4*>(&As[kk][ty * 8 + 4]);
            float4 b0 = *reinterpret_cast<const float4*>(&Bs[kk][tx * 8]);
            float4 b1 = *reinterpret_cast<const float4*>(&Bs[kk][tx * 8 + 4]);
            a[0]=a0.x; a[1]=a0.y; a[2]=a0.z; a[3]=a0.w;
            a[4]=a1.x; a[5]=a1.y; a[6]=a1.z; a[7]=a1.w;
            b[0]=b0.x; b[1]=b0.y; b[2]=b0.z; b[3]=b0.w;
            b[4]=b1.x; b[5]=b1.y; b[6]=b1.z; b[7]=b1.w;
            #pragma unroll
            for (int i = 0; i < 8; i++)
                #pragma unroll
                for (int j = 0; j < 8; j++)
                    acc[i][j] = fmaf(a[i], b[j], acc[i][j]);
        }
        __syncthreads();
    }

    #pragma unroll
    for (int i = 0; i < 8; i++) {
        int m = block_m + ty * 8 + i;
        #pragma unroll
        for (int j = 0; j < 8; j += 4) {
            int n = block_n + tx * 8 + j;
            float4 o;
            o.x = acc[i][j + 0] + bias[n + 0];
            o.y = acc[i][j + 1] + bias[n + 1];
            o.z = acc[i][j + 2] + bias[n + 2];
            o.w = acc[i][j + 3] + bias[n + 3];
            *reinterpret_cast<float4*>(&C[(size_t)m * N + n]) = o;
        }
    }
}

// ---------------------------------------------------------------------------
// Flash-attention (fp32, non-causal). One block = 64 query rows of one (b,h).
// 256 threads: thread (tr,tc) with tr=tid/16, tc=tid%16 owns a 4x4 tile
// for both S = Q K^T (rows tr*4.., cols tc*4..) and O += P V (rows tr*4..,
// d-cols tc*4..). Row reductions via shfl over the 16-lane tc group.
// ---------------------------------------------------------------------------
#define QTILE 64
#define KTILE 64
#define SM_STRIDE 65

__global__ __launch_bounds__(256, 2)
void attn_fwd(const float* __restrict__ qkv, float* __restrict__ out)
{
    extern __shared__ float sm[];
    float* Qs = sm;                         // [64][65]
    float* Ks = Qs + QTILE * SM_STRIDE;     // [64][65]
    float* Vs = Ks + KTILE * SM_STRIDE;     // [64][65]
    float* Ps = Vs + KTILE * SM_STRIDE;     // [64][65]

    const int tid = threadIdx.x;
    const int tr = tid >> 4;                // 0..15
    const int tc = tid & 15;                // 0..15
    const int q0 = blockIdx.x * QTILE;
    const int h  = blockIdx.y;
    const int b  = blockIdx.z;
    const size_t base = (size_t)b * SEQ * QKV_N;
    const float scale = 0.125f;             // 1/sqrt(64)

    // Load Q tile pre-scaled. 64x64 floats = 1024 float4, 4 per thread.
    #pragma unroll
    for (int i = 0; i < 4; i++) {
        int idx = tid + i * 256;
        int r   = idx >> 4;      // 16 float4 per row
        int c4  = idx & 15;
        float4 v = *reinterpret_cast<const float4*>(
            &qkv[base + (size_t)(q0 + r) * QKV_N + h * DH + c4 * 4]);
        Qs[r * SM_STRIDE + c4 * 4 + 0] = v.x * scale;
        Qs[r * SM_STRIDE + c4 * 4 + 1] = v.y * scale;
        Qs[r * SM_STRIDE + c4 * 4 + 2] = v.z * scale;
        Qs[r * SM_STRIDE + c4 * 4 + 3] = v.w * scale;
    }

    float o[4][4];
    #pragma unroll
    for (int i = 0; i < 4; i++)
        #pragma unroll
        for (int j = 0; j < 4; j++) o[i][j] = 0.0f;
    float m_i[4] = {-1e30f, -1e30f, -1e30f, -1e30f};
    float l_i[4] = {0.f, 0.f, 0.f, 0.f};

    for (int kt = 0; kt < SEQ / KTILE; kt++) {
        __syncthreads();   // previous iteration done with Ks/Vs
        // Load K and V tiles
        #pragma unroll
        for (int i = 0; i < 4; i++) {
            int idx = tid + i * 256;
            int r   = idx >> 4;
            int c4  = idx & 15;
            size_t rowoff = base + (size_t)(kt * KTILE + r) * QKV_N + h * DH + c4 * 4;
            float4 kv = *reinterpret_cast<const float4*>(&qkv[rowoff + EMBD]);
            Ks[r * SM_STRIDE + c4 * 4 + 0] = kv.x;
            Ks[r * SM_STRIDE + c4 * 4 + 1] = kv.y;
            Ks[r * SM_STRIDE + c4 * 4 + 2] = kv.z;
            Ks[r * SM_STRIDE + c4 * 4 + 3] = kv.w;
            float4 vv = *reinterpret_cast<const float4*>(&qkv[rowoff + 2 * EMBD]);
            Vs[r * SM_STRIDE + c4 * 4 + 0] = vv.x;
            Vs[r * SM_STRIDE + c4 * 4 + 1] = vv.y;
            Vs[r * SM_STRIDE + c4 * 4 + 2] = vv.z;
            Vs[r * SM_STRIDE + c4 * 4 + 3] = vv.w;
        }
        __syncthreads();

        // S = Q K^T : thread's 4x4 score tile
        float s[4][4];
        #pragma unroll
        for (int i = 0; i < 4; i++)
            #pragma unroll
            for (int j = 0; j < 4; j++) s[i][j] = 0.0f;
        #pragma unroll 8
        for (int d = 0; d < DH; d++) {
            float a[4], k[4];
            #pragma unroll
            for (int i = 0; i < 4; i++) a[i] = Qs[(tr * 4 + i) * SM_STRIDE + d];
            #pragma unroll
            for (int j = 0; j < 4; j++) k[j] = Ks[(tc * 4 + j) * SM_STRIDE + d];
            #pragma unroll
            for (int i = 0; i < 4; i++)
                #pragma unroll
                for (int j = 0; j < 4; j++)
                    s[i][j] = fmaf(a[i], k[j], s[i][j]);
        }

        // Online softmax (row reductions across the 16-lane tc group)
        #pragma unroll
        for (int i = 0; i < 4; i++) {
            float mx = fmaxf(fmaxf(s[i][0], s[i][1]), fmaxf(s[i][2], s[i][3]));
            #pragma unroll
            for (int off = 8; off >= 1; off >>= 1)
                mx = fmaxf(mx, __shfl_xor_sync(0xffffffffu, mx, off, 16));
            float m_new = fmaxf(m_i[i], mx);
            float rs = 0.0f;
            #pragma unroll
            for (int j = 0; j < 4; j++) {
                s[i][j] = __expf(s[i][j] - m_new);   // s now holds p
                rs += s[i][j];
            }
            #pragma unroll
            for (int off = 8; off >= 1; off >>= 1)
                rs += __shfl_xor_sync(0xffffffffu, rs, off, 16);
            float alpha = __expf(m_i[i] - m_new);
            l_i[i] = l_i[i] * alpha + rs;
            m_i[i] = m_new;
            #pragma unroll
            for (int j = 0; j < 4; j++) o[i][j] *= alpha;
            // stash P for the PV product (readers are in the same warp)
            #pragma unroll
            for (int j = 0; j < 4; j++)
                Ps[(tr * 4 + i) * SM_STRIDE + tc * 4 + j] = s[i][j];
        }
        __syncwarp();

        // O += P V : thread owns rows tr*4.. , d-cols tc*4..
        #pragma unroll 8
        for (int j = 0; j < KTILE; j++) {
            float p[4], v[4];
            #pragma unroll
            for (int i = 0; i < 4; i++) p[i] = Ps[(tr * 4 + i) * SM_STRIDE + j];
            #pragma unroll
            for (int dd = 0; dd < 4; dd++) v[dd] = Vs[j * SM_STRIDE + tc * 4 + dd];
            #pragma unroll
            for (int i = 0; i < 4; i++)
                #pragma unroll
                for (int dd = 0; dd < 4; dd++)
                    o[i][dd] = fmaf(p[i], v[dd], o[i][dd]);
        }
    }

    // Normalize and write to g_attn[b, q, h*64 + d]
    #pragma unroll
    for (int i = 0; i < 4; i++) {
        float inv = 1.0f / l_i[i];
        int q = q0 + tr * 4 + i;
        float4 ov;
        ov.x = o[i][0] * inv;
        ov.y = o[i][1] * inv;
        ov.z = o[i][2] * inv;
        ov.w = o[i][3] * inv;
        *reinterpret_cast<float4*>(
            &out[((size_t)b * SEQ + q) * EMBD + h * DH + tc * 4]) = ov;
    }
}

// ---------------------------------------------------------------------------
// Launch
// ---------------------------------------------------------------------------
extern "C" void kernel_launch(void* const* d_in, const int* in_sizes, int n_in,
                              void* d_out, int out_size)
{
    const float* x     = (const float*)d_in[0];  // [2,2048,1024]
    const float* W_in  = (const float*)d_in[1];  // [3072,1024]
    const float* b_in  = (const float*)d_in[2];  // [3072]
    const float* W_out = (const float*)d_in[3];  // [1024,1024]
    const float* b_out = (const float*)d_in[4];  // [1024]
    float* out = (float*)d_out;                  // [2,2048,1024]

    float* qkv;  cudaGetSymbolAddress((void**)&qkv,  g_qkv);
    float* attn; cudaGetSymbolAddress((void**)&attn, g_attn);

    // attention kernel needs 65 KB dynamic smem
    const int attn_smem = 4 * QTILE * SM_STRIDE * (int)sizeof(float);
    cudaFuncSetAttribute(attn_fwd, cudaFuncAttributeMaxDynamicSharedMemorySize,
                         attn_smem);

    // 1) qkv = x @ W_in^T + b_in
    {
        dim3 grid(QKV_N / 128, M_TOT / 128);
        gemm_nt_bias<<<grid, 256>>>(x, W_in, b_in, qkv, M_TOT, QKV_N, EMBD);
    }
    // 2) attention
    {
        dim3 grid(SEQ / QTILE, NH, BATCH);
        attn_fwd<<<grid, 256, attn_smem>>>(qkv, attn);
    }
    // 3) out = attn @ W_out^T + b_out
    {
        dim3 grid(EMBD / 128, M_TOT / 128);
        gemm_nt_bias<<<grid, 256>>>(attn, W_out, b_out, out, M_TOT, EMBD, EMBD);
    }
}

// round 3
// speedup vs baseline: 1.9114x; 1.9114x over previous
#include <cuda_runtime.h>
#include <cuda_bf16.h>
#include <cstdint>
#include <math.h>

#define EMBD   1024
#define NH     16
#define DH     64
#define BATCH  2
#define SEQ    2048
#define M_TOT  (BATCH * SEQ)   // 4096
#define QKV_N  (3 * EMBD)      // 3072

// ---------------------------------------------------------------------------
// Scratch (bf16 hi/lo pairs; allocation-free rule: __device__ globals)
// ---------------------------------------------------------------------------
__device__ __nv_bfloat16 g_xh [M_TOT * EMBD],  g_xl [M_TOT * EMBD];
__device__ __nv_bfloat16 g_wih[QKV_N * EMBD],  g_wil[QKV_N * EMBD];
__device__ __nv_bfloat16 g_woh[EMBD * EMBD],   g_wol[EMBD * EMBD];
__device__ __nv_bfloat16 g_qh [M_TOT * QKV_N], g_ql [M_TOT * QKV_N];
__device__ __nv_bfloat16 g_ah [M_TOT * EMBD],  g_al [M_TOT * EMBD];

// ---------------------------------------------------------------------------
// Helpers
// ---------------------------------------------------------------------------
__device__ __forceinline__ void mma_bf16(float* c, const uint32_t* a,
                                         const uint32_t* b) {
    asm volatile(
        "mma.sync.aligned.m16n8k16.row.col.f32.bf16.bf16.f32 "
        "{%0,%1,%2,%3}, {%4,%5,%6,%7}, {%8,%9}, {%0,%1,%2,%3};"
        : "+f"(c[0]), "+f"(c[1]), "+f"(c[2]), "+f"(c[3])
        : "r"(a[0]), "r"(a[1]), "r"(a[2]), "r"(a[3]), "r"(b[0]), "r"(b[1]));
}

// FFMA-only 2^x (avoids MUFU throttle). Valid for x <= 0 (clamped at -80).
__device__ __forceinline__ float exp2_poly(float x) {
    x = fmaxf(x, -80.0f);
    float t = x + 12582912.0f;          // 1.5 * 2^23 round-to-nearest
    float n = t - 12582912.0f;
    float f = x - n;                    // f in [-0.5, 0.5]
    float p = 1.33335581e-3f;
    p = fmaf(p, f, 9.61812911e-3f);
    p = fmaf(p, f, 5.55041087e-2f);
    p = fmaf(p, f, 2.40226507e-1f);
    p = fmaf(p, f, 6.93147181e-1f);
    p = fmaf(p, f, 1.0f);
    int e = (int)n;
    return p * __int_as_float((e + 127) << 23);
}

__device__ __forceinline__ uint32_t pack2(__nv_bfloat162 v) {
    return *reinterpret_cast<uint32_t*>(&v);
}

// ---------------------------------------------------------------------------
// Split fp32 -> bf16 hi/lo
// ---------------------------------------------------------------------------
__global__ void split_kernel(const float* __restrict__ s,
                             __nv_bfloat16* __restrict__ h,
                             __nv_bfloat16* __restrict__ l, int n)
{
    int i = (blockIdx.x * blockDim.x + threadIdx.x) * 4;
    if (i >= n) return;
    float4 v = *reinterpret_cast<const float4*>(&s[i]);
    __nv_bfloat162 h0 = __float22bfloat162_rn(make_float2(v.x, v.y));
    __nv_bfloat162 h1 = __float22bfloat162_rn(make_float2(v.z, v.w));
    __nv_bfloat162 l0 = __float22bfloat162_rn(make_float2(
        v.x - __bfloat162float(h0.x), v.y - __bfloat162float(h0.y)));
    __nv_bfloat162 l1 = __float22bfloat162_rn(make_float2(
        v.z - __bfloat162float(h1.x), v.w - __bfloat162float(h1.y)));
    *reinterpret_cast<__nv_bfloat162*>(&h[i])     = h0;
    *reinterpret_cast<__nv_bfloat162*>(&h[i + 2]) = h1;
    *reinterpret_cast<__nv_bfloat162*>(&l[i])     = l0;
    *reinterpret_cast<__nv_bfloat162*>(&l[i + 2]) = l1;
}

// ---------------------------------------------------------------------------
// GEMM: C[m,n] = sum_k (Ah+Al)[m,k]*(Bh+Bl)[n,k] + bias[n]
// via AhBh + AhBl + AlBh.  128x128 tile, BK=32 bf16, 8 warps (4m x 2n),
// warp tile 32x64 of m16n8k16.  Out: fp32 (Cf) or bf16 hi/lo (Ch/Cl),
// with optional scale applied to columns < scale_lim (Q pre-scale).
// ---------------------------------------------------------------------------
#define AS 40   // smem row stride in bf16 (conflict-free for frag loads)

__global__ __launch_bounds__(256)
void gemm_mma(const __nv_bfloat16* __restrict__ Ah_g,
              const __nv_bfloat16* __restrict__ Al_g,
              const __nv_bfloat16* __restrict__ Bh_g,
              const __nv_bfloat16* __restrict__ Bl_g,
              const float* __restrict__ bias,
              float* __restrict__ Cf,
              __nv_bfloat16* __restrict__ Ch,
              __nv_bfloat16* __restrict__ Cl,
              int N, int K, int scale_lim)
{
    extern __shared__ __nv_bfloat16 sm[];
    __nv_bfloat16* sAh = sm;
    __nv_bfloat16* sAl = sAh + 128 * AS;
    __nv_bfloat16* sBh = sAl + 128 * AS;
    __nv_bfloat16* sBl = sBh + 128 * AS;

    const int tid  = threadIdx.x;
    const int wid  = tid >> 5;
    const int lane = tid & 31;
    const int g    = lane >> 2;
    const int tg   = lane & 3;
    const int warp_m = (wid & 3) * 32;
    const int warp_n = (wid >> 2) * 64;
    const int bm = blockIdx.y * 128;
    const int bn = blockIdx.x * 128;

    float acc[2][8][4];
    #pragma unroll
    for (int mt = 0; mt < 2; mt++)
        #pragma unroll
        for (int nt = 0; nt < 8; nt++)
            #pragma unroll
            for (int i = 0; i < 4; i++) acc[mt][nt][i] = 0.0f;

    uint4 pAh[2], pAl[2], pBh[2], pBl[2];

    #pragma unroll
    for (int i = 0; i < 2; i++) {
        int u = tid + i * 256, row = u >> 2, q = u & 3;
        size_t oA = (size_t)(bm + row) * K + q * 8;
        size_t oB = (size_t)(bn + row) * K + q * 8;
        pAh[i] = *reinterpret_cast<const uint4*>(&Ah_g[oA]);
        pAl[i] = *reinterpret_cast<const uint4*>(&Al_g[oA]);
        pBh[i] = *reinterpret_cast<const uint4*>(&Bh_g[oB]);
        pBl[i] = *reinterpret_cast<const uint4*>(&Bl_g[oB]);
    }

    for (int k0 = 0; k0 < K; k0 += 32) {
        #pragma unroll
        for (int i = 0; i < 2; i++) {
            int u = tid + i * 256, row = u >> 2, q = u & 3;
            *reinterpret_cast<uint4*>(&sAh[row * AS + q * 8]) = pAh[i];
            *reinterpret_cast<uint4*>(&sAl[row * AS + q * 8]) = pAl[i];
            *reinterpret_cast<uint4*>(&sBh[row * AS + q * 8]) = pBh[i];
            *reinterpret_cast<uint4*>(&sBl[row * AS + q * 8]) = pBl[i];
        }
        __syncthreads();

        if (k0 + 32 < K) {
            #pragma unroll
            for (int i = 0; i < 2; i++) {
                int u = tid + i * 256, row = u >> 2, q = u & 3;
                size_t oA = (size_t)(bm + row) * K + k0 + 32 + q * 8;
                size_t oB = (size_t)(bn + row) * K + k0 + 32 + q * 8;
                pAh[i] = *reinterpret_cast<const uint4*>(&Ah_g[oA]);
                pAl[i] = *reinterpret_cast<const uint4*>(&Al_g[oA]);
                pBh[i] = *reinterpret_cast<const uint4*>(&Bh_g[oB]);
                pBl[i] = *reinterpret_cast<const uint4*>(&Bl_g[oB]);
            }
        }

        #pragma unroll
        for (int ks = 0; ks < 2; ks++) {
            uint32_t ah[2][4], al[2][4];
            #pragma unroll
            for (int mt = 0; mt < 2; mt++) {
                int r = warp_m + mt * 16 + g;
                int c = ks * 16 + tg * 2;
                ah[mt][0] = *reinterpret_cast<const uint32_t*>(&sAh[r * AS + c]);
                ah[mt][1] = *reinterpret_cast<const uint32_t*>(&sAh[(r + 8) * AS + c]);
                ah[mt][2] = *reinterpret_cast<const uint32_t*>(&sAh[r * AS + c + 8]);
                ah[mt][3] = *reinterpret_cast<const uint32_t*>(&sAh[(r + 8) * AS + c + 8]);
                al[mt][0] = *reinterpret_cast<const uint32_t*>(&sAl[r * AS + c]);
                al[mt][1] = *reinterpret_cast<const uint32_t*>(&sAl[(r + 8) * AS + c]);
                al[mt][2] = *reinterpret_cast<const uint32_t*>(&sAl[r * AS + c + 8]);
                al[mt][3] = *reinterpret_cast<const uint32_t*>(&sAl[(r + 8) * AS + c + 8]);
            }
            #pragma unroll
            for (int nt = 0; nt < 8; nt++) {
                int rn = warp_n + nt * 8 + g;
                int c  = ks * 16 + tg * 2;
                uint32_t bh[2], bl[2];
                bh[0] = *reinterpret_cast<const uint32_t*>(&sBh[rn * AS + c]);
                bh[1] = *reinterpret_cast<const uint32_t*>(&sBh[rn * AS + c + 8]);
                bl[0] = *reinterpret_cast<const uint32_t*>(&sBl[rn * AS + c]);
                bl[1] = *reinterpret_cast<const uint32_t*>(&sBl[rn * AS + c + 8]);
                #pragma unroll
                for (int mt = 0; mt < 2; mt++) {
                    mma_bf16(acc[mt][nt], ah[mt], bh);
                    mma_bf16(acc[mt][nt], ah[mt], bl);
                    mma_bf16(acc[mt][nt], al[mt], bh);
                }
            }
        }
        __syncthreads();
    }

    const float SCALE = 0.18033688f;   // 0.125 * log2(e)
    #pragma unroll
    for (int mt = 0; mt < 2; mt++) {
        int r0 = bm + warp_m + mt * 16 + g;
        #pragma unroll
        for (int nt = 0; nt < 8; nt++) {
            int col = bn + warp_n + nt * 8 + tg * 2;
            float b0 = __ldg(&bias[col]), b1 = __ldg(&bias[col + 1]);
            float v0 = acc[mt][nt][0] + b0, v1 = acc[mt][nt][1] + b1;
            float v2 = acc[mt][nt][2] + b0, v3 = acc[mt][nt][3] + b1;
            if (Cf) {
                *reinterpret_cast<float2*>(&Cf[(size_t)r0 * N + col])
                    = make_float2(v0, v1);
                *reinterpret_cast<float2*>(&Cf[(size_t)(r0 + 8) * N + col])
                    = make_float2(v2, v3);
            } else {
                if (col < scale_lim) { v0 *= SCALE; v1 *= SCALE; v2 *= SCALE; v3 *= SCALE; }
                __nv_bfloat162 h01 = __float22bfloat162_rn(make_float2(v0, v1));
                __nv_bfloat162 l01 = __float22bfloat162_rn(make_float2(
                    v0 - __bfloat162float(h01.x), v1 - __bfloat162float(h01.y)));
                __nv_bfloat162 h23 = __float22bfloat162_rn(make_float2(v2, v3));
                __nv_bfloat162 l23 = __float22bfloat162_rn(make_float2(
                    v2 - __bfloat162float(h23.x), v3 - __bfloat162float(h23.y)));
                *reinterpret_cast<uint32_t*>(&Ch[(size_t)r0 * N + col])       = pack2(h01);
                *reinterpret_cast<uint32_t*>(&Cl[(size_t)r0 * N + col])       = pack2(l01);
                *reinterpret_cast<uint32_t*>(&Ch[(size_t)(r0 + 8) * N + col]) = pack2(h23);
                *reinterpret_cast<uint32_t*>(&Cl[(size_t)(r0 + 8) * N + col]) = pack2(l23);
            }
        }
    }
}

// ---------------------------------------------------------------------------
// Flash attention on mma.sync bf16 (split operands). Block = 128 q rows of
// one (b,h); 8 warps, warp owns 16 rows. KTILE=64. Q pre-scaled by
// 0.125*log2e in GEMM1 epilogue -> softmax in exp2 domain with FFMA poly.
// ---------------------------------------------------------------------------
#define QS 72    // Q/K smem row stride (bf16)
#define VS 72    // V^T smem row stride
#define KT 64

__global__ __launch_bounds__(256)
void attn_mma(const __nv_bfloat16* __restrict__ qkvh,
              const __nv_bfloat16* __restrict__ qkvl,
              __nv_bfloat16* __restrict__ oh,
              __nv_bfloat16* __restrict__ ol)
{
    extern __shared__ __nv_bfloat16 sm[];
    __nv_bfloat16* sQh = sm;                    // [128][QS]
    __nv_bfloat16* sQl = sQh + 128 * QS;
    __nv_bfloat16* sKh = sQl + 128 * QS;        // [64][QS]
    __nv_bfloat16* sKl = sKh + KT * QS;
    __nv_bfloat16* sVh = sKl + KT * QS;         // V^T [64][VS]
    __nv_bfloat16* sVl = sVh + DH * VS;

    const int tid  = threadIdx.x;
    const int wid  = tid >> 5;
    const int lane = tid & 31;
    const int g    = lane >> 2;
    const int tg   = lane & 3;
    const int q0 = blockIdx.x * 128;
    const int h  = blockIdx.y;
    const int b  = blockIdx.z;
    const size_t rowbase = (size_t)b * SEQ;

    // Load Q tile (hi/lo)
    #pragma unroll
    for (int i = 0; i < 4; i++) {
        int u = tid + i * 256, r = u >> 3, q = u & 7;
        size_t off = (rowbase + q0 + r) * QKV_N + h * DH + q * 8;
        *reinterpret_cast<uint4*>(&sQh[r * QS + q * 8]) =
            *reinterpret_cast<const uint4*>(&qkvh[off]);
        *reinterpret_cast<uint4*>(&sQl[r * QS + q * 8]) =
            *reinterpret_cast<const uint4*>(&qkvl[off]);
    }
    __syncthreads();

    // Preload Q fragments (warp row block = wid*16)
    uint32_t qh[4][4], ql[4][4];
    {
        int r = wid * 16 + g;
        #pragma unroll
        for (int ks = 0; ks < 4; ks++) {
            int c = ks * 16 + tg * 2;
            qh[ks][0] = *reinterpret_cast<const uint32_t*>(&sQh[r * QS + c]);
            qh[ks][1] = *reinterpret_cast<const uint32_t*>(&sQh[(r + 8) * QS + c]);
            qh[ks][2] = *reinterpret_cast<const uint32_t*>(&sQh[r * QS + c + 8]);
            qh[ks][3] = *reinterpret_cast<const uint32_t*>(&sQh[(r + 8) * QS + c + 8]);
            ql[ks][0] = *reinterpret_cast<const uint32_t*>(&sQl[r * QS + c]);
            ql[ks][1] = *reinterpret_cast<const uint32_t*>(&sQl[(r + 8) * QS + c]);
            ql[ks][2] = *reinterpret_cast<const uint32_t*>(&sQl[r * QS + c + 8]);
            ql[ks][3] = *reinterpret_cast<const uint32_t*>(&sQl[(r + 8) * QS + c + 8]);
        }
    }

    float oacc[8][4];
    #pragma unroll
    for (int nt = 0; nt < 8; nt++)
        #pragma unroll
        for (int i = 0; i < 4; i++) oacc[nt][i] = 0.0f;
    float m0 = -1e30f, m1 = -1e30f, l0 = 0.0f, l1 = 0.0f;

    for (int kt = 0; kt < SEQ / KT; kt++) {
        __syncthreads();
        // K tile (hi/lo) + V^T tile (hi/lo)
        #pragma unroll
        for (int i = 0; i < 2; i++) {
            int u = tid + i * 256, r = u >> 3, q = u & 7;
            size_t koff = (rowbase + kt * KT + r) * QKV_N + EMBD + h * DH + q * 8;
            *reinterpret_cast<uint4*>(&sKh[r * QS + q * 8]) =
                *reinterpret_cast<const uint4*>(&qkvh[koff]);
            *reinterpret_cast<uint4*>(&sKl[r * QS + q * 8]) =
                *reinterpret_cast<const uint4*>(&qkvl[koff]);
            size_t voff = (rowbase + kt * KT + r) * QKV_N + 2 * EMBD + h * DH + q * 8;
            uint4 vh = *reinterpret_cast<const uint4*>(&qkvh[voff]);
            uint4 vl = *reinterpret_cast<const uint4*>(&qkvl[voff]);
            const __nv_bfloat16* ph = reinterpret_cast<const __nv_bfloat16*>(&vh);
            const __nv_bfloat16* pl = reinterpret_cast<const __nv_bfloat16*>(&vl);
            #pragma unroll
            for (int j = 0; j < 8; j++) {
                sVh[(q * 8 + j) * VS + r] = ph[j];
                sVl[(q * 8 + j) * VS + r] = pl[j];
            }
        }
        __syncthreads();

        // S = Q K^T (fp32 accum, 3-way split)
        float sacc[8][4];
        #pragma unroll
        for (int nt = 0; nt < 8; nt++)
            #pragma unroll
            for (int i = 0; i < 4; i++) sacc[nt][i] = 0.0f;
        #pragma unroll
        for (int ks = 0; ks < 4; ks++) {
            #pragma unroll
            for (int nt = 0; nt < 8; nt++) {
                int rn = nt * 8 + g;
                int c  = ks * 16 + tg * 2;
                uint32_t kh2[2], kl2[2];
                kh2[0] = *reinterpret_cast<const uint32_t*>(&sKh[rn * QS + c]);
                kh2[1] = *reinterpret_cast<const uint32_t*>(&sKh[rn * QS + c + 8]);
                kl2[0] = *reinterpret_cast<const uint32_t*>(&sKl[rn * QS + c]);
                kl2[1] = *reinterpret_cast<const uint32_t*>(&sKl[rn * QS + c + 8]);
                mma_bf16(sacc[nt], qh[ks], kh2);
                mma_bf16(sacc[nt], qh[ks], kl2);
                mma_bf16(sacc[nt], ql[ks], kh2);
            }
        }

        // Online softmax (rows g and g+8). Scores already in log2 domain.
        float mx0 = -1e30f, mx1 = -1e30f;
        #pragma unroll
        for (int nt = 0; nt < 8; nt++) {
            mx0 = fmaxf(mx0, fmaxf(sacc[nt][0], sacc[nt][1]));
            mx1 = fmaxf(mx1, fmaxf(sacc[nt][2], sacc[nt][3]));
        }
        mx0 = fmaxf(mx0, __shfl_xor_sync(0xffffffffu, mx0, 1));
        mx0 = fmaxf(mx0, __shfl_xor_sync(0xffffffffu, mx0, 2));
        mx1 = fmaxf(mx1, __shfl_xor_sync(0xffffffffu, mx1, 1));
        mx1 = fmaxf(mx1, __shfl_xor_sync(0xffffffffu, mx1, 2));
        float nm0 = fmaxf(m0, mx0), nm1 = fmaxf(m1, mx1);
        float a0 = exp2_poly(m0 - nm0), a1 = exp2_poly(m1 - nm1);

        float rs0 = 0.0f, rs1 = 0.0f;
        uint32_t pah[8], pbh[8], pal[8], pbl[8];
        #pragma unroll
        for (int nt = 0; nt < 8; nt++) {
            float p0 = exp2_poly(sacc[nt][0] - nm0);
            float p1 = exp2_poly(sacc[nt][1] - nm0);
            float p2 = exp2_poly(sacc[nt][2] - nm1);
            float p3 = exp2_poly(sacc[nt][3] - nm1);
            rs0 += p0 + p1; rs1 += p2 + p3;
            __nv_bfloat162 h01 = __float22bfloat162_rn(make_float2(p0, p1));
            __nv_bfloat162 h23 = __float22bfloat162_rn(make_float2(p2, p3));
            pah[nt] = pack2(h01);
            pbh[nt] = pack2(h23);
            pal[nt] = pack2(__float22bfloat162_rn(make_float2(
                p0 - __bfloat162float(h01.x), p1 - __bfloat162float(h01.y))));
            pbl[nt] = pack2(__float22bfloat162_rn(make_float2(
                p2 - __bfloat162float(h23.x), p3 - __bfloat162float(h23.y))));
        }
        rs0 += __shfl_xor_sync(0xffffffffu, rs0, 1);
        rs0 += __shfl_xor_sync(0xffffffffu, rs0, 2);
        rs1 += __shfl_xor_sync(0xffffffffu, rs1, 1);
        rs1 += __shfl_xor_sync(0xffffffffu, rs1, 2);
        l0 = l0 * a0 + rs0;
        l1 = l1 * a1 + rs1;
        m0 = nm0; m1 = nm1;
        #pragma unroll
        for (int nt = 0; nt < 8; nt++) {
            oacc[nt][0] *= a0; oacc[nt][1] *= a0;
            oacc[nt][2] *= a1; oacc[nt][3] *= a1;
        }

        // O += P V  (P from accum fragments, V^T from smem, 3-way split)
        #pragma unroll
        for (int ks = 0; ks < 4; ks++) {
            uint32_t pAh[4] = {pah[2*ks], pbh[2*ks], pah[2*ks+1], pbh[2*ks+1]};
            uint32_t pAl[4] = {pal[2*ks], pbl[2*ks], pal[2*ks+1], pbl[2*ks+1]};
            #pragma unroll
            for (int nt = 0; nt < 8; nt++) {
                int rn = nt * 8 + g;
                int c  = ks * 16 + tg * 2;
                uint32_t vh2[2], vl2[2];
                vh2[0] = *reinterpret_cast<const uint32_t*>(&sVh[rn * VS + c]);
                vh2[1] = *reinterpret_cast<const uint32_t*>(&sVh[rn * VS + c + 8]);
                vl2[0] = *reinterpret_cast<const uint32_t*>(&sVl[rn * VS + c]);
                vl2[1] = *reinterpret_cast<const uint32_t*>(&sVl[rn * VS + c + 8]);
                mma_bf16(oacc[nt], pAh, vh2);
                mma_bf16(oacc[nt], pAh, vl2);
                mma_bf16(oacc[nt], pAl, vh2);
            }
        }
    }

    // Epilogue: normalize, split bf16 hi/lo, store
    float inv0 = 1.0f / l0, inv1 = 1.0f / l1;
    int qrow = q0 + wid * 16 + g;
    #pragma unroll
    for (int nt = 0; nt < 8; nt++) {
        int col = h * DH + nt * 8 + tg * 2;
        float v0 = oacc[nt][0] * inv0, v1 = oacc[nt][1] * inv0;
        float v2 = oacc[nt][2] * inv1, v3 = oacc[nt][3] * inv1;
        __nv_bfloat162 h01 = __float22bfloat162_rn(make_float2(v0, v1));
        __nv_bfloat162 l01 = __float22bfloat162_rn(make_float2(
            v0 - __bfloat162float(h01.x), v1 - __bfloat162float(h01.y)));
        __nv_bfloat162 h23 = __float22bfloat162_rn(make_float2(v2, v3));
        __nv_bfloat162 l23 = __float22bfloat162_rn(make_float2(
            v2 - __bfloat162float(h23.x), v3 - __bfloat162float(h23.y)));
        *reinterpret_cast<uint32_t*>(&oh[(rowbase + qrow) * EMBD + col])     = pack2(h01);
        *reinterpret_cast<uint32_t*>(&ol[(rowbase + qrow) * EMBD + col])     = pack2(l01);
        *reinterpret_cast<uint32_t*>(&oh[(rowbase + qrow + 8) * EMBD + col]) = pack2(h23);
        *reinterpret_cast<uint32_t*>(&ol[(rowbase + qrow + 8) * EMBD + col]) = pack2(l23);
    }
}

// ---------------------------------------------------------------------------
// Launch
// ---------------------------------------------------------------------------
extern "C" void kernel_launch(void* const* d_in, const int* in_sizes, int n_in,
                              void* d_out, int out_size)
{
    const float* x     = (const float*)d_in[0];
    const float* W_in  = (const float*)d_in[1];
    const float* b_in  = (const float*)d_in[2];
    const float* W_out = (const float*)d_in[3];
    const float* b_out = (const float*)d_in[4];
    float* out = (float*)d_out;

    __nv_bfloat16 *xh, *xl, *wih, *wil, *woh, *wol, *qh, *ql, *ah, *al;
    cudaGetSymbolAddress((void**)&xh,  g_xh);  cudaGetSymbolAddress((void**)&xl,  g_xl);
    cudaGetSymbolAddress((void**)&wih, g_wih); cudaGetSymbolAddress((void**)&wil, g_wil);
    cudaGetSymbolAddress((void**)&woh, g_woh); cudaGetSymbolAddress((void**)&wol, g_wol);
    cudaGetSymbolAddress((void**)&qh,  g_qh);  cudaGetSymbolAddress((void**)&ql,  g_ql);
    cudaGetSymbolAddress((void**)&ah,  g_ah);  cudaGetSymbolAddress((void**)&al,  g_al);

    const int gemm_smem = 4 * 128 * AS * (int)sizeof(__nv_bfloat16);
    const int attn_smem = (2 * 128 * QS + 2 * KT * QS + 2 * DH * VS)
                          * (int)sizeof(__nv_bfloat16);
    cudaFuncSetAttribute(gemm_mma, cudaFuncAttributeMaxDynamicSharedMemorySize, gemm_smem);
    cudaFuncSetAttribute(attn_mma, cudaFuncAttributeMaxDynamicSharedMemorySize, attn_smem);

    // Pre-split inputs
    {
        int n1 = M_TOT * EMBD;
        split_kernel<<<n1 / 1024, 256>>>(x, xh, xl, n1);
        int n2 = QKV_N * EMBD;
        split_kernel<<<n2 / 1024, 256>>>(W_in, wih, wil, n2);
        int n3 = EMBD * EMBD;
        split_kernel<<<n3 / 1024, 256>>>(W_out, woh, wol, n3);
    }
    // 1) qkv = x @ W_in^T + b_in  -> bf16 hi/lo, Q columns pre-scaled
    {
        dim3 grid(QKV_N / 128, M_TOT / 128);
        gemm_mma<<<grid, 256, gemm_smem>>>(xh, xl, wih, wil, b_in,
                                           nullptr, qh, ql,
                                           QKV_N, EMBD, EMBD /*scale q cols*/);
    }
    // 2) attention -> bf16 hi/lo
    {
        dim3 grid(SEQ / 128, NH, BATCH);
        attn_mma<<<grid, 256, attn_smem>>>(qh, ql, ah, al);
    }
    // 3) out = attn @ W_out^T + b_out  -> fp32
    {
        dim3 grid(EMBD / 128, M_TOT / 128);
        gemm_mma<<<grid, 256, gemm_smem>>>(ah, al, woh, wol, b_out,
                                           out, nullptr, nullptr,
                                           EMBD, EMBD, 0);
    }
}

// round 4
// speedup vs baseline: 2.9273x; 1.5315x over previous
#include <cuda_runtime.h>
#include <cuda_fp16.h>
#include <cstdint>
#include <math.h>

#define EMBD   1024
#define NH     16
#define DH     64
#define BATCH  2
#define SEQ    2048
#define M_TOT  (BATCH * SEQ)   // 4096
#define QKV_N  (3 * EMBD)      // 3072

// ---------------------------------------------------------------------------
// Scratch (fp16; allocation-free rule: __device__ globals)
// ---------------------------------------------------------------------------
__device__ __half g_xh [M_TOT * EMBD],  g_xl [M_TOT * EMBD];
__device__ __half g_wih[QKV_N * EMBD];                      // W_in single fp16
__device__ __half g_woh[EMBD * EMBD];                       // W_out single fp16
__device__ __half g_qh [M_TOT * QKV_N], g_ql [M_TOT * QKV_N]; // qkv (lo only Q cols)
__device__ __half g_ah [M_TOT * EMBD],  g_al [M_TOT * EMBD];  // attn out hi/lo

// ---------------------------------------------------------------------------
// Helpers
// ---------------------------------------------------------------------------
__device__ __forceinline__ void mma_f16(float* c, const uint32_t* a,
                                        const uint32_t* b) {
    asm volatile(
        "mma.sync.aligned.m16n8k16.row.col.f32.f16.f16.f32 "
        "{%0,%1,%2,%3}, {%4,%5,%6,%7}, {%8,%9}, {%0,%1,%2,%3};"
        : "+f"(c[0]), "+f"(c[1]), "+f"(c[2]), "+f"(c[3])
        : "r"(a[0]), "r"(a[1]), "r"(a[2]), "r"(a[3]), "r"(b[0]), "r"(b[1]));
}

__device__ __forceinline__ void ldsm_x4_t(uint32_t& r0, uint32_t& r1,
                                          uint32_t& r2, uint32_t& r3,
                                          uint32_t a) {
    asm volatile("ldmatrix.sync.aligned.m8n8.x4.trans.shared.b16 "
                 "{%0,%1,%2,%3}, [%4];"
                 : "=r"(r0), "=r"(r1), "=r"(r2), "=r"(r3) : "r"(a));
}

__device__ __forceinline__ uint32_t smem_u32(const void* p) {
    uint32_t a;
    asm("{ .reg .u64 t; cvta.to.shared.u64 t, %1; cvt.u32.u64 %0, t; }"
        : "=r"(a) : "l"(p));
    return a;
}

// FFMA-only 2^x (avoids MUFU throttle). Valid for x <= 0 (clamped at -80).
__device__ __forceinline__ float exp2_poly(float x) {
    x = fmaxf(x, -80.0f);
    float t = x + 12582912.0f;
    float n = t - 12582912.0f;
    float f = x - n;
    float p = 1.33335581e-3f;
    p = fmaf(p, f, 9.61812911e-3f);
    p = fmaf(p, f, 5.55041087e-2f);
    p = fmaf(p, f, 2.40226507e-1f);
    p = fmaf(p, f, 6.93147181e-1f);
    p = fmaf(p, f, 1.0f);
    int e = (int)n;
    return p * __int_as_float((e + 127) << 23);
}

__device__ __forceinline__ uint32_t pk(__half2 v) {
    return *reinterpret_cast<uint32_t*>(&v);
}

// ---------------------------------------------------------------------------
// fp32 -> fp16 hi/lo split  and  fp32 -> fp16 single
// ---------------------------------------------------------------------------
__global__ void split_hl(const float* __restrict__ s,
                         __half* __restrict__ h, __half* __restrict__ l, int n)
{
    int i = (blockIdx.x * blockDim.x + threadIdx.x) * 4;
    if (i >= n) return;
    float4 v = *reinterpret_cast<const float4*>(&s[i]);
    __half2 h0 = __floats2half2_rn(v.x, v.y);
    __half2 h1 = __floats2half2_rn(v.z, v.w);
    __half2 l0 = __floats2half2_rn(v.x - __low2float(h0), v.y - __high2float(h0));
    __half2 l1 = __floats2half2_rn(v.z - __low2float(h1), v.w - __high2float(h1));
    *reinterpret_cast<__half2*>(&h[i])     = h0;
    *reinterpret_cast<__half2*>(&h[i + 2]) = h1;
    *reinterpret_cast<__half2*>(&l[i])     = l0;
    *reinterpret_cast<__half2*>(&l[i + 2]) = l1;
}

__global__ void cvt_h(const float* __restrict__ s, __half* __restrict__ h, int n)
{
    int i = (blockIdx.x * blockDim.x + threadIdx.x) * 4;
    if (i >= n) return;
    float4 v = *reinterpret_cast<const float4*>(&s[i]);
    *reinterpret_cast<__half2*>(&h[i])     = __floats2half2_rn(v.x, v.y);
    *reinterpret_cast<__half2*>(&h[i + 2]) = __floats2half2_rn(v.z, v.w);
}

// ---------------------------------------------------------------------------
// GEMM: C[m,n] = (Ah+Al)[m,:]·B[n,:] + bias[n]   (2 MMAs: Ah·B + Al·B)
// 128x128 tile, BK=32 fp16, 8 warps (4m x 2n), warp tile 32x64.
// Out: fp32 (Cf) or fp16 hi/lo (Ch always, Cl only cols < scale_lim which
// also get SCALE applied — the Q columns).
// ---------------------------------------------------------------------------
#define AS 40

__global__ __launch_bounds__(256)
void gemm_mma(const __half* __restrict__ Ah_g,
              const __half* __restrict__ Al_g,
              const __half* __restrict__ Bh_g,
              const float* __restrict__ bias,
              float* __restrict__ Cf,
              __half* __restrict__ Ch,
              __half* __restrict__ Cl,
              int N, int K, int scale_lim)
{
    extern __shared__ __half sm[];
    __half* sAh = sm;
    __half* sAl = sAh + 128 * AS;
    __half* sBh = sAl + 128 * AS;

    const int tid  = threadIdx.x;
    const int wid  = tid >> 5;
    const int lane = tid & 31;
    const int g    = lane >> 2;
    const int tg   = lane & 3;
    const int warp_m = (wid & 3) * 32;
    const int warp_n = (wid >> 2) * 64;
    const int bm = blockIdx.y * 128;
    const int bn = blockIdx.x * 128;

    float acc[2][8][4];
    #pragma unroll
    for (int mt = 0; mt < 2; mt++)
        #pragma unroll
        for (int nt = 0; nt < 8; nt++)
            #pragma unroll
            for (int i = 0; i < 4; i++) acc[mt][nt][i] = 0.0f;

    uint4 pAh[2], pAl[2], pBh[2];
    #pragma unroll
    for (int i = 0; i < 2; i++) {
        int u = tid + i * 256, row = u >> 2, q = u & 3;
        size_t oA = (size_t)(bm + row) * K + q * 8;
        size_t oB = (size_t)(bn + row) * K + q * 8;
        pAh[i] = *reinterpret_cast<const uint4*>(&Ah_g[oA]);
        pAl[i] = *reinterpret_cast<const uint4*>(&Al_g[oA]);
        pBh[i] = *reinterpret_cast<const uint4*>(&Bh_g[oB]);
    }

    for (int k0 = 0; k0 < K; k0 += 32) {
        #pragma unroll
        for (int i = 0; i < 2; i++) {
            int u = tid + i * 256, row = u >> 2, q = u & 3;
            *reinterpret_cast<uint4*>(&sAh[row * AS + q * 8]) = pAh[i];
            *reinterpret_cast<uint4*>(&sAl[row * AS + q * 8]) = pAl[i];
            *reinterpret_cast<uint4*>(&sBh[row * AS + q * 8]) = pBh[i];
        }
        __syncthreads();

        if (k0 + 32 < K) {
            #pragma unroll
            for (int i = 0; i < 2; i++) {
                int u = tid + i * 256, row = u >> 2, q = u & 3;
                size_t oA = (size_t)(bm + row) * K + k0 + 32 + q * 8;
                size_t oB = (size_t)(bn + row) * K + k0 + 32 + q * 8;
                pAh[i] = *reinterpret_cast<const uint4*>(&Ah_g[oA]);
                pAl[i] = *reinterpret_cast<const uint4*>(&Al_g[oA]);
                pBh[i] = *reinterpret_cast<const uint4*>(&Bh_g[oB]);
            }
        }

        #pragma unroll
        for (int ks = 0; ks < 2; ks++) {
            uint32_t ah[2][4], al[2][4];
            #pragma unroll
            for (int mt = 0; mt < 2; mt++) {
                int r = warp_m + mt * 16 + g;
                int c = ks * 16 + tg * 2;
                ah[mt][0] = *reinterpret_cast<const uint32_t*>(&sAh[r * AS + c]);
                ah[mt][1] = *reinterpret_cast<const uint32_t*>(&sAh[(r + 8) * AS + c]);
                ah[mt][2] = *reinterpret_cast<const uint32_t*>(&sAh[r * AS + c + 8]);
                ah[mt][3] = *reinterpret_cast<const uint32_t*>(&sAh[(r + 8) * AS + c + 8]);
                al[mt][0] = *reinterpret_cast<const uint32_t*>(&sAl[r * AS + c]);
                al[mt][1] = *reinterpret_cast<const uint32_t*>(&sAl[(r + 8) * AS + c]);
                al[mt][2] = *reinterpret_cast<const uint32_t*>(&sAl[r * AS + c + 8]);
                al[mt][3] = *reinterpret_cast<const uint32_t*>(&sAl[(r + 8) * AS + c + 8]);
            }
            #pragma unroll
            for (int nt = 0; nt < 8; nt++) {
                int rn = warp_n + nt * 8 + g;
                int c  = ks * 16 + tg * 2;
                uint32_t bh[2];
                bh[0] = *reinterpret_cast<const uint32_t*>(&sBh[rn * AS + c]);
                bh[1] = *reinterpret_cast<const uint32_t*>(&sBh[rn * AS + c + 8]);
                #pragma unroll
                for (int mt = 0; mt < 2; mt++) {
                    mma_f16(acc[mt][nt], ah[mt], bh);
                    mma_f16(acc[mt][nt], al[mt], bh);
                }
            }
        }
        __syncthreads();
    }

    const float SCALE = 0.18033688f;   // 0.125 * log2(e)
    #pragma unroll
    for (int mt = 0; mt < 2; mt++) {
        int r0 = bm + warp_m + mt * 16 + g;
        #pragma unroll
        for (int nt = 0; nt < 8; nt++) {
            int col = bn + warp_n + nt * 8 + tg * 2;
            float b0 = __ldg(&bias[col]), b1 = __ldg(&bias[col + 1]);
            float v0 = acc[mt][nt][0] + b0, v1 = acc[mt][nt][1] + b1;
            float v2 = acc[mt][nt][2] + b0, v3 = acc[mt][nt][3] + b1;
            if (Cf) {
                *reinterpret_cast<float2*>(&Cf[(size_t)r0 * N + col])
                    = make_float2(v0, v1);
                *reinterpret_cast<float2*>(&Cf[(size_t)(r0 + 8) * N + col])
                    = make_float2(v2, v3);
            } else {
                bool isq = col < scale_lim;
                if (isq) { v0 *= SCALE; v1 *= SCALE; v2 *= SCALE; v3 *= SCALE; }
                __half2 h01 = __floats2half2_rn(v0, v1);
                __half2 h23 = __floats2half2_rn(v2, v3);
                *reinterpret_cast<uint32_t*>(&Ch[(size_t)r0 * N + col])       = pk(h01);
                *reinterpret_cast<uint32_t*>(&Ch[(size_t)(r0 + 8) * N + col]) = pk(h23);
                if (isq) {
                    __half2 l01 = __floats2half2_rn(
                        v0 - __low2float(h01), v1 - __high2float(h01));
                    __half2 l23 = __floats2half2_rn(
                        v2 - __low2float(h23), v3 - __high2float(h23));
                    *reinterpret_cast<uint32_t*>(&Cl[(size_t)r0 * N + col])       = pk(l01);
                    *reinterpret_cast<uint32_t*>(&Cl[(size_t)(r0 + 8) * N + col]) = pk(l23);
                }
            }
        }
    }
}

// ---------------------------------------------------------------------------
// Flash attention. Block = 128 q rows of one (b,h); 8 warps x 16 rows.
// KT=64.  S = (Qh+Ql)·K  (2 MMAs, K single fp16).
// PV = (Ph+Pl)·V (2 MMAs, V single fp16 via ldmatrix.trans, row-major smem).
// Q pre-scaled by 0.125*log2e -> softmax in exp2 domain (FFMA poly).
// ---------------------------------------------------------------------------
#define QS 72
#define VS 72
#define KT 64

__global__ __launch_bounds__(256)
void attn_mma(const __half* __restrict__ qkvh,
              const __half* __restrict__ qkvl,
              __half* __restrict__ oh,
              __half* __restrict__ ol)
{
    extern __shared__ __half sm[];
    __half* sQh = sm;                      // [128][QS]
    __half* sQl = sQh + 128 * QS;
    __half* sKh = sQl + 128 * QS;          // [64][QS]
    __half* sVh = sKh + KT * QS;           // row-major [64][VS]

    const int tid  = threadIdx.x;
    const int wid  = tid >> 5;
    const int lane = tid & 31;
    const int g    = lane >> 2;
    const int tg   = lane & 3;
    const int q0 = blockIdx.x * 128;
    const int h  = blockIdx.y;
    const int b  = blockIdx.z;
    const size_t rowbase = (size_t)b * SEQ;

    // ldmatrix per-thread invariant offset within V tile
    const int lr = lane & 7, lq = (lane >> 3) & 1, lh = lane >> 4;
    const uint32_t sV_base = smem_u32(sVh);
    const uint32_t voff0 = (uint32_t)(((lq * 8 + lr) * VS + lh * 8) * 2);

    // Load Q tile (hi/lo)
    #pragma unroll
    for (int i = 0; i < 4; i++) {
        int u = tid + i * 256, r = u >> 3, q = u & 7;
        size_t off = (rowbase + q0 + r) * QKV_N + h * DH + q * 8;
        *reinterpret_cast<uint4*>(&sQh[r * QS + q * 8]) =
            *reinterpret_cast<const uint4*>(&qkvh[off]);
        *reinterpret_cast<uint4*>(&sQl[r * QS + q * 8]) =
            *reinterpret_cast<const uint4*>(&qkvl[off]);
    }
    __syncthreads();

    uint32_t qh[4][4], ql[4][4];
    {
        int r = wid * 16 + g;
        #pragma unroll
        for (int ks = 0; ks < 4; ks++) {
            int c = ks * 16 + tg * 2;
            qh[ks][0] = *reinterpret_cast<const uint32_t*>(&sQh[r * QS + c]);
            qh[ks][1] = *reinterpret_cast<const uint32_t*>(&sQh[(r + 8) * QS + c]);
            qh[ks][2] = *reinterpret_cast<const uint32_t*>(&sQh[r * QS + c + 8]);
            qh[ks][3] = *reinterpret_cast<const uint32_t*>(&sQh[(r + 8) * QS + c + 8]);
            ql[ks][0] = *reinterpret_cast<const uint32_t*>(&sQl[r * QS + c]);
            ql[ks][1] = *reinterpret_cast<const uint32_t*>(&sQl[(r + 8) * QS + c]);
            ql[ks][2] = *reinterpret_cast<const uint32_t*>(&sQl[r * QS + c + 8]);
            ql[ks][3] = *reinterpret_cast<const uint32_t*>(&sQl[(r + 8) * QS + c + 8]);
        }
    }

    float oacc[8][4];
    #pragma unroll
    for (int nt = 0; nt < 8; nt++)
        #pragma unroll
        for (int i = 0; i < 4; i++) oacc[nt][i] = 0.0f;
    float m0 = -1e30f, m1 = -1e30f, l0 = 0.0f, l1 = 0.0f;

    for (int kt = 0; kt < SEQ / KT; kt++) {
        __syncthreads();
        // K tile (hi only) + V tile (row-major, hi only)
        #pragma unroll
        for (int i = 0; i < 2; i++) {
            int u = tid + i * 256, r = u >> 3, q = u & 7;
            size_t koff = (rowbase + kt * KT + r) * QKV_N + EMBD + h * DH + q * 8;
            *reinterpret_cast<uint4*>(&sKh[r * QS + q * 8]) =
                *reinterpret_cast<const uint4*>(&qkvh[koff]);
            size_t voff = (rowbase + kt * KT + r) * QKV_N + 2 * EMBD + h * DH + q * 8;
            *reinterpret_cast<uint4*>(&sVh[r * VS + q * 8]) =
                *reinterpret_cast<const uint4*>(&qkvh[voff]);
        }
        __syncthreads();

        // S = Q K^T (2 MMAs per step)
        float sacc[8][4];
        #pragma unroll
        for (int nt = 0; nt < 8; nt++)
            #pragma unroll
            for (int i = 0; i < 4; i++) sacc[nt][i] = 0.0f;
        #pragma unroll
        for (int ks = 0; ks < 4; ks++) {
            #pragma unroll
            for (int nt = 0; nt < 8; nt++) {
                int rn = nt * 8 + g;
                int c  = ks * 16 + tg * 2;
                uint32_t kh2[2];
                kh2[0] = *reinterpret_cast<const uint32_t*>(&sKh[rn * QS + c]);
                kh2[1] = *reinterpret_cast<const uint32_t*>(&sKh[rn * QS + c + 8]);
                mma_f16(sacc[nt], qh[ks], kh2);
                mma_f16(sacc[nt], ql[ks], kh2);
            }
        }

        // Online softmax (log2 domain)
        float mx0 = -1e30f, mx1 = -1e30f;
        #pragma unroll
        for (int nt = 0; nt < 8; nt++) {
            mx0 = fmaxf(mx0, fmaxf(sacc[nt][0], sacc[nt][1]));
            mx1 = fmaxf(mx1, fmaxf(sacc[nt][2], sacc[nt][3]));
        }
        mx0 = fmaxf(mx0, __shfl_xor_sync(0xffffffffu, mx0, 1));
        mx0 = fmaxf(mx0, __shfl_xor_sync(0xffffffffu, mx0, 2));
        mx1 = fmaxf(mx1, __shfl_xor_sync(0xffffffffu, mx1, 1));
        mx1 = fmaxf(mx1, __shfl_xor_sync(0xffffffffu, mx1, 2));
        float nm0 = fmaxf(m0, mx0), nm1 = fmaxf(m1, mx1);
        float a0 = exp2_poly(m0 - nm0), a1 = exp2_poly(m1 - nm1);

        float rs0 = 0.0f, rs1 = 0.0f;
        uint32_t pah[8], pbh[8], pal[8], pbl[8];
        #pragma unroll
        for (int nt = 0; nt < 8; nt++) {
            float p0 = exp2_poly(sacc[nt][0] - nm0);
            float p1 = exp2_poly(sacc[nt][1] - nm0);
            float p2 = exp2_poly(sacc[nt][2] - nm1);
            float p3 = exp2_poly(sacc[nt][3] - nm1);
            rs0 += p0 + p1; rs1 += p2 + p3;
            __half2 h01 = __floats2half2_rn(p0, p1);
            __half2 h23 = __floats2half2_rn(p2, p3);
            pah[nt] = pk(h01);
            pbh[nt] = pk(h23);
            pal[nt] = pk(__floats2half2_rn(
                p0 - __low2float(h01), p1 - __high2float(h01)));
            pbl[nt] = pk(__floats2half2_rn(
                p2 - __low2float(h23), p3 - __high2float(h23)));
        }
        rs0 += __shfl_xor_sync(0xffffffffu, rs0, 1);
        rs0 += __shfl_xor_sync(0xffffffffu, rs0, 2);
        rs1 += __shfl_xor_sync(0xffffffffu, rs1, 1);
        rs1 += __shfl_xor_sync(0xffffffffu, rs1, 2);
        l0 = l0 * a0 + rs0;
        l1 = l1 * a1 + rs1;
        m0 = nm0; m1 = nm1;
        #pragma unroll
        for (int nt = 0; nt < 8; nt++) {
            oacc[nt][0] *= a0; oacc[nt][1] *= a0;
            oacc[nt][2] *= a1; oacc[nt][3] *= a1;
        }

        // O += P V  (2 MMAs; V fragments via ldmatrix.trans)
        #pragma unroll
        for (int ks = 0; ks < 4; ks++) {
            uint32_t pAh[4] = {pah[2*ks], pbh[2*ks], pah[2*ks+1], pbh[2*ks+1]};
            uint32_t pAl[4] = {pal[2*ks], pbl[2*ks], pal[2*ks+1], pbl[2*ks+1]};
            #pragma unroll
            for (int ntp = 0; ntp < 4; ntp++) {
                uint32_t v0, v1, v2, v3;
                uint32_t addr = sV_base + voff0
                              + (uint32_t)((ks * 16 * VS + ntp * 16) * 2);
                ldsm_x4_t(v0, v1, v2, v3, addr);
                uint32_t vb0[2] = {v0, v1};
                uint32_t vb1[2] = {v2, v3};
                mma_f16(oacc[2*ntp],     pAh, vb0);
                mma_f16(oacc[2*ntp],     pAl, vb0);
                mma_f16(oacc[2*ntp + 1], pAh, vb1);
                mma_f16(oacc[2*ntp + 1], pAl, vb1);
            }
        }
    }

    // Epilogue: normalize, split fp16 hi/lo, store
    float inv0 = 1.0f / l0, inv1 = 1.0f / l1;
    int qrow = q0 + wid * 16 + g;
    #pragma unroll
    for (int nt = 0; nt < 8; nt++) {
        int col = h * DH + nt * 8 + tg * 2;
        float v0 = oacc[nt][0] * inv0, v1 = oacc[nt][1] * inv0;
        float v2 = oacc[nt][2] * inv1, v3 = oacc[nt][3] * inv1;
        __half2 h01 = __floats2half2_rn(v0, v1);
        __half2 h23 = __floats2half2_rn(v2, v3);
        __half2 l01 = __floats2half2_rn(v0 - __low2float(h01), v1 - __high2float(h01));
        __half2 l23 = __floats2half2_rn(v2 - __low2float(h23), v3 - __high2float(h23));
        *reinterpret_cast<uint32_t*>(&oh[(rowbase + qrow) * EMBD + col])     = pk(h01);
        *reinterpret_cast<uint32_t*>(&ol[(rowbase + qrow) * EMBD + col])     = pk(l01);
        *reinterpret_cast<uint32_t*>(&oh[(rowbase + qrow + 8) * EMBD + col]) = pk(h23);
        *reinterpret_cast<uint32_t*>(&ol[(rowbase + qrow + 8) * EMBD + col]) = pk(l23);
    }
}

// ---------------------------------------------------------------------------
// Launch
// ---------------------------------------------------------------------------
extern "C" void kernel_launch(void* const* d_in, const int* in_sizes, int n_in,
                              void* d_out, int out_size)
{
    const float* x     = (const float*)d_in[0];
    const float* W_in  = (const float*)d_in[1];
    const float* b_in  = (const float*)d_in[2];
    const float* W_out = (const float*)d_in[3];
    const float* b_out = (const float*)d_in[4];
    float* out = (float*)d_out;

    __half *xh, *xl, *wih, *woh, *qh, *ql, *ah, *al;
    cudaGetSymbolAddress((void**)&xh,  g_xh);  cudaGetSymbolAddress((void**)&xl,  g_xl);
    cudaGetSymbolAddress((void**)&wih, g_wih);
    cudaGetSymbolAddress((void**)&woh, g_woh);
    cudaGetSymbolAddress((void**)&qh,  g_qh);  cudaGetSymbolAddress((void**)&ql,  g_ql);
    cudaGetSymbolAddress((void**)&ah,  g_ah);  cudaGetSymbolAddress((void**)&al,  g_al);

    const int gemm_smem = 3 * 128 * AS * (int)sizeof(__half);
    const int attn_smem = (2 * 128 * QS + KT * QS + KT * VS) * (int)sizeof(__half);
    cudaFuncSetAttribute(gemm_mma, cudaFuncAttributeMaxDynamicSharedMemorySize, gemm_smem);
    cudaFuncSetAttribute(attn_mma, cudaFuncAttributeMaxDynamicSharedMemorySize, attn_smem);

    // Pre-convert inputs
    {
        int n1 = M_TOT * EMBD;
        split_hl<<<n1 / 1024, 256>>>(x, xh, xl, n1);
        int n2 = QKV_N * EMBD;
        cvt_h<<<n2 / 1024, 256>>>(W_in, wih, n2);
        int n3 = EMBD * EMBD;
        cvt_h<<<n3 / 1024, 256>>>(W_out, woh, n3);
    }
    // 1) qkv = x @ W_in^T + b_in  -> fp16 (hi everywhere, lo + scale on Q cols)
    {
        dim3 grid(QKV_N / 128, M_TOT / 128);
        gemm_mma<<<grid, 256, gemm_smem>>>(xh, xl, wih, b_in,
                                           nullptr, qh, ql,
                                           QKV_N, EMBD, EMBD);
    }
    // 2) attention -> fp16 hi/lo
    {
        dim3 grid(SEQ / 128, NH, BATCH);
        attn_mma<<<grid, 256, attn_smem>>>(qh, ql, ah, al);
    }
    // 3) out = attn @ W_out^T + b_out  -> fp32
    {
        dim3 grid(EMBD / 128, M_TOT / 128);
        gemm_mma<<<grid, 256, gemm_smem>>>(ah, al, woh, b_out,
                                           out, nullptr, nullptr,
                                           EMBD, EMBD, 0);
    }
}

// round 5
// speedup vs baseline: 3.3560x; 1.1464x over previous
#include <cuda_runtime.h>
#include <cuda_fp16.h>
#include <cstdint>
#include <math.h>

#define EMBD   1024
#define NH     16
#define DH     64
#define BATCH  2
#define SEQ    2048
#define M_TOT  (BATCH * SEQ)   // 4096
#define QKV_N  (3 * EMBD)      // 3072

// ---------------------------------------------------------------------------
// Scratch (fp16; allocation-free rule: __device__ globals)
// ---------------------------------------------------------------------------
__device__ __half g_xh [M_TOT * EMBD],  g_xl [M_TOT * EMBD];
__device__ __half g_wih[QKV_N * EMBD];
__device__ __half g_woh[EMBD * EMBD];
__device__ __half g_qh [M_TOT * QKV_N], g_ql [M_TOT * QKV_N];
__device__ __half g_ah [M_TOT * EMBD],  g_al [M_TOT * EMBD];

// ---------------------------------------------------------------------------
// Helpers
// ---------------------------------------------------------------------------
__device__ __forceinline__ void mma_f16(float* c, const uint32_t* a,
                                        const uint32_t* b) {
    asm volatile(
        "mma.sync.aligned.m16n8k16.row.col.f32.f16.f16.f32 "
        "{%0,%1,%2,%3}, {%4,%5,%6,%7}, {%8,%9}, {%0,%1,%2,%3};"
        : "+f"(c[0]), "+f"(c[1]), "+f"(c[2]), "+f"(c[3])
        : "r"(a[0]), "r"(a[1]), "r"(a[2]), "r"(a[3]), "r"(b[0]), "r"(b[1]));
}

__device__ __forceinline__ void ldsm_x4_t(uint32_t& r0, uint32_t& r1,
                                          uint32_t& r2, uint32_t& r3,
                                          uint32_t a) {
    asm volatile("ldmatrix.sync.aligned.m8n8.x4.trans.shared.b16 "
                 "{%0,%1,%2,%3}, [%4];"
                 : "=r"(r0), "=r"(r1), "=r"(r2), "=r"(r3) : "r"(a));
}

__device__ __forceinline__ uint32_t smem_u32(const void* p) {
    uint32_t a;
    asm("{ .reg .u64 t; cvta.to.shared.u64 t, %1; cvt.u32.u64 %0, t; }"
        : "=r"(a) : "l"(p));
    return a;
}

__device__ __forceinline__ void cp16(uint32_t dst, const void* src) {
    asm volatile("cp.async.cg.shared.global [%0], [%1], 16;"
                 :: "r"(dst), "l"(src));
}
#define CP_COMMIT() asm volatile("cp.async.commit_group;")
#define CP_WAIT0()  asm volatile("cp.async.wait_group 0;")

// FFMA-only 2^x (avoids MUFU throttle). Valid for x <= 0 (clamped at -80).
__device__ __forceinline__ float exp2_poly(float x) {
    x = fmaxf(x, -80.0f);
    float t = x + 12582912.0f;
    float n = t - 12582912.0f;
    float f = x - n;
    float p = 1.33335581e-3f;
    p = fmaf(p, f, 9.61812911e-3f);
    p = fmaf(p, f, 5.55041087e-2f);
    p = fmaf(p, f, 2.40226507e-1f);
    p = fmaf(p, f, 6.93147181e-1f);
    p = fmaf(p, f, 1.0f);
    int e = (int)n;
    return p * __int_as_float((e + 127) << 23);
}

__device__ __forceinline__ uint32_t pk(__half2 v) {
    return *reinterpret_cast<uint32_t*>(&v);
}

// ---------------------------------------------------------------------------
// fp32 -> fp16 hi/lo split  and  fp32 -> fp16 single
// ---------------------------------------------------------------------------
__global__ void split_hl(const float* __restrict__ s,
                         __half* __restrict__ h, __half* __restrict__ l, int n)
{
    int i = (blockIdx.x * blockDim.x + threadIdx.x) * 4;
    if (i >= n) return;
    float4 v = *reinterpret_cast<const float4*>(&s[i]);
    __half2 h0 = __floats2half2_rn(v.x, v.y);
    __half2 h1 = __floats2half2_rn(v.z, v.w);
    __half2 l0 = __floats2half2_rn(v.x - __low2float(h0), v.y - __high2float(h0));
    __half2 l1 = __floats2half2_rn(v.z - __low2float(h1), v.w - __high2float(h1));
    *reinterpret_cast<__half2*>(&h[i])     = h0;
    *reinterpret_cast<__half2*>(&h[i + 2]) = h1;
    *reinterpret_cast<__half2*>(&l[i])     = l0;
    *reinterpret_cast<__half2*>(&l[i + 2]) = l1;
}

__global__ void cvt_h(const float* __restrict__ s, __half* __restrict__ h, int n)
{
    int i = (blockIdx.x * blockDim.x + threadIdx.x) * 4;
    if (i >= n) return;
    float4 v = *reinterpret_cast<const float4*>(&s[i]);
    *reinterpret_cast<__half2*>(&h[i])     = __floats2half2_rn(v.x, v.y);
    *reinterpret_cast<__half2*>(&h[i + 2]) = __floats2half2_rn(v.z, v.w);
}

// ---------------------------------------------------------------------------
// GEMM: C[m,n] = (Ah+Al)[m,:]·B[n,:] + bias[n]   (2 MMAs: Ah·B + Al·B)
// 128x128 tile, BK=32 fp16, cp.async 2-stage smem pipeline, 2 CTAs/SM.
// ---------------------------------------------------------------------------
#define AS 40
#define G_TILE (128 * AS)          // halfs per operand tile
#define G_STG  (3 * G_TILE)        // halfs per stage

__global__ __launch_bounds__(256, 2)
void gemm_mma(const __half* __restrict__ Ah_g,
              const __half* __restrict__ Al_g,
              const __half* __restrict__ Bh_g,
              const float* __restrict__ bias,
              float* __restrict__ Cf,
              __half* __restrict__ Ch,
              __half* __restrict__ Cl,
              int N, int K, int scale_lim)
{
    extern __shared__ __half sm[];
    const uint32_t smb = smem_u32(sm);

    const int tid  = threadIdx.x;
    const int wid  = tid >> 5;
    const int lane = tid & 31;
    const int g    = lane >> 2;
    const int tg   = lane & 3;
    const int warp_m = (wid & 3) * 32;
    const int warp_n = (wid >> 2) * 64;
    const int bm = blockIdx.y * 128;
    const int bn = blockIdx.x * 128;

    const int l_row = tid >> 2;        // 0..63 base row (x2 via +64)
    const int l_q   = tid & 3;

    float acc[2][8][4];
    #pragma unroll
    for (int mt = 0; mt < 2; mt++)
        #pragma unroll
        for (int nt = 0; nt < 8; nt++)
            #pragma unroll
            for (int i = 0; i < 4; i++) acc[mt][nt][i] = 0.0f;

    const int nch = K / 32;

    // issue loads for chunk ch into stage s
    auto issue = [&](int ch, int s) {
        int k0 = ch * 32;
        uint32_t sb = smb + (uint32_t)(s * G_STG) * 2;
        #pragma unroll
        for (int i = 0; i < 2; i++) {
            int row = l_row + i * 64;
            uint32_t so = (uint32_t)(row * AS + l_q * 8) * 2;
            size_t oA = (size_t)(bm + row) * K + k0 + l_q * 8;
            size_t oB = (size_t)(bn + row) * K + k0 + l_q * 8;
            cp16(sb + so,                    &Ah_g[oA]);
            cp16(sb + G_TILE * 2 + so,       &Al_g[oA]);
            cp16(sb + 2 * G_TILE * 2 + so,   &Bh_g[oB]);
        }
    };

    issue(0, 0);
    CP_COMMIT();

    for (int ch = 0; ch < nch; ch++) {
        CP_WAIT0();
        __syncthreads();
        if (ch + 1 < nch) { issue(ch + 1, (ch + 1) & 1); CP_COMMIT(); }

        const __half* sAh = sm + (ch & 1) * G_STG;
        const __half* sAl = sAh + G_TILE;
        const __half* sBh = sAl + G_TILE;

        #pragma unroll
        for (int ks = 0; ks < 2; ks++) {
            uint32_t ah[2][4], al[2][4];
            #pragma unroll
            for (int mt = 0; mt < 2; mt++) {
                int r = warp_m + mt * 16 + g;
                int c = ks * 16 + tg * 2;
                ah[mt][0] = *reinterpret_cast<const uint32_t*>(&sAh[r * AS + c]);
                ah[mt][1] = *reinterpret_cast<const uint32_t*>(&sAh[(r + 8) * AS + c]);
                ah[mt][2] = *reinterpret_cast<const uint32_t*>(&sAh[r * AS + c + 8]);
                ah[mt][3] = *reinterpret_cast<const uint32_t*>(&sAh[(r + 8) * AS + c + 8]);
                al[mt][0] = *reinterpret_cast<const uint32_t*>(&sAl[r * AS + c]);
                al[mt][1] = *reinterpret_cast<const uint32_t*>(&sAl[(r + 8) * AS + c]);
                al[mt][2] = *reinterpret_cast<const uint32_t*>(&sAl[r * AS + c + 8]);
                al[mt][3] = *reinterpret_cast<const uint32_t*>(&sAl[(r + 8) * AS + c + 8]);
            }
            #pragma unroll
            for (int nt = 0; nt < 8; nt++) {
                int rn = warp_n + nt * 8 + g;
                int c  = ks * 16 + tg * 2;
                uint32_t bh[2];
                bh[0] = *reinterpret_cast<const uint32_t*>(&sBh[rn * AS + c]);
                bh[1] = *reinterpret_cast<const uint32_t*>(&sBh[rn * AS + c + 8]);
                #pragma unroll
                for (int mt = 0; mt < 2; mt++) {
                    mma_f16(acc[mt][nt], ah[mt], bh);
                    mma_f16(acc[mt][nt], al[mt], bh);
                }
            }
        }
        __syncthreads();
    }

    const float SCALE = 0.18033688f;   // 0.125 * log2(e)
    #pragma unroll
    for (int mt = 0; mt < 2; mt++) {
        int r0 = bm + warp_m + mt * 16 + g;
        #pragma unroll
        for (int nt = 0; nt < 8; nt++) {
            int col = bn + warp_n + nt * 8 + tg * 2;
            float b0 = __ldg(&bias[col]), b1 = __ldg(&bias[col + 1]);
            float v0 = acc[mt][nt][0] + b0, v1 = acc[mt][nt][1] + b1;
            float v2 = acc[mt][nt][2] + b0, v3 = acc[mt][nt][3] + b1;
            if (Cf) {
                *reinterpret_cast<float2*>(&Cf[(size_t)r0 * N + col])
                    = make_float2(v0, v1);
                *reinterpret_cast<float2*>(&Cf[(size_t)(r0 + 8) * N + col])
                    = make_float2(v2, v3);
            } else {
                bool isq = col < scale_lim;
                if (isq) { v0 *= SCALE; v1 *= SCALE; v2 *= SCALE; v3 *= SCALE; }
                __half2 h01 = __floats2half2_rn(v0, v1);
                __half2 h23 = __floats2half2_rn(v2, v3);
                *reinterpret_cast<uint32_t*>(&Ch[(size_t)r0 * N + col])       = pk(h01);
                *reinterpret_cast<uint32_t*>(&Ch[(size_t)(r0 + 8) * N + col]) = pk(h23);
                if (isq) {
                    __half2 l01 = __floats2half2_rn(
                        v0 - __low2float(h01), v1 - __high2float(h01));
                    __half2 l23 = __floats2half2_rn(
                        v2 - __low2float(h23), v3 - __high2float(h23));
                    *reinterpret_cast<uint32_t*>(&Cl[(size_t)r0 * N + col])       = pk(l01);
                    *reinterpret_cast<uint32_t*>(&Cl[(size_t)(r0 + 8) * N + col]) = pk(l23);
                }
            }
        }
    }
}

// ---------------------------------------------------------------------------
// Flash attention, cp.async 2-stage K/V pipeline.  Block = 128 q rows of
// one (b,h); 8 warps x 16 rows.  S=(Qh+Ql)·K, PV=(Ph+Pl)·V (V via
// ldmatrix.trans).  Q pre-scaled by 0.125*log2e -> exp2-domain softmax.
// ---------------------------------------------------------------------------
#define QS 72
#define VS 72
#define KT 64
#define A_QSZ   (128 * QS)          // one Q operand tile (halfs)
#define A_KVSTG (KT * QS + KT * VS) // one K+V stage (halfs)

__global__ __launch_bounds__(256)
void attn_mma(const __half* __restrict__ qkvh,
              const __half* __restrict__ qkvl,
              __half* __restrict__ oh,
              __half* __restrict__ ol)
{
    extern __shared__ __half sm[];
    __half* sQh = sm;                       // [128][QS]
    __half* sQl = sQh + A_QSZ;
    __half* sKV = sQl + A_QSZ;              // 2 stages of K[64][QS] + V[64][VS]

    const int tid  = threadIdx.x;
    const int wid  = tid >> 5;
    const int lane = tid & 31;
    const int g    = lane >> 2;
    const int tg   = lane & 3;
    const int q0 = blockIdx.x * 128;
    const int h  = blockIdx.y;
    const int b  = blockIdx.z;
    const size_t rowbase = (size_t)b * SEQ;

    const uint32_t smb = smem_u32(sm);
    const uint32_t kv_base_u = smb + (uint32_t)(2 * A_QSZ) * 2;

    // ldmatrix per-thread invariant offset within V tile
    const int lr = lane & 7, lq = (lane >> 3) & 1, lh2 = lane >> 4;
    const uint32_t voff0 = (uint32_t)(((lq * 8 + lr) * VS + lh2 * 8) * 2);

    const int l_r = tid >> 3;      // 0..31 (x2 via +32)
    const int l_q = tid & 7;

    auto issue = [&](int kt, int s) {
        uint32_t sb = kv_base_u + (uint32_t)(s * A_KVSTG) * 2;
        #pragma unroll
        for (int i = 0; i < 2; i++) {
            int r = l_r + i * 32;
            size_t koff = (rowbase + kt * KT + r) * QKV_N + EMBD + h * DH + l_q * 8;
            size_t voff = koff + EMBD;
            cp16(sb + (uint32_t)(r * QS + l_q * 8) * 2, &qkvh[koff]);
            cp16(sb + (uint32_t)(KT * QS + r * VS + l_q * 8) * 2, &qkvh[voff]);
        }
    };

    issue(0, 0);
    CP_COMMIT();

    // Load Q tile (hi/lo) with regular loads (once)
    #pragma unroll
    for (int i = 0; i < 4; i++) {
        int u = tid + i * 256, r = u >> 3, q = u & 7;
        size_t off = (rowbase + q0 + r) * QKV_N + h * DH + q * 8;
        *reinterpret_cast<uint4*>(&sQh[r * QS + q * 8]) =
            *reinterpret_cast<const uint4*>(&qkvh[off]);
        *reinterpret_cast<uint4*>(&sQl[r * QS + q * 8]) =
            *reinterpret_cast<const uint4*>(&qkvl[off]);
    }
    __syncthreads();

    uint32_t qh[4][4], ql[4][4];
    {
        int r = wid * 16 + g;
        #pragma unroll
        for (int ks = 0; ks < 4; ks++) {
            int c = ks * 16 + tg * 2;
            qh[ks][0] = *reinterpret_cast<const uint32_t*>(&sQh[r * QS + c]);
            qh[ks][1] = *reinterpret_cast<const uint32_t*>(&sQh[(r + 8) * QS + c]);
            qh[ks][2] = *reinterpret_cast<const uint32_t*>(&sQh[r * QS + c + 8]);
            qh[ks][3] = *reinterpret_cast<const uint32_t*>(&sQh[(r + 8) * QS + c + 8]);
            ql[ks][0] = *reinterpret_cast<const uint32_t*>(&sQl[r * QS + c]);
            ql[ks][1] = *reinterpret_cast<const uint32_t*>(&sQl[(r + 8) * QS + c]);
            ql[ks][2] = *reinterpret_cast<const uint32_t*>(&sQl[r * QS + c + 8]);
            ql[ks][3] = *reinterpret_cast<const uint32_t*>(&sQl[(r + 8) * QS + c + 8]);
        }
    }

    float oacc[8][4];
    #pragma unroll
    for (int nt = 0; nt < 8; nt++)
        #pragma unroll
        for (int i = 0; i < 4; i++) oacc[nt][i] = 0.0f;
    float m0 = -1e30f, m1 = -1e30f, l0 = 0.0f, l1 = 0.0f;

    const int nkt = SEQ / KT;
    for (int kt = 0; kt < nkt; kt++) {
        CP_WAIT0();
        __syncthreads();
        if (kt + 1 < nkt) { issue(kt + 1, (kt + 1) & 1); CP_COMMIT(); }

        const __half* sKh = sKV + (kt & 1) * A_KVSTG;
        const uint32_t sV_u = kv_base_u + (uint32_t)((kt & 1) * A_KVSTG + KT * QS) * 2;

        // S = Q K^T (2 MMAs per step)
        float sacc[8][4];
        #pragma unroll
        for (int nt = 0; nt < 8; nt++)
            #pragma unroll
            for (int i = 0; i < 4; i++) sacc[nt][i] = 0.0f;
        #pragma unroll
        for (int ks = 0; ks < 4; ks++) {
            #pragma unroll
            for (int nt = 0; nt < 8; nt++) {
                int rn = nt * 8 + g;
                int c  = ks * 16 + tg * 2;
                uint32_t kh2[2];
                kh2[0] = *reinterpret_cast<const uint32_t*>(&sKh[rn * QS + c]);
                kh2[1] = *reinterpret_cast<const uint32_t*>(&sKh[rn * QS + c + 8]);
                mma_f16(sacc[nt], qh[ks], kh2);
                mma_f16(sacc[nt], ql[ks], kh2);
            }
        }

        // Online softmax (log2 domain)
        float mx0 = -1e30f, mx1 = -1e30f;
        #pragma unroll
        for (int nt = 0; nt < 8; nt++) {
            mx0 = fmaxf(mx0, fmaxf(sacc[nt][0], sacc[nt][1]));
            mx1 = fmaxf(mx1, fmaxf(sacc[nt][2], sacc[nt][3]));
        }
        mx0 = fmaxf(mx0, __shfl_xor_sync(0xffffffffu, mx0, 1));
        mx0 = fmaxf(mx0, __shfl_xor_sync(0xffffffffu, mx0, 2));
        mx1 = fmaxf(mx1, __shfl_xor_sync(0xffffffffu, mx1, 1));
        mx1 = fmaxf(mx1, __shfl_xor_sync(0xffffffffu, mx1, 2));
        float nm0 = fmaxf(m0, mx0), nm1 = fmaxf(m1, mx1);
        float a0 = exp2_poly(m0 - nm0), a1 = exp2_poly(m1 - nm1);

        float rs0 = 0.0f, rs1 = 0.0f;
        uint32_t pah[8], pbh[8], pal[8], pbl[8];
        #pragma unroll
        for (int nt = 0; nt < 8; nt++) {
            float p0 = exp2_poly(sacc[nt][0] - nm0);
            float p1 = exp2_poly(sacc[nt][1] - nm0);
            float p2 = exp2_poly(sacc[nt][2] - nm1);
            float p3 = exp2_poly(sacc[nt][3] - nm1);
            rs0 += p0 + p1; rs1 += p2 + p3;
            __half2 h01 = __floats2half2_rn(p0, p1);
            __half2 h23 = __floats2half2_rn(p2, p3);
            pah[nt] = pk(h01);
            pbh[nt] = pk(h23);
            pal[nt] = pk(__floats2half2_rn(
                p0 - __low2float(h01), p1 - __high2float(h01)));
            pbl[nt] = pk(__floats2half2_rn(
                p2 - __low2float(h23), p3 - __high2float(h23)));
        }
        rs0 += __shfl_xor_sync(0xffffffffu, rs0, 1);
        rs0 += __shfl_xor_sync(0xffffffffu, rs0, 2);
        rs1 += __shfl_xor_sync(0xffffffffu, rs1, 1);
        rs1 += __shfl_xor_sync(0xffffffffu, rs1, 2);
        l0 = l0 * a0 + rs0;
        l1 = l1 * a1 + rs1;
        m0 = nm0; m1 = nm1;
        #pragma unroll
        for (int nt = 0; nt < 8; nt++) {
            oacc[nt][0] *= a0; oacc[nt][1] *= a0;
            oacc[nt][2] *= a1; oacc[nt][3] *= a1;
        }

        // O += P V  (2 MMAs; V fragments via ldmatrix.trans)
        #pragma unroll
        for (int ks = 0; ks < 4; ks++) {
            uint32_t pAh[4] = {pah[2*ks], pbh[2*ks], pah[2*ks+1], pbh[2*ks+1]};
            uint32_t pAl[4] = {pal[2*ks], pbl[2*ks], pal[2*ks+1], pbl[2*ks+1]};
            #pragma unroll
            for (int ntp = 0; ntp < 4; ntp++) {
                uint32_t v0, v1, v2, v3;
                uint32_t addr = sV_u + voff0
                              + (uint32_t)((ks * 16 * VS + ntp * 16) * 2);
                ldsm_x4_t(v0, v1, v2, v3, addr);
                uint32_t vb0[2] = {v0, v1};
                uint32_t vb1[2] = {v2, v3};
                mma_f16(oacc[2*ntp],     pAh, vb0);
                mma_f16(oacc[2*ntp],     pAl, vb0);
                mma_f16(oacc[2*ntp + 1], pAh, vb1);
                mma_f16(oacc[2*ntp + 1], pAl, vb1);
            }
        }
        __syncthreads();
    }

    // Epilogue: normalize, split fp16 hi/lo, store
    float inv0 = 1.0f / l0, inv1 = 1.0f / l1;
    int qrow = q0 + wid * 16 + g;
    #pragma unroll
    for (int nt = 0; nt < 8; nt++) {
        int col = h * DH + nt * 8 + tg * 2;
        float v0 = oacc[nt][0] * inv0, v1 = oacc[nt][1] * inv0;
        float v2 = oacc[nt][2] * inv1, v3 = oacc[nt][3] * inv1;
        __half2 h01 = __floats2half2_rn(v0, v1);
        __half2 h23 = __floats2half2_rn(v2, v3);
        __half2 l01 = __floats2half2_rn(v0 - __low2float(h01), v1 - __high2float(h01));
        __half2 l23 = __floats2half2_rn(v2 - __low2float(h23), v3 - __high2float(h23));
        *reinterpret_cast<uint32_t*>(&oh[(rowbase + qrow) * EMBD + col])     = pk(h01);
        *reinterpret_cast<uint32_t*>(&ol[(rowbase + qrow) * EMBD + col])     = pk(l01);
        *reinterpret_cast<uint32_t*>(&oh[(rowbase + qrow + 8) * EMBD + col]) = pk(h23);
        *reinterpret_cast<uint32_t*>(&ol[(rowbase + qrow + 8) * EMBD + col]) = pk(l23);
    }
}

// ---------------------------------------------------------------------------
// Launch
// ---------------------------------------------------------------------------
extern "C" void kernel_launch(void* const* d_in, const int* in_sizes, int n_in,
                              void* d_out, int out_size)
{
    const float* x     = (const float*)d_in[0];
    const float* W_in  = (const float*)d_in[1];
    const float* b_in  = (const float*)d_in[2];
    const float* W_out = (const float*)d_in[3];
    const float* b_out = (const float*)d_in[4];
    float* out = (float*)d_out;

    __half *xh, *xl, *wih, *woh, *qh, *ql, *ah, *al;
    cudaGetSymbolAddress((void**)&xh,  g_xh);  cudaGetSymbolAddress((void**)&xl,  g_xl);
    cudaGetSymbolAddress((void**)&wih, g_wih);
    cudaGetSymbolAddress((void**)&woh, g_woh);
    cudaGetSymbolAddress((void**)&qh,  g_qh);  cudaGetSymbolAddress((void**)&ql,  g_ql);
    cudaGetSymbolAddress((void**)&ah,  g_ah);  cudaGetSymbolAddress((void**)&al,  g_al);

    const int gemm_smem = 2 * G_STG * (int)sizeof(__half);
    const int attn_smem = (2 * A_QSZ + 2 * A_KVSTG) * (int)sizeof(__half);
    cudaFuncSetAttribute(gemm_mma, cudaFuncAttributeMaxDynamicSharedMemorySize, gemm_smem);
    cudaFuncSetAttribute(attn_mma, cudaFuncAttributeMaxDynamicSharedMemorySize, attn_smem);

    {
        int n1 = M_TOT * EMBD;
        split_hl<<<n1 / 1024, 256>>>(x, xh, xl, n1);
        int n2 = QKV_N * EMBD;
        cvt_h<<<n2 / 1024, 256>>>(W_in, wih, n2);
        int n3 = EMBD * EMBD;
        cvt_h<<<n3 / 1024, 256>>>(W_out, woh, n3);
    }
    {
        dim3 grid(QKV_N / 128, M_TOT / 128);
        gemm_mma<<<grid, 256, gemm_smem>>>(xh, xl, wih, b_in,
                                           nullptr, qh, ql,
                                           QKV_N, EMBD, EMBD);
    }
    {
        dim3 grid(SEQ / 128, NH, BATCH);
        attn_mma<<<grid, 256, attn_smem>>>(qh, ql, ah, al);
    }
    {
        dim3 grid(EMBD / 128, M_TOT / 128);
        gemm_mma<<<grid, 256, gemm_smem>>>(ah, al, woh, b_out,
                                           out, nullptr, nullptr,
                                           EMBD, EMBD, 0);
    }
}

// round 7
// speedup vs baseline: 3.6246x; 1.0800x over previous
#include <cuda_runtime.h>
#include <cuda_fp16.h>
#include <cstdint>
#include <math.h>

#define EMBD   1024
#define NH     16
#define DH     64
#define BATCH  2
#define SEQ    2048
#define M_TOT  (BATCH * SEQ)   // 4096
#define QKV_N  (3 * EMBD)      // 3072

// ---------------------------------------------------------------------------
// Scratch (fp16; allocation-free rule: __device__ globals)
// ---------------------------------------------------------------------------
__device__ __half g_xh [M_TOT * EMBD],  g_xl [M_TOT * EMBD];
__device__ __half g_wih[QKV_N * EMBD];
__device__ __half g_woh[EMBD * EMBD];
__device__ __half g_qh [M_TOT * QKV_N], g_ql [M_TOT * QKV_N];
__device__ __half g_ah [M_TOT * EMBD],  g_al [M_TOT * EMBD];

// ---------------------------------------------------------------------------
// Helpers
// ---------------------------------------------------------------------------
__device__ __forceinline__ void mma_f16(float* c, const uint32_t* a,
                                        const uint32_t* b) {
    asm volatile(
        "mma.sync.aligned.m16n8k16.row.col.f32.f16.f16.f32 "
        "{%0,%1,%2,%3}, {%4,%5,%6,%7}, {%8,%9}, {%0,%1,%2,%3};"
        : "+f"(c[0]), "+f"(c[1]), "+f"(c[2]), "+f"(c[3])
        : "r"(a[0]), "r"(a[1]), "r"(a[2]), "r"(a[3]), "r"(b[0]), "r"(b[1]));
}

__device__ __forceinline__ void ldsm_x4(uint32_t& r0, uint32_t& r1,
                                        uint32_t& r2, uint32_t& r3,
                                        uint32_t a) {
    asm volatile("ldmatrix.sync.aligned.m8n8.x4.shared.b16 "
                 "{%0,%1,%2,%3}, [%4];"
                 : "=r"(r0), "=r"(r1), "=r"(r2), "=r"(r3) : "r"(a));
}

__device__ __forceinline__ void ldsm_x4_t(uint32_t& r0, uint32_t& r1,
                                          uint32_t& r2, uint32_t& r3,
                                          uint32_t a) {
    asm volatile("ldmatrix.sync.aligned.m8n8.x4.trans.shared.b16 "
                 "{%0,%1,%2,%3}, [%4];"
                 : "=r"(r0), "=r"(r1), "=r"(r2), "=r"(r3) : "r"(a));
}

__device__ __forceinline__ uint32_t smem_u32(const void* p) {
    uint32_t a;
    asm("{ .reg .u64 t; cvta.to.shared.u64 t, %1; cvt.u32.u64 %0, t; }"
        : "=r"(a) : "l"(p));
    return a;
}

__device__ __forceinline__ void cp16(uint32_t dst, const void* src) {
    asm volatile("cp.async.cg.shared.global [%0], [%1], 16;"
                 :: "r"(dst), "l"(src));
}
#define CP_COMMIT() asm volatile("cp.async.commit_group;")
#define CP_WAIT0()  asm volatile("cp.async.wait_group 0;")
#define CP_WAIT1()  asm volatile("cp.async.wait_group 1;")

// FFMA-only 2^x (avoids MUFU throttle). Valid for x <= 0 (clamped at -80).
__device__ __forceinline__ float exp2_poly(float x) {
    x = fmaxf(x, -80.0f);
    float t = x + 12582912.0f;
    float n = t - 12582912.0f;
    float f = x - n;
    float p = 1.33335581e-3f;
    p = fmaf(p, f, 9.61812911e-3f);
    p = fmaf(p, f, 5.55041087e-2f);
    p = fmaf(p, f, 2.40226507e-1f);
    p = fmaf(p, f, 6.93147181e-1f);
    p = fmaf(p, f, 1.0f);
    int e = (int)n;
    return p * __int_as_float((e + 127) << 23);
}

__device__ __forceinline__ uint32_t pk(__half2 v) {
    return *reinterpret_cast<uint32_t*>(&v);
}

// ---------------------------------------------------------------------------
// fp32 -> fp16 hi/lo split  and  fp32 -> fp16 single
// ---------------------------------------------------------------------------
__global__ void split_hl(const float* __restrict__ s,
                         __half* __restrict__ h, __half* __restrict__ l, int n)
{
    int i = (blockIdx.x * blockDim.x + threadIdx.x) * 4;
    if (i >= n) return;
    float4 v = *reinterpret_cast<const float4*>(&s[i]);
    __half2 h0 = __floats2half2_rn(v.x, v.y);
    __half2 h1 = __floats2half2_rn(v.z, v.w);
    __half2 l0 = __floats2half2_rn(v.x - __low2float(h0), v.y - __high2float(h0));
    __half2 l1 = __floats2half2_rn(v.z - __low2float(h1), v.w - __high2float(h1));
    *reinterpret_cast<__half2*>(&h[i])     = h0;
    *reinterpret_cast<__half2*>(&h[i + 2]) = h1;
    *reinterpret_cast<__half2*>(&l[i])     = l0;
    *reinterpret_cast<__half2*>(&l[i + 2]) = l1;
}

__global__ void cvt_h(const float* __restrict__ s, __half* __restrict__ h, int n)
{
    int i = (blockIdx.x * blockDim.x + threadIdx.x) * 4;
    if (i >= n) return;
    float4 v = *reinterpret_cast<const float4*>(&s[i]);
    *reinterpret_cast<__half2*>(&h[i])     = __floats2half2_rn(v.x, v.y);
    *reinterpret_cast<__half2*>(&h[i + 2]) = __floats2half2_rn(v.z, v.w);
}

// ---------------------------------------------------------------------------
// GEMM: C[m,n] = (Ah+Al)[m,:]·B[n,:] + bias[n]   (2 MMAs: Ah·B + Al·B)
// 128x128 tile, BK=32, cp.async 3-stage pipeline, ldmatrix fragment loads.
// ---------------------------------------------------------------------------
#define AS 40
#define G_TILE (128 * AS)          // halfs per operand tile
#define G_STG  (3 * G_TILE)        // halfs per stage
#define G_NSTG 3

__global__ __launch_bounds__(256, 2)
void gemm_mma(const __half* __restrict__ Ah_g,
              const __half* __restrict__ Al_g,
              const __half* __restrict__ Bh_g,
              const float* __restrict__ bias,
              float* __restrict__ Cf,
              __half* __restrict__ Ch,
              __half* __restrict__ Cl,
              int N, int K, int scale_lim)
{
    extern __shared__ __half sm[];
    const uint32_t smb = smem_u32(sm);

    const int tid  = threadIdx.x;
    const int wid  = tid >> 5;
    const int lane = tid & 31;
    const int g    = lane >> 2;
    const int tg   = lane & 3;
    const int warp_m = (wid & 3) * 32;
    const int warp_n = (wid >> 2) * 64;
    const int bm = blockIdx.y * 128;
    const int bn = blockIdx.x * 128;

    const int l_row = tid >> 2;
    const int l_q   = tid & 3;

    // ldmatrix per-lane row/col offsets (halfs)
    const int aRow = warp_m + (lane & 15);
    const int aCol = (lane >> 4) * 8;
    const int bRow = warp_n + (lane & 7) + ((lane >> 4) << 3);
    const int bCol = ((lane >> 3) & 1) * 8;

    float acc[2][8][4];
    #pragma unroll
    for (int mt = 0; mt < 2; mt++)
        #pragma unroll
        for (int nt = 0; nt < 8; nt++)
            #pragma unroll
            for (int i = 0; i < 4; i++) acc[mt][nt][i] = 0.0f;

    const int nch = K / 32;

    auto issue = [&](int ch) {
        int k0 = ch * 32;
        uint32_t sb = smb + (uint32_t)((ch % G_NSTG) * G_STG) * 2;
        #pragma unroll
        for (int i = 0; i < 2; i++) {
            int row = l_row + i * 64;
            uint32_t so = (uint32_t)(row * AS + l_q * 8) * 2;
            size_t oA = (size_t)(bm + row) * K + k0 + l_q * 8;
            size_t oB = (size_t)(bn + row) * K + k0 + l_q * 8;
            cp16(sb + so,                  &Ah_g[oA]);
            cp16(sb + G_TILE * 2 + so,     &Al_g[oA]);
            cp16(sb + 2 * G_TILE * 2 + so, &Bh_g[oB]);
        }
    };

    issue(0); CP_COMMIT();
    issue(1); CP_COMMIT();

    for (int ch = 0; ch < nch; ch++) {
        CP_WAIT1();
        __syncthreads();
        if (ch + 2 < nch) issue(ch + 2);
        CP_COMMIT();

        uint32_t stg = smb + (uint32_t)((ch % G_NSTG) * G_STG) * 2;
        uint32_t aHb = stg;
        uint32_t aLb = stg + (uint32_t)G_TILE * 2;
        uint32_t bHb = stg + (uint32_t)(2 * G_TILE) * 2;

        #pragma unroll
        for (int ks = 0; ks < 2; ks++) {
            uint32_t ah[2][4], al[2][4], bf[8][2];
            #pragma unroll
            for (int mt = 0; mt < 2; mt++) {
                uint32_t ao = (uint32_t)(((aRow + mt * 16) * AS) + ks * 16 + aCol) * 2;
                ldsm_x4(ah[mt][0], ah[mt][1], ah[mt][2], ah[mt][3], aHb + ao);
                ldsm_x4(al[mt][0], al[mt][1], al[mt][2], al[mt][3], aLb + ao);
            }
            #pragma unroll
            for (int q = 0; q < 4; q++) {
                uint32_t bo = (uint32_t)(((bRow + q * 16) * AS) + ks * 16 + bCol) * 2;
                ldsm_x4(bf[2*q][0], bf[2*q][1], bf[2*q+1][0], bf[2*q+1][1], bHb + bo);
            }
            #pragma unroll
            for (int nt = 0; nt < 8; nt++) {
                #pragma unroll
                for (int mt = 0; mt < 2; mt++) {
                    mma_f16(acc[mt][nt], ah[mt], bf[nt]);
                    mma_f16(acc[mt][nt], al[mt], bf[nt]);
                }
            }
        }
    }

    const float SCALE = 0.18033688f;   // 0.125 * log2(e)
    #pragma unroll
    for (int mt = 0; mt < 2; mt++) {
        int r0 = bm + warp_m + mt * 16 + g;
        #pragma unroll
        for (int nt = 0; nt < 8; nt++) {
            int col = bn + warp_n + nt * 8 + tg * 2;
            float b0 = __ldg(&bias[col]), b1 = __ldg(&bias[col + 1]);
            float v0 = acc[mt][nt][0] + b0, v1 = acc[mt][nt][1] + b1;
            float v2 = acc[mt][nt][2] + b0, v3 = acc[mt][nt][3] + b1;
            if (Cf) {
                *reinterpret_cast<float2*>(&Cf[(size_t)r0 * N + col])
                    = make_float2(v0, v1);
                *reinterpret_cast<float2*>(&Cf[(size_t)(r0 + 8) * N + col])
                    = make_float2(v2, v3);
            } else {
                bool isq = col < scale_lim;
                if (isq) { v0 *= SCALE; v1 *= SCALE; v2 *= SCALE; v3 *= SCALE; }
                __half2 h01 = __floats2half2_rn(v0, v1);
                __half2 h23 = __floats2half2_rn(v2, v3);
                *reinterpret_cast<uint32_t*>(&Ch[(size_t)r0 * N + col])       = pk(h01);
                *reinterpret_cast<uint32_t*>(&Ch[(size_t)(r0 + 8) * N + col]) = pk(h23);
                if (isq) {
                    __half2 l01 = __floats2half2_rn(
                        v0 - __low2float(h01), v1 - __high2float(h01));
                    __half2 l23 = __floats2half2_rn(
                        v2 - __low2float(h23), v3 - __high2float(h23));
                    *reinterpret_cast<uint32_t*>(&Cl[(size_t)r0 * N + col])       = pk(l01);
                    *reinterpret_cast<uint32_t*>(&Cl[(size_t)(r0 + 8) * N + col]) = pk(l23);
                }
            }
        }
    }
}

// ---------------------------------------------------------------------------
// Flash attention, cp.async 2-stage K/V pipeline, one barrier per tile.
// S=(Qh+Ql)·K (K frags via ldmatrix), PV=(Ph+Pl)·V (V via ldmatrix.trans).
// Q pre-scaled by 0.125*log2e -> exp2-domain softmax (FFMA poly).
// ---------------------------------------------------------------------------
#define QS 72
#define VS 72
#define KT 64
#define A_QSZ   (128 * QS)
#define A_KVSTG (KT * QS + KT * VS)

__global__ __launch_bounds__(256)
void attn_mma(const __half* __restrict__ qkvh,
              const __half* __restrict__ qkvl,
              __half* __restrict__ oh,
              __half* __restrict__ ol)
{
    extern __shared__ __half sm[];
    __half* sQh = sm;                       // [128][QS]
    __half* sQl = sQh + A_QSZ;

    const int tid  = threadIdx.x;
    const int wid  = tid >> 5;
    const int lane = tid & 31;
    const int g    = lane >> 2;
    const int tg   = lane & 3;
    const int q0 = blockIdx.x * 128;
    const int h  = blockIdx.y;
    const int b  = blockIdx.z;
    const size_t rowbase = (size_t)b * SEQ;

    const uint32_t smb = smem_u32(sm);
    const uint32_t kv_base_u = smb + (uint32_t)(2 * A_QSZ) * 2;

    // ldmatrix lane offsets
    const int kRow = (lane & 7) + ((lane >> 4) << 3);        // K frags (non-T)
    const int kCol = ((lane >> 3) & 1) * 8;
    const int lr = lane & 7, lq = (lane >> 3) & 1, lh2 = lane >> 4;
    const uint32_t voff0 = (uint32_t)(((lq * 8 + lr) * VS + lh2 * 8) * 2);

    const int l_r = tid >> 3;
    const int l_q = tid & 7;

    auto issue = [&](int kt) {
        uint32_t sb = kv_base_u + (uint32_t)((kt & 1) * A_KVSTG) * 2;
        #pragma unroll
        for (int i = 0; i < 2; i++) {
            int r = l_r + i * 32;
            size_t koff = (rowbase + kt * KT + r) * QKV_N + EMBD + h * DH + l_q * 8;
            size_t voff = koff + EMBD;
            cp16(sb + (uint32_t)(r * QS + l_q * 8) * 2, &qkvh[koff]);
            cp16(sb + (uint32_t)(KT * QS + r * VS + l_q * 8) * 2, &qkvh[voff]);
        }
    };

    issue(0);
    CP_COMMIT();

    // Load Q tile (hi/lo) once
    #pragma unroll
    for (int i = 0; i < 4; i++) {
        int u = tid + i * 256, r = u >> 3, q = u & 7;
        size_t off = (rowbase + q0 + r) * QKV_N + h * DH + q * 8;
        *reinterpret_cast<uint4*>(&sQh[r * QS + q * 8]) =
            *reinterpret_cast<const uint4*>(&qkvh[off]);
        *reinterpret_cast<uint4*>(&sQl[r * QS + q * 8]) =
            *reinterpret_cast<const uint4*>(&qkvl[off]);
    }
    __syncthreads();

    uint32_t qh[4][4], ql[4][4];
    {
        // A-frag ldmatrix loads for Q (row = wid*16 + (lane&15))
        const uint32_t qHb = smb;
        const uint32_t qLb = smb + (uint32_t)A_QSZ * 2;
        int r = wid * 16 + (lane & 15);
        int co = (lane >> 4) * 8;
        #pragma unroll
        for (int ks = 0; ks < 4; ks++) {
            uint32_t ao = (uint32_t)(r * QS + ks * 16 + co) * 2;
            ldsm_x4(qh[ks][0], qh[ks][1], qh[ks][2], qh[ks][3], qHb + ao);
            ldsm_x4(ql[ks][0], ql[ks][1], ql[ks][2], ql[ks][3], qLb + ao);
        }
    }

    float oacc[8][4];
    #pragma unroll
    for (int nt = 0; nt < 8; nt++)
        #pragma unroll
        for (int i = 0; i < 4; i++) oacc[nt][i] = 0.0f;
    float m0 = -1e30f, m1 = -1e30f, l0 = 0.0f, l1 = 0.0f;

    const int nkt = SEQ / KT;
    for (int kt = 0; kt < nkt; kt++) {
        CP_WAIT0();
        __syncthreads();
        if (kt + 1 < nkt) issue(kt + 1);
        CP_COMMIT();

        const uint32_t sK_u = kv_base_u + (uint32_t)((kt & 1) * A_KVSTG) * 2;
        const uint32_t sV_u = sK_u + (uint32_t)(KT * QS) * 2;

        // S = Q K^T (2 MMAs per step; K frags via ldmatrix)
        float sacc[8][4];
        #pragma unroll
        for (int nt = 0; nt < 8; nt++)
            #pragma unroll
            for (int i = 0; i < 4; i++) sacc[nt][i] = 0.0f;
        #pragma unroll
        for (int ks = 0; ks < 4; ks++) {
            uint32_t kf[8][2];
            #pragma unroll
            for (int q = 0; q < 4; q++) {
                uint32_t ko = (uint32_t)(((kRow + q * 16) * QS) + ks * 16 + kCol) * 2;
                ldsm_x4(kf[2*q][0], kf[2*q][1], kf[2*q+1][0], kf[2*q+1][1], sK_u + ko);
            }
            #pragma unroll
            for (int nt = 0; nt < 8; nt++) {
                mma_f16(sacc[nt], qh[ks], kf[nt]);
                mma_f16(sacc[nt], ql[ks], kf[nt]);
            }
        }

        // Online softmax (log2 domain)
        float mx0 = -1e30f, mx1 = -1e30f;
        #pragma unroll
        for (int nt = 0; nt < 8; nt++) {
            mx0 = fmaxf(mx0, fmaxf(sacc[nt][0], sacc[nt][1]));
            mx1 = fmaxf(mx1, fmaxf(sacc[nt][2], sacc[nt][3]));
        }
        mx0 = fmaxf(mx0, __shfl_xor_sync(0xffffffffu, mx0, 1));
        mx0 = fmaxf(mx0, __shfl_xor_sync(0xffffffffu, mx0, 2));
        mx1 = fmaxf(mx1, __shfl_xor_sync(0xffffffffu, mx1, 1));
        mx1 = fmaxf(mx1, __shfl_xor_sync(0xffffffffu, mx1, 2));
        float nm0 = fmaxf(m0, mx0), nm1 = fmaxf(m1, mx1);
        float a0 = exp2_poly(m0 - nm0), a1 = exp2_poly(m1 - nm1);

        float rs0 = 0.0f, rs1 = 0.0f;
        uint32_t pah[8], pbh[8], pal[8], pbl[8];
        #pragma unroll
        for (int nt = 0; nt < 8; nt++) {
            float p0 = exp2_poly(sacc[nt][0] - nm0);
            float p1 = exp2_poly(sacc[nt][1] - nm0);
            float p2 = exp2_poly(sacc[nt][2] - nm1);
            float p3 = exp2_poly(sacc[nt][3] - nm1);
            rs0 += p0 + p1; rs1 += p2 + p3;
            __half2 h01 = __floats2half2_rn(p0, p1);
            __half2 h23 = __floats2half2_rn(p2, p3);
            pah[nt] = pk(h01);
            pbh[nt] = pk(h23);
            pal[nt] = pk(__floats2half2_rn(
                p0 - __low2float(h01), p1 - __high2float(h01)));
            pbl[nt] = pk(__floats2half2_rn(
                p2 - __low2float(h23), p3 - __high2float(h23)));
        }
        rs0 += __shfl_xor_sync(0xffffffffu, rs0, 1);
        rs0 += __shfl_xor_sync(0xffffffffu, rs0, 2);
        rs1 += __shfl_xor_sync(0xffffffffu, rs1, 1);
        rs1 += __shfl_xor_sync(0xffffffffu, rs1, 2);
        l0 = l0 * a0 + rs0;
        l1 = l1 * a1 + rs1;
        m0 = nm0; m1 = nm1;
        #pragma unroll
        for (int nt = 0; nt < 8; nt++) {
            oacc[nt][0] *= a0; oacc[nt][1] *= a0;
            oacc[nt][2] *= a1; oacc[nt][3] *= a1;
        }

        // O += P V  (2 MMAs; V fragments via ldmatrix.trans)
        #pragma unroll
        for (int ks = 0; ks < 4; ks++) {
            uint32_t pAh[4] = {pah[2*ks], pbh[2*ks], pah[2*ks+1], pbh[2*ks+1]};
            uint32_t pAl[4] = {pal[2*ks], pbl[2*ks], pal[2*ks+1], pbl[2*ks+1]};
            #pragma unroll
            for (int ntp = 0; ntp < 4; ntp++) {
                uint32_t v0, v1, v2, v3;
                uint32_t addr = sV_u + voff0
                              + (uint32_t)((ks * 16 * VS + ntp * 16) * 2);
                ldsm_x4_t(v0, v1, v2, v3, addr);
                uint32_t vb0[2] = {v0, v1};
                uint32_t vb1[2] = {v2, v3};
                mma_f16(oacc[2*ntp],     pAh, vb0);
                mma_f16(oacc[2*ntp],     pAl, vb0);
                mma_f16(oacc[2*ntp + 1], pAh, vb1);
                mma_f16(oacc[2*ntp + 1], pAl, vb1);
            }
        }
    }

    // Epilogue: normalize, split fp16 hi/lo, store
    float inv0 = 1.0f / l0, inv1 = 1.0f / l1;
    int qrow = q0 + wid * 16 + g;
    #pragma unroll
    for (int nt = 0; nt < 8; nt++) {
        int col = h * DH + nt * 8 + tg * 2;
        float v0 = oacc[nt][0] * inv0, v1 = oacc[nt][1] * inv0;
        float v2 = oacc[nt][2] * inv1, v3 = oacc[nt][3] * inv1;
        __half2 h01 = __floats2half2_rn(v0, v1);
        __half2 h23 = __floats2half2_rn(v2, v3);
        __half2 l01 = __floats2half2_rn(v0 - __low2float(h01), v1 - __high2float(h01));
        __half2 l23 = __floats2half2_rn(v2 - __low2float(h23), v3 - __high2float(h23));
        *reinterpret_cast<uint32_t*>(&oh[(rowbase + qrow) * EMBD + col])     = pk(h01);
        *reinterpret_cast<uint32_t*>(&ol[(rowbase + qrow) * EMBD + col])     = pk(l01);
        *reinterpret_cast<uint32_t*>(&oh[(rowbase + qrow + 8) * EMBD + col]) = pk(h23);
        *reinterpret_cast<uint32_t*>(&ol[(rowbase + qrow + 8) * EMBD + col]) = pk(l23);
    }
}

// ---------------------------------------------------------------------------
// Launch
// ---------------------------------------------------------------------------
extern "C" void kernel_launch(void* const* d_in, const int* in_sizes, int n_in,
                              void* d_out, int out_size)
{
    const float* x     = (const float*)d_in[0];
    const float* W_in  = (const float*)d_in[1];
    const float* b_in  = (const float*)d_in[2];
    const float* W_out = (const float*)d_in[3];
    const float* b_out = (const float*)d_in[4];
    float* out = (float*)d_out;

    __half *xh, *xl, *wih, *woh, *qh, *ql, *ah, *al;
    cudaGetSymbolAddress((void**)&xh,  g_xh);  cudaGetSymbolAddress((void**)&xl,  g_xl);
    cudaGetSymbolAddress((void**)&wih, g_wih);
    cudaGetSymbolAddress((void**)&woh, g_woh);
    cudaGetSymbolAddress((void**)&qh,  g_qh);  cudaGetSymbolAddress((void**)&ql,  g_ql);
    cudaGetSymbolAddress((void**)&ah,  g_ah);  cudaGetSymbolAddress((void**)&al,  g_al);

    const int gemm_smem = G_NSTG * G_STG * (int)sizeof(__half);
    const int attn_smem = (2 * A_QSZ + 2 * A_KVSTG) * (int)sizeof(__half);
    cudaFuncSetAttribute(gemm_mma, cudaFuncAttributeMaxDynamicSharedMemorySize, gemm_smem);
    cudaFuncSetAttribute(attn_mma, cudaFuncAttributeMaxDynamicSharedMemorySize, attn_smem);

    {
        int n1 = M_TOT * EMBD;
        split_hl<<<n1 / 1024, 256>>>(x, xh, xl, n1);
        int n2 = QKV_N * EMBD;
        cvt_h<<<n2 / 1024, 256>>>(W_in, wih, n2);
        int n3 = EMBD * EMBD;
        cvt_h<<<n3 / 1024, 256>>>(W_out, woh, n3);
    }
    {
        dim3 grid(QKV_N / 128, M_TOT / 128);
        gemm_mma<<<grid, 256, gemm_smem>>>(xh, xl, wih, b_in,
                                           nullptr, qh, ql,
                                           QKV_N, EMBD, EMBD);
    }
    {
        dim3 grid(SEQ / 128, NH, BATCH);
        attn_mma<<<grid, 256, attn_smem>>>(qh, ql, ah, al);
    }
    {
        dim3 grid(EMBD / 128, M_TOT / 128);
        gemm_mma<<<grid, 256, gemm_smem>>>(ah, al, woh, b_out,
                                           out, nullptr, nullptr,
                                           EMBD, EMBD, 0);
    }
}

// round 8
// speedup vs baseline: 4.1619x; 1.1482x over previous
#include <cuda_runtime.h>
#include <cuda_fp16.h>
#include <cstdint>
#include <math.h>

#define EMBD   1024
#define NH     16
#define DH     64
#define BATCH  2
#define SEQ    2048
#define M_TOT  (BATCH * SEQ)   // 4096
#define QKV_N  (3 * EMBD)      // 3072

// ---------------------------------------------------------------------------
// Scratch (fp16; allocation-free rule: __device__ globals)
// ---------------------------------------------------------------------------
__device__ __half g_xh [M_TOT * EMBD],  g_xl [M_TOT * EMBD];
__device__ __half g_wih[QKV_N * EMBD];
__device__ __half g_woh[EMBD * EMBD];
__device__ __half g_qh [M_TOT * QKV_N], g_ql [M_TOT * QKV_N];
__device__ __half g_ah [M_TOT * EMBD],  g_al [M_TOT * EMBD];

// ---------------------------------------------------------------------------
// Helpers
// ---------------------------------------------------------------------------
__device__ __forceinline__ void mma_f16(float* c, const uint32_t* a,
                                        const uint32_t* b) {
    asm volatile(
        "mma.sync.aligned.m16n8k16.row.col.f32.f16.f16.f32 "
        "{%0,%1,%2,%3}, {%4,%5,%6,%7}, {%8,%9}, {%0,%1,%2,%3};"
        : "+f"(c[0]), "+f"(c[1]), "+f"(c[2]), "+f"(c[3])
        : "r"(a[0]), "r"(a[1]), "r"(a[2]), "r"(a[3]), "r"(b[0]), "r"(b[1]));
}

__device__ __forceinline__ void ldsm_x4(uint32_t& r0, uint32_t& r1,
                                        uint32_t& r2, uint32_t& r3,
                                        uint32_t a) {
    asm volatile("ldmatrix.sync.aligned.m8n8.x4.shared.b16 "
                 "{%0,%1,%2,%3}, [%4];"
                 : "=r"(r0), "=r"(r1), "=r"(r2), "=r"(r3) : "r"(a));
}

__device__ __forceinline__ void ldsm_x4_t(uint32_t& r0, uint32_t& r1,
                                          uint32_t& r2, uint32_t& r3,
                                          uint32_t a) {
    asm volatile("ldmatrix.sync.aligned.m8n8.x4.trans.shared.b16 "
                 "{%0,%1,%2,%3}, [%4];"
                 : "=r"(r0), "=r"(r1), "=r"(r2), "=r"(r3) : "r"(a));
}

__device__ __forceinline__ uint32_t smem_u32(const void* p) {
    uint32_t a;
    asm("{ .reg .u64 t; cvta.to.shared.u64 t, %1; cvt.u32.u64 %0, t; }"
        : "=r"(a) : "l"(p));
    return a;
}

__device__ __forceinline__ void cp16(uint32_t dst, const void* src) {
    asm volatile("cp.async.cg.shared.global [%0], [%1], 16;"
                 :: "r"(dst), "l"(src));
}
#define CP_COMMIT() asm volatile("cp.async.commit_group;")
#define CP_WAIT0()  asm volatile("cp.async.wait_group 0;")
#define CP_WAIT1()  asm volatile("cp.async.wait_group 1;")

// FFMA-only 2^x (avoids MUFU throttle). Valid for x <= 0 (clamped at -80).
__device__ __forceinline__ float exp2_poly(float x) {
    x = fmaxf(x, -80.0f);
    float t = x + 12582912.0f;
    float n = t - 12582912.0f;
    float f = x - n;
    float p = 1.33335581e-3f;
    p = fmaf(p, f, 9.61812911e-3f);
    p = fmaf(p, f, 5.55041087e-2f);
    p = fmaf(p, f, 2.40226507e-1f);
    p = fmaf(p, f, 6.93147181e-1f);
    p = fmaf(p, f, 1.0f);
    int e = (int)n;
    return p * __int_as_float((e + 127) << 23);
}

__device__ __forceinline__ uint32_t pk(__half2 v) {
    return *reinterpret_cast<uint32_t*>(&v);
}

// ---------------------------------------------------------------------------
// fp32 -> fp16 hi/lo split  and  fp32 -> fp16 single
// ---------------------------------------------------------------------------
__global__ void split_hl(const float* __restrict__ s,
                         __half* __restrict__ h, __half* __restrict__ l, int n)
{
    int i = (blockIdx.x * blockDim.x + threadIdx.x) * 4;
    if (i >= n) return;
    float4 v = *reinterpret_cast<const float4*>(&s[i]);
    __half2 h0 = __floats2half2_rn(v.x, v.y);
    __half2 h1 = __floats2half2_rn(v.z, v.w);
    __half2 l0 = __floats2half2_rn(v.x - __low2float(h0), v.y - __high2float(h0));
    __half2 l1 = __floats2half2_rn(v.z - __low2float(h1), v.w - __high2float(h1));
    *reinterpret_cast<__half2*>(&h[i])     = h0;
    *reinterpret_cast<__half2*>(&h[i + 2]) = h1;
    *reinterpret_cast<__half2*>(&l[i])     = l0;
    *reinterpret_cast<__half2*>(&l[i + 2]) = l1;
}

__global__ void cvt_h(const float* __restrict__ s, __half* __restrict__ h, int n)
{
    int i = (blockIdx.x * blockDim.x + threadIdx.x) * 4;
    if (i >= n) return;
    float4 v = *reinterpret_cast<const float4*>(&s[i]);
    *reinterpret_cast<__half2*>(&h[i])     = __floats2half2_rn(v.x, v.y);
    *reinterpret_cast<__half2*>(&h[i + 2]) = __floats2half2_rn(v.z, v.w);
}

// ---------------------------------------------------------------------------
// GEMM: C[m,n] = (Ah+Al)[m,:]·B[n,:] + bias[n]   (2 MMAs: Ah·B + Al·B)
// 128x128 tile, BK=32, cp.async 3-stage pipeline, ldmatrix fragment loads.
// ---------------------------------------------------------------------------
#define AS 40
#define G_TILE (128 * AS)
#define G_STG  (3 * G_TILE)
#define G_NSTG 3

__global__ __launch_bounds__(256, 2)
void gemm_mma(const __half* __restrict__ Ah_g,
              const __half* __restrict__ Al_g,
              const __half* __restrict__ Bh_g,
              const float* __restrict__ bias,
              float* __restrict__ Cf,
              __half* __restrict__ Ch,
              __half* __restrict__ Cl,
              int N, int K, int scale_lim)
{
    extern __shared__ __half sm[];
    const uint32_t smb = smem_u32(sm);

    const int tid  = threadIdx.x;
    const int wid  = tid >> 5;
    const int lane = tid & 31;
    const int g    = lane >> 2;
    const int tg   = lane & 3;
    const int warp_m = (wid & 3) * 32;
    const int warp_n = (wid >> 2) * 64;
    const int bm = blockIdx.y * 128;
    const int bn = blockIdx.x * 128;

    const int l_row = tid >> 2;
    const int l_q   = tid & 3;

    const int aRow = warp_m + (lane & 15);
    const int aCol = (lane >> 4) * 8;
    const int bRow = warp_n + (lane & 7) + ((lane >> 4) << 3);
    const int bCol = ((lane >> 3) & 1) * 8;

    float acc[2][8][4];
    #pragma unroll
    for (int mt = 0; mt < 2; mt++)
        #pragma unroll
        for (int nt = 0; nt < 8; nt++)
            #pragma unroll
            for (int i = 0; i < 4; i++) acc[mt][nt][i] = 0.0f;

    const int nch = K / 32;

    auto issue = [&](int ch) {
        int k0 = ch * 32;
        uint32_t sb = smb + (uint32_t)((ch % G_NSTG) * G_STG) * 2;
        #pragma unroll
        for (int i = 0; i < 2; i++) {
            int row = l_row + i * 64;
            uint32_t so = (uint32_t)(row * AS + l_q * 8) * 2;
            size_t oA = (size_t)(bm + row) * K + k0 + l_q * 8;
            size_t oB = (size_t)(bn + row) * K + k0 + l_q * 8;
            cp16(sb + so,                  &Ah_g[oA]);
            cp16(sb + G_TILE * 2 + so,     &Al_g[oA]);
            cp16(sb + 2 * G_TILE * 2 + so, &Bh_g[oB]);
        }
    };

    issue(0); CP_COMMIT();
    issue(1); CP_COMMIT();

    for (int ch = 0; ch < nch; ch++) {
        CP_WAIT1();
        __syncthreads();
        if (ch + 2 < nch) issue(ch + 2);
        CP_COMMIT();

        uint32_t stg = smb + (uint32_t)((ch % G_NSTG) * G_STG) * 2;
        uint32_t aHb = stg;
        uint32_t aLb = stg + (uint32_t)G_TILE * 2;
        uint32_t bHb = stg + (uint32_t)(2 * G_TILE) * 2;

        #pragma unroll
        for (int ks = 0; ks < 2; ks++) {
            uint32_t ah[2][4], al[2][4], bf[8][2];
            #pragma unroll
            for (int mt = 0; mt < 2; mt++) {
                uint32_t ao = (uint32_t)(((aRow + mt * 16) * AS) + ks * 16 + aCol) * 2;
                ldsm_x4(ah[mt][0], ah[mt][1], ah[mt][2], ah[mt][3], aHb + ao);
                ldsm_x4(al[mt][0], al[mt][1], al[mt][2], al[mt][3], aLb + ao);
            }
            #pragma unroll
            for (int q = 0; q < 4; q++) {
                uint32_t bo = (uint32_t)(((bRow + q * 16) * AS) + ks * 16 + bCol) * 2;
                ldsm_x4(bf[2*q][0], bf[2*q][1], bf[2*q+1][0], bf[2*q+1][1], bHb + bo);
            }
            #pragma unroll
            for (int nt = 0; nt < 8; nt++) {
                #pragma unroll
                for (int mt = 0; mt < 2; mt++) {
                    mma_f16(acc[mt][nt], ah[mt], bf[nt]);
                    mma_f16(acc[mt][nt], al[mt], bf[nt]);
                }
            }
        }
    }

    const float SCALE = 0.18033688f;   // 0.125 * log2(e)
    #pragma unroll
    for (int mt = 0; mt < 2; mt++) {
        int r0 = bm + warp_m + mt * 16 + g;
        #pragma unroll
        for (int nt = 0; nt < 8; nt++) {
            int col = bn + warp_n + nt * 8 + tg * 2;
            float b0 = __ldg(&bias[col]), b1 = __ldg(&bias[col + 1]);
            float v0 = acc[mt][nt][0] + b0, v1 = acc[mt][nt][1] + b1;
            float v2 = acc[mt][nt][2] + b0, v3 = acc[mt][nt][3] + b1;
            if (Cf) {
                *reinterpret_cast<float2*>(&Cf[(size_t)r0 * N + col])
                    = make_float2(v0, v1);
                *reinterpret_cast<float2*>(&Cf[(size_t)(r0 + 8) * N + col])
                    = make_float2(v2, v3);
            } else {
                bool isq = col < scale_lim;
                if (isq) { v0 *= SCALE; v1 *= SCALE; v2 *= SCALE; v3 *= SCALE; }
                __half2 h01 = __floats2half2_rn(v0, v1);
                __half2 h23 = __floats2half2_rn(v2, v3);
                *reinterpret_cast<uint32_t*>(&Ch[(size_t)r0 * N + col])       = pk(h01);
                *reinterpret_cast<uint32_t*>(&Ch[(size_t)(r0 + 8) * N + col]) = pk(h23);
                if (isq) {
                    __half2 l01 = __floats2half2_rn(
                        v0 - __low2float(h01), v1 - __high2float(h01));
                    __half2 l23 = __floats2half2_rn(
                        v2 - __low2float(h23), v3 - __high2float(h23));
                    *reinterpret_cast<uint32_t*>(&Cl[(size_t)r0 * N + col])       = pk(l01);
                    *reinterpret_cast<uint32_t*>(&Cl[(size_t)(r0 + 8) * N + col]) = pk(l23);
                }
            }
        }
    }
}

// ---------------------------------------------------------------------------
// Flash attention, cp.async 2-stage K/V pipeline, 2 CTAs/SM.
// S=(Qh+Ql)·K (K frags via ldmatrix), PV=Ph·V (single fp16 P; V via
// ldmatrix.trans).  Q pre-scaled by 0.125*log2e -> exp2-domain softmax.
// ---------------------------------------------------------------------------
#define QS 72
#define VS 72
#define KT 64
#define A_QSZ   (128 * QS)
#define A_KVSTG (KT * QS + KT * VS)

__global__ __launch_bounds__(256, 2)
void attn_mma(const __half* __restrict__ qkvh,
              const __half* __restrict__ qkvl,
              __half* __restrict__ oh,
              __half* __restrict__ ol)
{
    extern __shared__ __half sm[];
    __half* sQh = sm;                       // [128][QS]
    __half* sQl = sQh + A_QSZ;

    const int tid  = threadIdx.x;
    const int wid  = tid >> 5;
    const int lane = tid & 31;
    const int g    = lane >> 2;
    const int tg   = lane & 3;
    const int q0 = blockIdx.x * 128;
    const int h  = blockIdx.y;
    const int b  = blockIdx.z;
    const size_t rowbase = (size_t)b * SEQ;

    const uint32_t smb = smem_u32(sm);
    const uint32_t kv_base_u = smb + (uint32_t)(2 * A_QSZ) * 2;

    const int kRow = (lane & 7) + ((lane >> 4) << 3);
    const int kCol = ((lane >> 3) & 1) * 8;
    const int lr = lane & 7, lq = (lane >> 3) & 1, lh2 = lane >> 4;
    const uint32_t voff0 = (uint32_t)(((lq * 8 + lr) * VS + lh2 * 8) * 2);

    const int l_r = tid >> 3;
    const int l_q = tid & 7;

    auto issue = [&](int kt) {
        uint32_t sb = kv_base_u + (uint32_t)((kt & 1) * A_KVSTG) * 2;
        #pragma unroll
        for (int i = 0; i < 2; i++) {
            int r = l_r + i * 32;
            size_t koff = (rowbase + kt * KT + r) * QKV_N + EMBD + h * DH + l_q * 8;
            size_t voff = koff + EMBD;
            cp16(sb + (uint32_t)(r * QS + l_q * 8) * 2, &qkvh[koff]);
            cp16(sb + (uint32_t)(KT * QS + r * VS + l_q * 8) * 2, &qkvh[voff]);
        }
    };

    issue(0);
    CP_COMMIT();

    // Load Q tile (hi/lo) once
    #pragma unroll
    for (int i = 0; i < 4; i++) {
        int u = tid + i * 256, r = u >> 3, q = u & 7;
        size_t off = (rowbase + q0 + r) * QKV_N + h * DH + q * 8;
        *reinterpret_cast<uint4*>(&sQh[r * QS + q * 8]) =
            *reinterpret_cast<const uint4*>(&qkvh[off]);
        *reinterpret_cast<uint4*>(&sQl[r * QS + q * 8]) =
            *reinterpret_cast<const uint4*>(&qkvl[off]);
    }
    __syncthreads();

    uint32_t qh[4][4], ql[4][4];
    {
        const uint32_t qHb = smb;
        const uint32_t qLb = smb + (uint32_t)A_QSZ * 2;
        int r = wid * 16 + (lane & 15);
        int co = (lane >> 4) * 8;
        #pragma unroll
        for (int ks = 0; ks < 4; ks++) {
            uint32_t ao = (uint32_t)(r * QS + ks * 16 + co) * 2;
            ldsm_x4(qh[ks][0], qh[ks][1], qh[ks][2], qh[ks][3], qHb + ao);
            ldsm_x4(ql[ks][0], ql[ks][1], ql[ks][2], ql[ks][3], qLb + ao);
        }
    }

    float oacc[8][4];
    #pragma unroll
    for (int nt = 0; nt < 8; nt++)
        #pragma unroll
        for (int i = 0; i < 4; i++) oacc[nt][i] = 0.0f;
    float m0 = -1e30f, m1 = -1e30f, l0 = 0.0f, l1 = 0.0f;

    const int nkt = SEQ / KT;
    for (int kt = 0; kt < nkt; kt++) {
        CP_WAIT0();
        __syncthreads();
        if (kt + 1 < nkt) issue(kt + 1);
        CP_COMMIT();

        const uint32_t sK_u = kv_base_u + (uint32_t)((kt & 1) * A_KVSTG) * 2;
        const uint32_t sV_u = sK_u + (uint32_t)(KT * QS) * 2;

        // S = Q K^T (2 MMAs per step; K frags via ldmatrix)
        float sacc[8][4];
        #pragma unroll
        for (int nt = 0; nt < 8; nt++)
            #pragma unroll
            for (int i = 0; i < 4; i++) sacc[nt][i] = 0.0f;
        #pragma unroll
        for (int ks = 0; ks < 4; ks++) {
            uint32_t kf[8][2];
            #pragma unroll
            for (int q = 0; q < 4; q++) {
                uint32_t ko = (uint32_t)(((kRow + q * 16) * QS) + ks * 16 + kCol) * 2;
                ldsm_x4(kf[2*q][0], kf[2*q][1], kf[2*q+1][0], kf[2*q+1][1], sK_u + ko);
            }
            #pragma unroll
            for (int nt = 0; nt < 8; nt++) {
                mma_f16(sacc[nt], qh[ks], kf[nt]);
                mma_f16(sacc[nt], ql[ks], kf[nt]);
            }
        }

        // Online softmax (log2 domain)
        float mx0 = -1e30f, mx1 = -1e30f;
        #pragma unroll
        for (int nt = 0; nt < 8; nt++) {
            mx0 = fmaxf(mx0, fmaxf(sacc[nt][0], sacc[nt][1]));
            mx1 = fmaxf(mx1, fmaxf(sacc[nt][2], sacc[nt][3]));
        }
        mx0 = fmaxf(mx0, __shfl_xor_sync(0xffffffffu, mx0, 1));
        mx0 = fmaxf(mx0, __shfl_xor_sync(0xffffffffu, mx0, 2));
        mx1 = fmaxf(mx1, __shfl_xor_sync(0xffffffffu, mx1, 1));
        mx1 = fmaxf(mx1, __shfl_xor_sync(0xffffffffu, mx1, 2));
        float nm0 = fmaxf(m0, mx0), nm1 = fmaxf(m1, mx1);
        float a0 = exp2_poly(m0 - nm0), a1 = exp2_poly(m1 - nm1);

        float rs0 = 0.0f, rs1 = 0.0f;
        uint32_t pah[8], pbh[8];
        #pragma unroll
        for (int nt = 0; nt < 8; nt++) {
            float p0 = exp2_poly(sacc[nt][0] - nm0);
            float p1 = exp2_poly(sacc[nt][1] - nm0);
            float p2 = exp2_poly(sacc[nt][2] - nm1);
            float p3 = exp2_poly(sacc[nt][3] - nm1);
            rs0 += p0 + p1; rs1 += p2 + p3;
            pah[nt] = pk(__floats2half2_rn(p0, p1));
            pbh[nt] = pk(__floats2half2_rn(p2, p3));
        }
        rs0 += __shfl_xor_sync(0xffffffffu, rs0, 1);
        rs0 += __shfl_xor_sync(0xffffffffu, rs0, 2);
        rs1 += __shfl_xor_sync(0xffffffffu, rs1, 1);
        rs1 += __shfl_xor_sync(0xffffffffu, rs1, 2);
        l0 = l0 * a0 + rs0;
        l1 = l1 * a1 + rs1;
        m0 = nm0; m1 = nm1;
        #pragma unroll
        for (int nt = 0; nt < 8; nt++) {
            oacc[nt][0] *= a0; oacc[nt][1] *= a0;
            oacc[nt][2] *= a1; oacc[nt][3] *= a1;
        }

        // O += P V  (1 MMA per vb; V fragments via ldmatrix.trans)
        #pragma unroll
        for (int ks = 0; ks < 4; ks++) {
            uint32_t pAh[4] = {pah[2*ks], pbh[2*ks], pah[2*ks+1], pbh[2*ks+1]};
            #pragma unroll
            for (int ntp = 0; ntp < 4; ntp++) {
                uint32_t v0, v1, v2, v3;
                uint32_t addr = sV_u + voff0
                              + (uint32_t)((ks * 16 * VS + ntp * 16) * 2);
                ldsm_x4_t(v0, v1, v2, v3, addr);
                uint32_t vb0[2] = {v0, v1};
                uint32_t vb1[2] = {v2, v3};
                mma_f16(oacc[2*ntp],     pAh, vb0);
                mma_f16(oacc[2*ntp + 1], pAh, vb1);
            }
        }
    }

    // Epilogue: normalize, split fp16 hi/lo, store
    float inv0 = 1.0f / l0, inv1 = 1.0f / l1;
    int qrow = q0 + wid * 16 + g;
    #pragma unroll
    for (int nt = 0; nt < 8; nt++) {
        int col = h * DH + nt * 8 + tg * 2;
        float v0 = oacc[nt][0] * inv0, v1 = oacc[nt][1] * inv0;
        float v2 = oacc[nt][2] * inv1, v3 = oacc[nt][3] * inv1;
        __half2 h01 = __floats2half2_rn(v0, v1);
        __half2 h23 = __floats2half2_rn(v2, v3);
        __half2 l01 = __floats2half2_rn(v0 - __low2float(h01), v1 - __high2float(h01));
        __half2 l23 = __floats2half2_rn(v2 - __low2float(h23), v3 - __high2float(h23));
        *reinterpret_cast<uint32_t*>(&oh[(rowbase + qrow) * EMBD + col])     = pk(h01);
        *reinterpret_cast<uint32_t*>(&ol[(rowbase + qrow) * EMBD + col])     = pk(l01);
        *reinterpret_cast<uint32_t*>(&oh[(rowbase + qrow + 8) * EMBD + col]) = pk(h23);
        *reinterpret_cast<uint32_t*>(&ol[(rowbase + qrow + 8) * EMBD + col]) = pk(l23);
    }
}

// ---------------------------------------------------------------------------
// Launch
// ---------------------------------------------------------------------------
extern "C" void kernel_launch(void* const* d_in, const int* in_sizes, int n_in,
                              void* d_out, int out_size)
{
    const float* x     = (const float*)d_in[0];
    const float* W_in  = (const float*)d_in[1];
    const float* b_in  = (const float*)d_in[2];
    const float* W_out = (const float*)d_in[3];
    const float* b_out = (const float*)d_in[4];
    float* out = (float*)d_out;

    __half *xh, *xl, *wih, *woh, *qh, *ql, *ah, *al;
    cudaGetSymbolAddress((void**)&xh,  g_xh);  cudaGetSymbolAddress((void**)&xl,  g_xl);
    cudaGetSymbolAddress((void**)&wih, g_wih);
    cudaGetSymbolAddress((void**)&woh, g_woh);
    cudaGetSymbolAddress((void**)&qh,  g_qh);  cudaGetSymbolAddress((void**)&ql,  g_ql);
    cudaGetSymbolAddress((void**)&ah,  g_ah);  cudaGetSymbolAddress((void**)&al,  g_al);

    const int gemm_smem = G_NSTG * G_STG * (int)sizeof(__half);
    const int attn_smem = (2 * A_QSZ + 2 * A_KVSTG) * (int)sizeof(__half);
    cudaFuncSetAttribute(gemm_mma, cudaFuncAttributeMaxDynamicSharedMemorySize, gemm_smem);
    cudaFuncSetAttribute(attn_mma, cudaFuncAttributeMaxDynamicSharedMemorySize, attn_smem);

    {
        int n1 = M_TOT * EMBD;
        split_hl<<<n1 / 1024, 256>>>(x, xh, xl, n1);
        int n2 = QKV_N * EMBD;
        cvt_h<<<n2 / 1024, 256>>>(W_in, wih, n2);
        int n3 = EMBD * EMBD;
        cvt_h<<<n3 / 1024, 256>>>(W_out, woh, n3);
    }
    {
        dim3 grid(QKV_N / 128, M_TOT / 128);
        gemm_mma<<<grid, 256, gemm_smem>>>(xh, xl, wih, b_in,
                                           nullptr, qh, ql,
                                           QKV_N, EMBD, EMBD);
    }
    {
        dim3 grid(SEQ / 128, NH, BATCH);
        attn_mma<<<grid, 256, attn_smem>>>(qh, ql, ah, al);
    }
    {
        dim3 grid(EMBD / 128, M_TOT / 128);
        gemm_mma<<<grid, 256, gemm_smem>>>(ah, al, woh, b_out,
                                           out, nullptr, nullptr,
                                           EMBD, EMBD, 0);
    }
}

// round 10
// speedup vs baseline: 5.4228x; 1.3030x over previous
#include <cuda_runtime.h>
#include <cuda_fp16.h>
#include <cstdint>
#include <math.h>

#define EMBD   1024
#define NH     16
#define DH     64
#define BATCH  2
#define SEQ    2048
#define M_TOT  (BATCH * SEQ)   // 4096
#define QKV_N  (3 * EMBD)      // 3072

// ---------------------------------------------------------------------------
// Scratch (fp16; allocation-free rule: __device__ globals)
// ---------------------------------------------------------------------------
__device__ __half g_xh [M_TOT * EMBD];
__device__ __half g_wih[QKV_N * EMBD];
__device__ __half g_woh[EMBD * EMBD];
__device__ __half g_qh [M_TOT * QKV_N], g_ql [M_TOT * QKV_N]; // lo only Q cols
__device__ __half g_ah [M_TOT * EMBD];

// ---------------------------------------------------------------------------
// Helpers
// ---------------------------------------------------------------------------
__device__ __forceinline__ void mma_f16(float* c, const uint32_t* a,
                                        const uint32_t* b) {
    asm volatile(
        "mma.sync.aligned.m16n8k16.row.col.f32.f16.f16.f32 "
        "{%0,%1,%2,%3}, {%4,%5,%6,%7}, {%8,%9}, {%0,%1,%2,%3};"
        : "+f"(c[0]), "+f"(c[1]), "+f"(c[2]), "+f"(c[3])
        : "r"(a[0]), "r"(a[1]), "r"(a[2]), "r"(a[3]), "r"(b[0]), "r"(b[1]));
}

__device__ __forceinline__ void ldsm_x4(uint32_t& r0, uint32_t& r1,
                                        uint32_t& r2, uint32_t& r3,
                                        uint32_t a) {
    asm volatile("ldmatrix.sync.aligned.m8n8.x4.shared.b16 "
                 "{%0,%1,%2,%3}, [%4];"
                 : "=r"(r0), "=r"(r1), "=r"(r2), "=r"(r3) : "r"(a));
}

__device__ __forceinline__ void ldsm_x4_t(uint32_t& r0, uint32_t& r1,
                                          uint32_t& r2, uint32_t& r3,
                                          uint32_t a) {
    asm volatile("ldmatrix.sync.aligned.m8n8.x4.trans.shared.b16 "
                 "{%0,%1,%2,%3}, [%4];"
                 : "=r"(r0), "=r"(r1), "=r"(r2), "=r"(r3) : "r"(a));
}

__device__ __forceinline__ uint32_t smem_u32(const void* p) {
    uint32_t a;
    asm("{ .reg .u64 t; cvta.to.shared.u64 t, %1; cvt.u32.u64 %0, t; }"
        : "=r"(a) : "l"(p));
    return a;
}

__device__ __forceinline__ void cp16(uint32_t dst, const void* src) {
    asm volatile("cp.async.cg.shared.global [%0], [%1], 16;"
                 :: "r"(dst), "l"(src));
}
#define CP_COMMIT() asm volatile("cp.async.commit_group;")
#define CP_WAIT0()  asm volatile("cp.async.wait_group 0;")
#define CP_WAIT2()  asm volatile("cp.async.wait_group 2;")

// FFMA-only 2^x (avoids MUFU throttle). Valid for x <= 0 (clamped at -80).
__device__ __forceinline__ float exp2_poly(float x) {
    x = fmaxf(x, -80.0f);
    float t = x + 12582912.0f;
    float n = t - 12582912.0f;
    float f = x - n;
    float p = 1.33335581e-3f;
    p = fmaf(p, f, 9.61812911e-3f);
    p = fmaf(p, f, 5.55041087e-2f);
    p = fmaf(p, f, 2.40226507e-1f);
    p = fmaf(p, f, 6.93147181e-1f);
    p = fmaf(p, f, 1.0f);
    int e = (int)n;
    return p * __int_as_float((e + 127) << 23);
}

__device__ __forceinline__ uint32_t pk(__half2 v) {
    return *reinterpret_cast<uint32_t*>(&v);
}

// ---------------------------------------------------------------------------
// fp32 -> fp16 single
// ---------------------------------------------------------------------------
__global__ void cvt_h(const float* __restrict__ s, __half* __restrict__ h, int n)
{
    int i = (blockIdx.x * blockDim.x + threadIdx.x) * 4;
    if (i >= n) return;
    float4 v = *reinterpret_cast<const float4*>(&s[i]);
    *reinterpret_cast<__half2*>(&h[i])     = __floats2half2_rn(v.x, v.y);
    *reinterpret_cast<__half2*>(&h[i + 2]) = __floats2half2_rn(v.z, v.w);
}

// ---------------------------------------------------------------------------
// GEMM: C[m,n] = A[m,:]·B[n,:] + bias[n]   (single fp16 MMA)
// 128x128 tile, BK=32, cp.async 4-stage pipeline, ldmatrix fragment loads.
// Out: fp32 (Cf) or fp16 (Ch always; Cl = residual, only cols < scale_lim
// which also get SCALE applied — the Q columns).
// ---------------------------------------------------------------------------
#define AS 40
#define G_TILE (128 * AS)
#define G_STG  (2 * G_TILE)
#define G_NSTG 4

__global__ __launch_bounds__(256, 2)
void gemm_mma(const __half* __restrict__ A_g,
              const __half* __restrict__ B_g,
              const float* __restrict__ bias,
              float* __restrict__ Cf,
              __half* __restrict__ Ch,
              __half* __restrict__ Cl,
              int N, int K, int scale_lim)
{
    extern __shared__ __half sm[];
    const uint32_t smb = smem_u32(sm);

    const int tid  = threadIdx.x;
    const int wid  = tid >> 5;
    const int lane = tid & 31;
    const int g    = lane >> 2;
    const int tg   = lane & 3;
    const int warp_m = (wid & 3) * 32;
    const int warp_n = (wid >> 2) * 64;
    const int bm = blockIdx.y * 128;
    const int bn = blockIdx.x * 128;

    const int l_row = tid >> 2;
    const int l_q   = tid & 3;

    const int aRow = warp_m + (lane & 15);
    const int aCol = (lane >> 4) * 8;
    const int bRow = warp_n + (lane & 7) + ((lane >> 4) << 3);
    const int bCol = ((lane >> 3) & 1) * 8;

    float acc[2][8][4];
    #pragma unroll
    for (int mt = 0; mt < 2; mt++)
        #pragma unroll
        for (int nt = 0; nt < 8; nt++)
            #pragma unroll
            for (int i = 0; i < 4; i++) acc[mt][nt][i] = 0.0f;

    const int nch = K / 32;

    auto issue = [&](int ch) {
        int k0 = ch * 32;
        uint32_t sb = smb + (uint32_t)((ch % G_NSTG) * G_STG) * 2;
        #pragma unroll
        for (int i = 0; i < 2; i++) {
            int row = l_row + i * 64;
            uint32_t so = (uint32_t)(row * AS + l_q * 8) * 2;
            size_t oA = (size_t)(bm + row) * K + k0 + l_q * 8;
            size_t oB = (size_t)(bn + row) * K + k0 + l_q * 8;
            cp16(sb + so,              &A_g[oA]);
            cp16(sb + G_TILE * 2 + so, &B_g[oB]);
        }
    };

    issue(0); CP_COMMIT();
    issue(1); CP_COMMIT();
    issue(2); CP_COMMIT();

    for (int ch = 0; ch < nch; ch++) {
        CP_WAIT2();
        __syncthreads();
        if (ch + 3 < nch) issue(ch + 3);
        CP_COMMIT();

        uint32_t stg = smb + (uint32_t)((ch % G_NSTG) * G_STG) * 2;
        uint32_t aB = stg;
        uint32_t bB = stg + (uint32_t)G_TILE * 2;

        #pragma unroll
        for (int ks = 0; ks < 2; ks++) {
            uint32_t ah[2][4], bf[8][2];
            #pragma unroll
            for (int mt = 0; mt < 2; mt++) {
                uint32_t ao = (uint32_t)(((aRow + mt * 16) * AS) + ks * 16 + aCol) * 2;
                ldsm_x4(ah[mt][0], ah[mt][1], ah[mt][2], ah[mt][3], aB + ao);
            }
            #pragma unroll
            for (int q = 0; q < 4; q++) {
                uint32_t bo = (uint32_t)(((bRow + q * 16) * AS) + ks * 16 + bCol) * 2;
                ldsm_x4(bf[2*q][0], bf[2*q][1], bf[2*q+1][0], bf[2*q+1][1], bB + bo);
            }
            #pragma unroll
            for (int nt = 0; nt < 8; nt++) {
                #pragma unroll
                for (int mt = 0; mt < 2; mt++)
                    mma_f16(acc[mt][nt], ah[mt], bf[nt]);
            }
        }
    }

    const float SCALE = 0.18033688f;   // 0.125 * log2(e)
    #pragma unroll
    for (int mt = 0; mt < 2; mt++) {
        int r0 = bm + warp_m + mt * 16 + g;
        #pragma unroll
        for (int nt = 0; nt < 8; nt++) {
            int col = bn + warp_n + nt * 8 + tg * 2;
            float b0 = __ldg(&bias[col]), b1 = __ldg(&bias[col + 1]);
            float v0 = acc[mt][nt][0] + b0, v1 = acc[mt][nt][1] + b1;
            float v2 = acc[mt][nt][2] + b0, v3 = acc[mt][nt][3] + b1;
            if (Cf) {
                *reinterpret_cast<float2*>(&Cf[(size_t)r0 * N + col])
                    = make_float2(v0, v1);
                *reinterpret_cast<float2*>(&Cf[(size_t)(r0 + 8) * N + col])
                    = make_float2(v2, v3);
            } else {
                bool isq = col < scale_lim;
                if (isq) { v0 *= SCALE; v1 *= SCALE; v2 *= SCALE; v3 *= SCALE; }
                __half2 h01 = __floats2half2_rn(v0, v1);
                __half2 h23 = __floats2half2_rn(v2, v3);
                *reinterpret_cast<uint32_t*>(&Ch[(size_t)r0 * N + col])       = pk(h01);
                *reinterpret_cast<uint32_t*>(&Ch[(size_t)(r0 + 8) * N + col]) = pk(h23);
                if (isq) {
                    __half2 l01 = __floats2half2_rn(
                        v0 - __low2float(h01), v1 - __high2float(h01));
                    __half2 l23 = __floats2half2_rn(
                        v2 - __low2float(h23), v3 - __high2float(h23));
                    *reinterpret_cast<uint32_t*>(&Cl[(size_t)r0 * N + col])       = pk(l01);
                    *reinterpret_cast<uint32_t*>(&Cl[(size_t)(r0 + 8) * N + col]) = pk(l23);
                }
            }
        }
    }
}

// ---------------------------------------------------------------------------
// Flash attention, cp.async 2-stage K/V pipeline, 2 CTAs/SM.
// S=(Qh+Ql)·K (K frags via ldmatrix), PV=Ph·V (single fp16 P; V via
// ldmatrix.trans).  Q pre-scaled by 0.125*log2e -> exp2-domain softmax.
// Output: single fp16.
// ---------------------------------------------------------------------------
#define QS 72
#define VS 72
#define KT 64
#define A_QSZ   (128 * QS)
#define A_KVSTG (KT * QS + KT * VS)

__global__ __launch_bounds__(256, 2)
void attn_mma(const __half* __restrict__ qkvh,
              const __half* __restrict__ qkvl,
              __half* __restrict__ oh)
{
    extern __shared__ __half sm[];
    __half* sQh = sm;                       // [128][QS]
    __half* sQl = sQh + A_QSZ;

    const int tid  = threadIdx.x;
    const int wid  = tid >> 5;
    const int lane = tid & 31;
    const int g    = lane >> 2;
    const int tg   = lane & 3;
    const int q0 = blockIdx.x * 128;
    const int h  = blockIdx.y;
    const int b  = blockIdx.z;
    const size_t rowbase = (size_t)b * SEQ;

    const uint32_t smb = smem_u32(sm);
    const uint32_t kv_base_u = smb + (uint32_t)(2 * A_QSZ) * 2;

    const int kRow = (lane & 7) + ((lane >> 4) << 3);
    const int kCol = ((lane >> 3) & 1) * 8;
    const int lr = lane & 7, lq = (lane >> 3) & 1, lh2 = lane >> 4;
    const uint32_t voff0 = (uint32_t)(((lq * 8 + lr) * VS + lh2 * 8) * 2);

    const int l_r = tid >> 3;
    const int l_q = tid & 7;

    auto issue = [&](int kt) {
        uint32_t sb = kv_base_u + (uint32_t)((kt & 1) * A_KVSTG) * 2;
        #pragma unroll
        for (int i = 0; i < 2; i++) {
            int r = l_r + i * 32;
            size_t koff = (rowbase + kt * KT + r) * QKV_N + EMBD + h * DH + l_q * 8;
            size_t voff = koff + EMBD;
            cp16(sb + (uint32_t)(r * QS + l_q * 8) * 2, &qkvh[koff]);
            cp16(sb + (uint32_t)(KT * QS + r * VS + l_q * 8) * 2, &qkvh[voff]);
        }
    };

    issue(0);
    CP_COMMIT();

    // Load Q tile (hi/lo) once
    #pragma unroll
    for (int i = 0; i < 4; i++) {
        int u = tid + i * 256, r = u >> 3, q = u & 7;
        size_t off = (rowbase + q0 + r) * QKV_N + h * DH + q * 8;
        *reinterpret_cast<uint4*>(&sQh[r * QS + q * 8]) =
            *reinterpret_cast<const uint4*>(&qkvh[off]);
        *reinterpret_cast<uint4*>(&sQl[r * QS + q * 8]) =
            *reinterpret_cast<const uint4*>(&qkvl[off]);
    }
    __syncthreads();

    uint32_t qh[4][4], ql[4][4];
    {
        const uint32_t qHb = smb;
        const uint32_t qLb = smb + (uint32_t)A_QSZ * 2;
        int r = wid * 16 + (lane & 15);
        int co = (lane >> 4) * 8;
        #pragma unroll
        for (int ks = 0; ks < 4; ks++) {
            uint32_t ao = (uint32_t)(r * QS + ks * 16 + co) * 2;
            ldsm_x4(qh[ks][0], qh[ks][1], qh[ks][2], qh[ks][3], qHb + ao);
            ldsm_x4(ql[ks][0], ql[ks][1], ql[ks][2], ql[ks][3], qLb + ao);
        }
    }

    float oacc[8][4];
    #pragma unroll
    for (int nt = 0; nt < 8; nt++)
        #pragma unroll
        for (int i = 0; i < 4; i++) oacc[nt][i] = 0.0f;
    float m0 = -1e30f, m1 = -1e30f, l0 = 0.0f, l1 = 0.0f;

    const int nkt = SEQ / KT;
    for (int kt = 0; kt < nkt; kt++) {
        CP_WAIT0();
        __syncthreads();
        if (kt + 1 < nkt) issue(kt + 1);
        CP_COMMIT();

        const uint32_t sK_u = kv_base_u + (uint32_t)((kt & 1) * A_KVSTG) * 2;
        const uint32_t sV_u = sK_u + (uint32_t)(KT * QS) * 2;

        // S = Q K^T (2 MMAs per step; K frags via ldmatrix)
        float sacc[8][4];
        #pragma unroll
        for (int nt = 0; nt < 8; nt++)
            #pragma unroll
            for (int i = 0; i < 4; i++) sacc[nt][i] = 0.0f;
        #pragma unroll
        for (int ks = 0; ks < 4; ks++) {
            uint32_t kf[8][2];
            #pragma unroll
            for (int q = 0; q < 4; q++) {
                uint32_t ko = (uint32_t)(((kRow + q * 16) * QS) + ks * 16 + kCol) * 2;
                ldsm_x4(kf[2*q][0], kf[2*q][1], kf[2*q+1][0], kf[2*q+1][1], sK_u + ko);
            }
            #pragma unroll
            for (int nt = 0; nt < 8; nt++) {
                mma_f16(sacc[nt], qh[ks], kf[nt]);
                mma_f16(sacc[nt], ql[ks], kf[nt]);
            }
        }

        // Online softmax (log2 domain)
        float mx0 = -1e30f, mx1 = -1e30f;
        #pragma unroll
        for (int nt = 0; nt < 8; nt++) {
            mx0 = fmaxf(mx0, fmaxf(sacc[nt][0], sacc[nt][1]));
            mx1 = fmaxf(mx1, fmaxf(sacc[nt][2], sacc[nt][3]));
        }
        mx0 = fmaxf(mx0, __shfl_xor_sync(0xffffffffu, mx0, 1));
        mx0 = fmaxf(mx0, __shfl_xor_sync(0xffffffffu, mx0, 2));
        mx1 = fmaxf(mx1, __shfl_xor_sync(0xffffffffu, mx1, 1));
        mx1 = fmaxf(mx1, __shfl_xor_sync(0xffffffffu, mx1, 2));
        float nm0 = fmaxf(m0, mx0), nm1 = fmaxf(m1, mx1);
        float a0 = exp2_poly(m0 - nm0), a1 = exp2_poly(m1 - nm1);

        float rs0 = 0.0f, rs1 = 0.0f;
        uint32_t pah[8], pbh[8];
        #pragma unroll
        for (int nt = 0; nt < 8; nt++) {
            float p0 = exp2_poly(sacc[nt][0] - nm0);
            float p1 = exp2_poly(sacc[nt][1] - nm0);
            float p2 = exp2_poly(sacc[nt][2] - nm1);
            float p3 = exp2_poly(sacc[nt][3] - nm1);
            rs0 += p0 + p1; rs1 += p2 + p3;
            pah[nt] = pk(__floats2half2_rn(p0, p1));
            pbh[nt] = pk(__floats2half2_rn(p2, p3));
        }
        rs0 += __shfl_xor_sync(0xffffffffu, rs0, 1);
        rs0 += __shfl_xor_sync(0xffffffffu, rs0, 2);
        rs1 += __shfl_xor_sync(0xffffffffu, rs1, 1);
        rs1 += __shfl_xor_sync(0xffffffffu, rs1, 2);
        l0 = l0 * a0 + rs0;
        l1 = l1 * a1 + rs1;
        m0 = nm0; m1 = nm1;
        #pragma unroll
        for (int nt = 0; nt < 8; nt++) {
            oacc[nt][0] *= a0; oacc[nt][1] *= a0;
            oacc[nt][2] *= a1; oacc[nt][3] *= a1;
        }

        // O += P V  (1 MMA per vb; V fragments via ldmatrix.trans)
        #pragma unroll
        for (int ks = 0; ks < 4; ks++) {
            uint32_t pAh[4] = {pah[2*ks], pbh[2*ks], pah[2*ks+1], pbh[2*ks+1]};
            #pragma unroll
            for (int ntp = 0; ntp < 4; ntp++) {
                uint32_t v0, v1, v2, v3;
                uint32_t addr = sV_u + voff0
                              + (uint32_t)((ks * 16 * VS + ntp * 16) * 2);
                ldsm_x4_t(v0, v1, v2, v3, addr);
                uint32_t vb0[2] = {v0, v1};
                uint32_t vb1[2] = {v2, v3};
                mma_f16(oacc[2*ntp],     pAh, vb0);
                mma_f16(oacc[2*ntp + 1], pAh, vb1);
            }
        }
    }

    // Epilogue: normalize, store fp16
    float inv0 = 1.0f / l0, inv1 = 1.0f / l1;
    int qrow = q0 + wid * 16 + g;
    #pragma unroll
    for (int nt = 0; nt < 8; nt++) {
        int col = h * DH + nt * 8 + tg * 2;
        float v0 = oacc[nt][0] * inv0, v1 = oacc[nt][1] * inv0;
        float v2 = oacc[nt][2] * inv1, v3 = oacc[nt][3] * inv1;
        *reinterpret_cast<uint32_t*>(&oh[(rowbase + qrow) * EMBD + col])
            = pk(__floats2half2_rn(v0, v1));
        *reinterpret_cast<uint32_t*>(&oh[(rowbase + qrow + 8) * EMBD + col])
            = pk(__floats2half2_rn(v2, v3));
    }
}

// ---------------------------------------------------------------------------
// Launch
// ---------------------------------------------------------------------------
extern "C" void kernel_launch(void* const* d_in, const int* in_sizes, int n_in,
                              void* d_out, int out_size)
{
    const float* x     = (const float*)d_in[0];
    const float* W_in  = (const float*)d_in[1];
    const float* b_in  = (const float*)d_in[2];
    const float* W_out = (const float*)d_in[3];
    const float* b_out = (const float*)d_in[4];
    float* out = (float*)d_out;

    __half *xh, *wih, *woh, *qh, *ql, *ah;
    cudaGetSymbolAddress((void**)&xh,  g_xh);
    cudaGetSymbolAddress((void**)&wih, g_wih);
    cudaGetSymbolAddress((void**)&woh, g_woh);
    cudaGetSymbolAddress((void**)&qh,  g_qh);
    cudaGetSymbolAddress((void**)&ql,  g_ql);
    cudaGetSymbolAddress((void**)&ah,  g_ah);

    const int gemm_smem = G_NSTG * G_STG * (int)sizeof(__half);
    const int attn_smem = (2 * A_QSZ + 2 * A_KVSTG) * (int)sizeof(__half);
    cudaFuncSetAttribute(gemm_mma, cudaFuncAttributeMaxDynamicSharedMemorySize, gemm_smem);
    cudaFuncSetAttribute(attn_mma, cudaFuncAttributeMaxDynamicSharedMemorySize, attn_smem);

    {
        int n1 = M_TOT * EMBD;
        cvt_h<<<n1 / 1024, 256>>>(x, xh, n1);
        int n2 = QKV_N * EMBD;
        cvt_h<<<n2 / 1024, 256>>>(W_in, wih, n2);
        int n3 = EMBD * EMBD;
        cvt_h<<<n3 / 1024, 256>>>(W_out, woh, n3);
    }
    // 1) qkv = x @ W_in^T + b_in  -> fp16 (hi everywhere, lo + scale on Q cols)
    {
        dim3 grid(QKV_N / 128, M_TOT / 128);
        gemm_mma<<<grid, 256, gemm_smem>>>(xh, wih, b_in,
                                           nullptr, qh, ql,
                                           QKV_N, EMBD, EMBD);
    }
    // 2) attention -> fp16
    {
        dim3 grid(SEQ / 128, NH, BATCH);
        attn_mma<<<grid, 256, attn_smem>>>(qh, ql, ah);
    }
    // 3) out = attn @ W_out^T + b_out  -> fp32
    {
        dim3 grid(EMBD / 128, M_TOT / 128);
        gemm_mma<<<grid, 256, gemm_smem>>>(ah, woh, b_out,
                                           out, nullptr, nullptr,
                                           EMBD, EMBD, 0);
    }
}

// round 11
// speedup vs baseline: 5.9471x; 1.0967x over previous
#include <cuda_runtime.h>
#include <cuda_fp16.h>
#include <cstdint>
#include <math.h>

#define EMBD   1024
#define NH     16
#define DH     64
#define BATCH  2
#define SEQ    2048
#define M_TOT  (BATCH * SEQ)   // 4096
#define QKV_N  (3 * EMBD)      // 3072

// ---------------------------------------------------------------------------
// Scratch (fp16; allocation-free rule: __device__ globals)
// ---------------------------------------------------------------------------
__device__ __half g_xh [M_TOT * EMBD];
__device__ __half g_wih[QKV_N * EMBD];
__device__ __half g_woh[EMBD * EMBD];
__device__ __half g_qh [M_TOT * QKV_N];
__device__ __half g_ah [M_TOT * EMBD];

// ---------------------------------------------------------------------------
// Helpers
// ---------------------------------------------------------------------------
__device__ __forceinline__ void mma_f16(float* c, const uint32_t* a,
                                        const uint32_t* b) {
    asm volatile(
        "mma.sync.aligned.m16n8k16.row.col.f32.f16.f16.f32 "
        "{%0,%1,%2,%3}, {%4,%5,%6,%7}, {%8,%9}, {%0,%1,%2,%3};"
        : "+f"(c[0]), "+f"(c[1]), "+f"(c[2]), "+f"(c[3])
        : "r"(a[0]), "r"(a[1]), "r"(a[2]), "r"(a[3]), "r"(b[0]), "r"(b[1]));
}

__device__ __forceinline__ void ldsm_x4(uint32_t& r0, uint32_t& r1,
                                        uint32_t& r2, uint32_t& r3,
                                        uint32_t a) {
    asm volatile("ldmatrix.sync.aligned.m8n8.x4.shared.b16 "
                 "{%0,%1,%2,%3}, [%4];"
                 : "=r"(r0), "=r"(r1), "=r"(r2), "=r"(r3) : "r"(a));
}

__device__ __forceinline__ void ldsm_x4_t(uint32_t& r0, uint32_t& r1,
                                          uint32_t& r2, uint32_t& r3,
                                          uint32_t a) {
    asm volatile("ldmatrix.sync.aligned.m8n8.x4.trans.shared.b16 "
                 "{%0,%1,%2,%3}, [%4];"
                 : "=r"(r0), "=r"(r1), "=r"(r2), "=r"(r3) : "r"(a));
}

__device__ __forceinline__ uint32_t smem_u32(const void* p) {
    uint32_t a;
    asm("{ .reg .u64 t; cvta.to.shared.u64 t, %1; cvt.u32.u64 %0, t; }"
        : "=r"(a) : "l"(p));
    return a;
}

__device__ __forceinline__ void cp16(uint32_t dst, const void* src) {
    asm volatile("cp.async.cg.shared.global [%0], [%1], 16;"
                 :: "r"(dst), "l"(src));
}
#define CP_COMMIT() asm volatile("cp.async.commit_group;")
#define CP_WAIT0()  asm volatile("cp.async.wait_group 0;")
#define CP_WAIT2()  asm volatile("cp.async.wait_group 2;")

// FFMA-only 2^x (avoids MUFU throttle). Valid for x <= 0 (clamped at -80).
__device__ __forceinline__ float exp2_poly(float x) {
    x = fmaxf(x, -80.0f);
    float t = x + 12582912.0f;
    float n = t - 12582912.0f;
    float f = x - n;
    float p = 1.33335581e-3f;
    p = fmaf(p, f, 9.61812911e-3f);
    p = fmaf(p, f, 5.55041087e-2f);
    p = fmaf(p, f, 2.40226507e-1f);
    p = fmaf(p, f, 6.93147181e-1f);
    p = fmaf(p, f, 1.0f);
    int e = (int)n;
    return p * __int_as_float((e + 127) << 23);
}

__device__ __forceinline__ uint32_t pk(__half2 v) {
    return *reinterpret_cast<uint32_t*>(&v);
}

// ---------------------------------------------------------------------------
// fp32 -> fp16 single
// ---------------------------------------------------------------------------
__global__ void cvt_h(const float* __restrict__ s, __half* __restrict__ h, int n)
{
    int i = (blockIdx.x * blockDim.x + threadIdx.x) * 4;
    if (i >= n) return;
    float4 v = *reinterpret_cast<const float4*>(&s[i]);
    *reinterpret_cast<__half2*>(&h[i])     = __floats2half2_rn(v.x, v.y);
    *reinterpret_cast<__half2*>(&h[i + 2]) = __floats2half2_rn(v.z, v.w);
}

// ---------------------------------------------------------------------------
// GEMM: C[m,n] = A[m,:]·B[n,:] + bias[n]   (single fp16 MMA)
// 128x128 tile, BK=32, cp.async 4-stage pipeline, ldmatrix fragment loads.
// Out: fp32 (Cf) or fp16 (Ch; cols < scale_lim get SCALE — the Q columns).
// ---------------------------------------------------------------------------
#define AS 40
#define G_TILE (128 * AS)
#define G_STG  (2 * G_TILE)
#define G_NSTG 4

__global__ __launch_bounds__(256, 2)
void gemm_mma(const __half* __restrict__ A_g,
              const __half* __restrict__ B_g,
              const float* __restrict__ bias,
              float* __restrict__ Cf,
              __half* __restrict__ Ch,
              int N, int K, int scale_lim)
{
    extern __shared__ __half sm[];
    const uint32_t smb = smem_u32(sm);

    const int tid  = threadIdx.x;
    const int wid  = tid >> 5;
    const int lane = tid & 31;
    const int g    = lane >> 2;
    const int tg   = lane & 3;
    const int warp_m = (wid & 3) * 32;
    const int warp_n = (wid >> 2) * 64;
    const int bm = blockIdx.y * 128;
    const int bn = blockIdx.x * 128;

    const int l_row = tid >> 2;
    const int l_q   = tid & 3;

    const int aRow = warp_m + (lane & 15);
    const int aCol = (lane >> 4) * 8;
    const int bRow = warp_n + (lane & 7) + ((lane >> 4) << 3);
    const int bCol = ((lane >> 3) & 1) * 8;

    float acc[2][8][4];
    #pragma unroll
    for (int mt = 0; mt < 2; mt++)
        #pragma unroll
        for (int nt = 0; nt < 8; nt++)
            #pragma unroll
            for (int i = 0; i < 4; i++) acc[mt][nt][i] = 0.0f;

    const int nch = K / 32;

    auto issue = [&](int ch) {
        int k0 = ch * 32;
        uint32_t sb = smb + (uint32_t)((ch % G_NSTG) * G_STG) * 2;
        #pragma unroll
        for (int i = 0; i < 2; i++) {
            int row = l_row + i * 64;
            uint32_t so = (uint32_t)(row * AS + l_q * 8) * 2;
            size_t oA = (size_t)(bm + row) * K + k0 + l_q * 8;
            size_t oB = (size_t)(bn + row) * K + k0 + l_q * 8;
            cp16(sb + so,              &A_g[oA]);
            cp16(sb + G_TILE * 2 + so, &B_g[oB]);
        }
    };

    issue(0); CP_COMMIT();
    issue(1); CP_COMMIT();
    issue(2); CP_COMMIT();

    for (int ch = 0; ch < nch; ch++) {
        CP_WAIT2();
        __syncthreads();
        if (ch + 3 < nch) issue(ch + 3);
        CP_COMMIT();

        uint32_t stg = smb + (uint32_t)((ch % G_NSTG) * G_STG) * 2;
        uint32_t aB = stg;
        uint32_t bB = stg + (uint32_t)G_TILE * 2;

        #pragma unroll
        for (int ks = 0; ks < 2; ks++) {
            uint32_t ah[2][4], bf[8][2];
            #pragma unroll
            for (int mt = 0; mt < 2; mt++) {
                uint32_t ao = (uint32_t)(((aRow + mt * 16) * AS) + ks * 16 + aCol) * 2;
                ldsm_x4(ah[mt][0], ah[mt][1], ah[mt][2], ah[mt][3], aB + ao);
            }
            #pragma unroll
            for (int q = 0; q < 4; q++) {
                uint32_t bo = (uint32_t)(((bRow + q * 16) * AS) + ks * 16 + bCol) * 2;
                ldsm_x4(bf[2*q][0], bf[2*q][1], bf[2*q+1][0], bf[2*q+1][1], bB + bo);
            }
            #pragma unroll
            for (int nt = 0; nt < 8; nt++) {
                #pragma unroll
                for (int mt = 0; mt < 2; mt++)
                    mma_f16(acc[mt][nt], ah[mt], bf[nt]);
            }
        }
    }

    const float SCALE = 0.18033688f;   // 0.125 * log2(e)
    #pragma unroll
    for (int mt = 0; mt < 2; mt++) {
        int r0 = bm + warp_m + mt * 16 + g;
        #pragma unroll
        for (int nt = 0; nt < 8; nt++) {
            int col = bn + warp_n + nt * 8 + tg * 2;
            float b0 = __ldg(&bias[col]), b1 = __ldg(&bias[col + 1]);
            float v0 = acc[mt][nt][0] + b0, v1 = acc[mt][nt][1] + b1;
            float v2 = acc[mt][nt][2] + b0, v3 = acc[mt][nt][3] + b1;
            if (Cf) {
                *reinterpret_cast<float2*>(&Cf[(size_t)r0 * N + col])
                    = make_float2(v0, v1);
                *reinterpret_cast<float2*>(&Cf[(size_t)(r0 + 8) * N + col])
                    = make_float2(v2, v3);
            } else {
                if (col < scale_lim) { v0 *= SCALE; v1 *= SCALE; v2 *= SCALE; v3 *= SCALE; }
                *reinterpret_cast<uint32_t*>(&Ch[(size_t)r0 * N + col])
                    = pk(__floats2half2_rn(v0, v1));
                *reinterpret_cast<uint32_t*>(&Ch[(size_t)(r0 + 8) * N + col])
                    = pk(__floats2half2_rn(v2, v3));
            }
        }
    }
}

// ---------------------------------------------------------------------------
// Flash attention, cp.async 2-stage K/V pipeline, 2 CTAs/SM.
// S=Q·K (single fp16, K frags via ldmatrix), PV=P·V (single fp16 P; V via
// ldmatrix.trans).  Q pre-scaled by 0.125*log2e -> exp2-domain softmax.
// ---------------------------------------------------------------------------
#define QS 72
#define VS 72
#define KT 64
#define A_QSZ   (128 * QS)
#define A_KVSTG (KT * QS + KT * VS)

__global__ __launch_bounds__(256, 2)
void attn_mma(const __half* __restrict__ qkvh,
              __half* __restrict__ oh)
{
    extern __shared__ __half sm[];
    __half* sQh = sm;                       // [128][QS]

    const int tid  = threadIdx.x;
    const int wid  = tid >> 5;
    const int lane = tid & 31;
    const int g    = lane >> 2;
    const int tg   = lane & 3;
    const int q0 = blockIdx.x * 128;
    const int h  = blockIdx.y;
    const int b  = blockIdx.z;
    const size_t rowbase = (size_t)b * SEQ;

    const uint32_t smb = smem_u32(sm);
    const uint32_t kv_base_u = smb + (uint32_t)A_QSZ * 2;

    const int kRow = (lane & 7) + ((lane >> 4) << 3);
    const int kCol = ((lane >> 3) & 1) * 8;
    const int lr = lane & 7, lq = (lane >> 3) & 1, lh2 = lane >> 4;
    const uint32_t voff0 = (uint32_t)(((lq * 8 + lr) * VS + lh2 * 8) * 2);

    const int l_r = tid >> 3;
    const int l_q = tid & 7;

    auto issue = [&](int kt) {
        uint32_t sb = kv_base_u + (uint32_t)((kt & 1) * A_KVSTG) * 2;
        #pragma unroll
        for (int i = 0; i < 2; i++) {
            int r = l_r + i * 32;
            size_t koff = (rowbase + kt * KT + r) * QKV_N + EMBD + h * DH + l_q * 8;
            size_t voff = koff + EMBD;
            cp16(sb + (uint32_t)(r * QS + l_q * 8) * 2, &qkvh[koff]);
            cp16(sb + (uint32_t)(KT * QS + r * VS + l_q * 8) * 2, &qkvh[voff]);
        }
    };

    issue(0);
    CP_COMMIT();

    // Load Q tile once
    #pragma unroll
    for (int i = 0; i < 4; i++) {
        int u = tid + i * 256, r = u >> 3, q = u & 7;
        size_t off = (rowbase + q0 + r) * QKV_N + h * DH + q * 8;
        *reinterpret_cast<uint4*>(&sQh[r * QS + q * 8]) =
            *reinterpret_cast<const uint4*>(&qkvh[off]);
    }
    __syncthreads();

    uint32_t qh[4][4];
    {
        int r = wid * 16 + (lane & 15);
        int co = (lane >> 4) * 8;
        #pragma unroll
        for (int ks = 0; ks < 4; ks++) {
            uint32_t ao = (uint32_t)(r * QS + ks * 16 + co) * 2;
            ldsm_x4(qh[ks][0], qh[ks][1], qh[ks][2], qh[ks][3], smb + ao);
        }
    }

    float oacc[8][4];
    #pragma unroll
    for (int nt = 0; nt < 8; nt++)
        #pragma unroll
        for (int i = 0; i < 4; i++) oacc[nt][i] = 0.0f;
    float m0 = -1e30f, m1 = -1e30f, l0 = 0.0f, l1 = 0.0f;

    const int nkt = SEQ / KT;
    for (int kt = 0; kt < nkt; kt++) {
        CP_WAIT0();
        __syncthreads();
        if (kt + 1 < nkt) issue(kt + 1);
        CP_COMMIT();

        const uint32_t sK_u = kv_base_u + (uint32_t)((kt & 1) * A_KVSTG) * 2;
        const uint32_t sV_u = sK_u + (uint32_t)(KT * QS) * 2;

        // S = Q K^T (single fp16 MMA; K frags via ldmatrix)
        float sacc[8][4];
        #pragma unroll
        for (int nt = 0; nt < 8; nt++)
            #pragma unroll
            for (int i = 0; i < 4; i++) sacc[nt][i] = 0.0f;
        #pragma unroll
        for (int ks = 0; ks < 4; ks++) {
            uint32_t kf[8][2];
            #pragma unroll
            for (int q = 0; q < 4; q++) {
                uint32_t ko = (uint32_t)(((kRow + q * 16) * QS) + ks * 16 + kCol) * 2;
                ldsm_x4(kf[2*q][0], kf[2*q][1], kf[2*q+1][0], kf[2*q+1][1], sK_u + ko);
            }
            #pragma unroll
            for (int nt = 0; nt < 8; nt++)
                mma_f16(sacc[nt], qh[ks], kf[nt]);
        }

        // Online softmax (log2 domain)
        float mx0 = -1e30f, mx1 = -1e30f;
        #pragma unroll
        for (int nt = 0; nt < 8; nt++) {
            mx0 = fmaxf(mx0, fmaxf(sacc[nt][0], sacc[nt][1]));
            mx1 = fmaxf(mx1, fmaxf(sacc[nt][2], sacc[nt][3]));
        }
        mx0 = fmaxf(mx0, __shfl_xor_sync(0xffffffffu, mx0, 1));
        mx0 = fmaxf(mx0, __shfl_xor_sync(0xffffffffu, mx0, 2));
        mx1 = fmaxf(mx1, __shfl_xor_sync(0xffffffffu, mx1, 1));
        mx1 = fmaxf(mx1, __shfl_xor_sync(0xffffffffu, mx1, 2));
        float nm0 = fmaxf(m0, mx0), nm1 = fmaxf(m1, mx1);
        float a0 = exp2_poly(m0 - nm0), a1 = exp2_poly(m1 - nm1);

        float rs0 = 0.0f, rs1 = 0.0f;
        uint32_t pah[8], pbh[8];
        #pragma unroll
        for (int nt = 0; nt < 8; nt++) {
            float p0 = exp2_poly(sacc[nt][0] - nm0);
            float p1 = exp2_poly(sacc[nt][1] - nm0);
            float p2 = exp2_poly(sacc[nt][2] - nm1);
            float p3 = exp2_poly(sacc[nt][3] - nm1);
            rs0 += p0 + p1; rs1 += p2 + p3;
            pah[nt] = pk(__floats2half2_rn(p0, p1));
            pbh[nt] = pk(__floats2half2_rn(p2, p3));
        }
        rs0 += __shfl_xor_sync(0xffffffffu, rs0, 1);
        rs0 += __shfl_xor_sync(0xffffffffu, rs0, 2);
        rs1 += __shfl_xor_sync(0xffffffffu, rs1, 1);
        rs1 += __shfl_xor_sync(0xffffffffu, rs1, 2);
        l0 = l0 * a0 + rs0;
        l1 = l1 * a1 + rs1;
        m0 = nm0; m1 = nm1;
        #pragma unroll
        for (int nt = 0; nt < 8; nt++) {
            oacc[nt][0] *= a0; oacc[nt][1] *= a0;
            oacc[nt][2] *= a1; oacc[nt][3] *= a1;
        }

        // O += P V  (V fragments via ldmatrix.trans)
        #pragma unroll
        for (int ks = 0; ks < 4; ks++) {
            uint32_t pAh[4] = {pah[2*ks], pbh[2*ks], pah[2*ks+1], pbh[2*ks+1]};
            #pragma unroll
            for (int ntp = 0; ntp < 4; ntp++) {
                uint32_t v0, v1, v2, v3;
                uint32_t addr = sV_u + voff0
                              + (uint32_t)((ks * 16 * VS + ntp * 16) * 2);
                ldsm_x4_t(v0, v1, v2, v3, addr);
                uint32_t vb0[2] = {v0, v1};
                uint32_t vb1[2] = {v2, v3};
                mma_f16(oacc[2*ntp],     pAh, vb0);
                mma_f16(oacc[2*ntp + 1], pAh, vb1);
            }
        }
    }

    // Epilogue: normalize, store fp16
    float inv0 = 1.0f / l0, inv1 = 1.0f / l1;
    int qrow = q0 + wid * 16 + g;
    #pragma unroll
    for (int nt = 0; nt < 8; nt++) {
        int col = h * DH + nt * 8 + tg * 2;
        float v0 = oacc[nt][0] * inv0, v1 = oacc[nt][1] * inv0;
        float v2 = oacc[nt][2] * inv1, v3 = oacc[nt][3] * inv1;
        *reinterpret_cast<uint32_t*>(&oh[(rowbase + qrow) * EMBD + col])
            = pk(__floats2half2_rn(v0, v1));
        *reinterpret_cast<uint32_t*>(&oh[(rowbase + qrow + 8) * EMBD + col])
            = pk(__floats2half2_rn(v2, v3));
    }
}

// ---------------------------------------------------------------------------
// Launch
// ---------------------------------------------------------------------------
extern "C" void kernel_launch(void* const* d_in, const int* in_sizes, int n_in,
                              void* d_out, int out_size)
{
    const float* x     = (const float*)d_in[0];
    const float* W_in  = (const float*)d_in[1];
    const float* b_in  = (const float*)d_in[2];
    const float* W_out = (const float*)d_in[3];
    const float* b_out = (const float*)d_in[4];
    float* out = (float*)d_out;

    __half *xh, *wih, *woh, *qh, *ah;
    cudaGetSymbolAddress((void**)&xh,  g_xh);
    cudaGetSymbolAddress((void**)&wih, g_wih);
    cudaGetSymbolAddress((void**)&woh, g_woh);
    cudaGetSymbolAddress((void**)&qh,  g_qh);
    cudaGetSymbolAddress((void**)&ah,  g_ah);

    const int gemm_smem = G_NSTG * G_STG * (int)sizeof(__half);
    const int attn_smem = (A_QSZ + 2 * A_KVSTG) * (int)sizeof(__half);
    cudaFuncSetAttribute(gemm_mma, cudaFuncAttributeMaxDynamicSharedMemorySize, gemm_smem);
    cudaFuncSetAttribute(attn_mma, cudaFuncAttributeMaxDynamicSharedMemorySize, attn_smem);

    {
        int n1 = M_TOT * EMBD;
        cvt_h<<<n1 / 1024, 256>>>(x, xh, n1);
        int n2 = QKV_N * EMBD;
        cvt_h<<<n2 / 1024, 256>>>(W_in, wih, n2);
        int n3 = EMBD * EMBD;
        cvt_h<<<n3 / 1024, 256>>>(W_out, woh, n3);
    }
    // 1) qkv = x @ W_in^T + b_in  -> fp16 (Q cols pre-scaled)
    {
        dim3 grid(QKV_N / 128, M_TOT / 128);
        gemm_mma<<<grid, 256, gemm_smem>>>(xh, wih, b_in,
                                           nullptr, qh,
                                           QKV_N, EMBD, EMBD);
    }
    // 2) attention -> fp16
    {
        dim3 grid(SEQ / 128, NH, BATCH);
        attn_mma<<<grid, 256, attn_smem>>>(qh, ah);
    }
    // 3) out = attn @ W_out^T + b_out  -> fp32
    {
        dim3 grid(EMBD / 128, M_TOT / 128);
        gemm_mma<<<grid, 256, gemm_smem>>>(ah, woh, b_out,
                                           out, nullptr,
                                           EMBD, EMBD, 0);
    }
}

// round 16
// speedup vs baseline: 6.3227x; 1.0631x over previous
#include <cuda_runtime.h>
#include <cuda_fp16.h>
#include <cstdint>
#include <math.h>

#define EMBD   1024
#define NH     16
#define DH     64
#define BATCH  2
#define SEQ    2048
#define M_TOT  (BATCH * SEQ)   // 4096
#define QKV_N  (3 * EMBD)      // 3072

// ---------------------------------------------------------------------------
// Scratch (fp16; allocation-free rule: __device__ globals)
// ---------------------------------------------------------------------------
__device__ __half g_xh [M_TOT * EMBD];
__device__ __half g_wih[QKV_N * EMBD];
__device__ __half g_woh[EMBD * EMBD];
__device__ __half g_qh [M_TOT * QKV_N];
__device__ __half g_ah [M_TOT * EMBD];

// ---------------------------------------------------------------------------
// Helpers
// ---------------------------------------------------------------------------
__device__ __forceinline__ void mma_f16(float* c, const uint32_t* a,
                                        const uint32_t* b) {
    asm volatile(
        "mma.sync.aligned.m16n8k16.row.col.f32.f16.f16.f32 "
        "{%0,%1,%2,%3}, {%4,%5,%6,%7}, {%8,%9}, {%0,%1,%2,%3};"
        : "+f"(c[0]), "+f"(c[1]), "+f"(c[2]), "+f"(c[3])
        : "r"(a[0]), "r"(a[1]), "r"(a[2]), "r"(a[3]), "r"(b[0]), "r"(b[1]));
}

__device__ __forceinline__ void ldsm_x4(uint32_t& r0, uint32_t& r1,
                                        uint32_t& r2, uint32_t& r3,
                                        uint32_t a) {
    asm volatile("ldmatrix.sync.aligned.m8n8.x4.shared.b16 "
                 "{%0,%1,%2,%3}, [%4];"
                 : "=r"(r0), "=r"(r1), "=r"(r2), "=r"(r3) : "r"(a));
}

__device__ __forceinline__ void ldsm_x4_t(uint32_t& r0, uint32_t& r1,
                                          uint32_t& r2, uint32_t& r3,
                                          uint32_t a) {
    asm volatile("ldmatrix.sync.aligned.m8n8.x4.trans.shared.b16 "
                 "{%0,%1,%2,%3}, [%4];"
                 : "=r"(r0), "=r"(r1), "=r"(r2), "=r"(r3) : "r"(a));
}

__device__ __forceinline__ uint32_t smem_u32(const void* p) {
    uint32_t a;
    asm("{ .reg .u64 t; cvta.to.shared.u64 t, %1; cvt.u32.u64 %0, t; }"
        : "=r"(a) : "l"(p));
    return a;
}

__device__ __forceinline__ void cp16(uint32_t dst, const void* src) {
    asm volatile("cp.async.cg.shared.global [%0], [%1], 16;"
                 :: "r"(dst), "l"(src));
}
#define CP_COMMIT() asm volatile("cp.async.commit_group;")
#define CP_WAIT0()  asm volatile("cp.async.wait_group 0;")
#define CP_WAIT1()  asm volatile("cp.async.wait_group 1;")

// FFMA-only 2^x, degree-3 minimax on [-0.5,0.5] (rel err ~1.5e-4).
// Valid for x <= 0 (clamped at -80).
__device__ __forceinline__ float exp2_poly(float x) {
    x = fmaxf(x, -80.0f);
    float t = x + 12582912.0f;
    float n = t - 12582912.0f;
    float f = x - n;
    float p = 5.54906e-2f;
    p = fmaf(p, f, 2.40231e-1f);
    p = fmaf(p, f, 6.93147e-1f);
    p = fmaf(p, f, 1.0f);
    int e = (int)n;
    return p * __int_as_float((e + 127) << 23);
}

__device__ __forceinline__ uint32_t pk(__half2 v) {
    return *reinterpret_cast<uint32_t*>(&v);
}

// ---------------------------------------------------------------------------
// fp32 -> fp16 single
// ---------------------------------------------------------------------------
__global__ void cvt_h(const float* __restrict__ s, __half* __restrict__ h, int n)
{
    int i = (blockIdx.x * blockDim.x + threadIdx.x) * 4;
    if (i >= n) return;
    float4 v = *reinterpret_cast<const float4*>(&s[i]);
    *reinterpret_cast<__half2*>(&h[i])     = __floats2half2_rn(v.x, v.y);
    *reinterpret_cast<__half2*>(&h[i + 2]) = __floats2half2_rn(v.z, v.w);
}

// ---------------------------------------------------------------------------
// GEMM: C[m,n] = A[m,:]·B[n,:] + bias[n]   (single fp16 MMA)
// 128x128 tile, BK=64, cp.async 3-stage pipeline, ldmatrix fragment loads.
// Out: fp32 (Cf) or fp16 (Ch; cols < scale_lim get SCALE — the Q columns).
// ---------------------------------------------------------------------------
#define AS 72
#define G_TILE (128 * AS)          // halfs per operand tile (128 x 64 + pad)
#define G_STG  (2 * G_TILE)
#define G_NSTG 3

__global__ __launch_bounds__(256, 2)
void gemm_mma(const __half* __restrict__ A_g,
              const __half* __restrict__ B_g,
              const float* __restrict__ bias,
              float* __restrict__ Cf,
              __half* __restrict__ Ch,
              int N, int K, int scale_lim)
{
    extern __shared__ __half sm[];
    const uint32_t smb = smem_u32(sm);

    const int tid  = threadIdx.x;
    const int wid  = tid >> 5;
    const int lane = tid & 31;
    const int g    = lane >> 2;
    const int tg   = lane & 3;
    const int warp_m = (wid & 3) * 32;
    const int warp_n = (wid >> 2) * 64;
    const int bm = blockIdx.y * 128;
    const int bn = blockIdx.x * 128;

    const int l_row = tid >> 3;        // 0..31 (x4 via +32)
    const int l_q   = tid & 7;         // float4 col within 64-half row

    const int aRow = warp_m + (lane & 15);
    const int aCol = (lane >> 4) * 8;
    const int bRow = warp_n + (lane & 7) + ((lane >> 4) << 3);
    const int bCol = ((lane >> 3) & 1) * 8;

    float acc[2][8][4];
    #pragma unroll
    for (int mt = 0; mt < 2; mt++)
        #pragma unroll
        for (int nt = 0; nt < 8; nt++)
            #pragma unroll
            for (int i = 0; i < 4; i++) acc[mt][nt][i] = 0.0f;

    const int nch = K / 64;

    auto issue = [&](int ch) {
        int k0 = ch * 64;
        uint32_t sb = smb + (uint32_t)((ch % G_NSTG) * G_STG) * 2;
        #pragma unroll
        for (int i = 0; i < 4; i++) {
            int row = l_row + i * 32;
            uint32_t so = (uint32_t)(row * AS + l_q * 8) * 2;
            size_t oA = (size_t)(bm + row) * K + k0 + l_q * 8;
            size_t oB = (size_t)(bn + row) * K + k0 + l_q * 8;
            cp16(sb + so,              &A_g[oA]);
            cp16(sb + G_TILE * 2 + so, &B_g[oB]);
        }
    };

    issue(0); CP_COMMIT();
    issue(1); CP_COMMIT();

    for (int ch = 0; ch < nch; ch++) {
        CP_WAIT1();
        __syncthreads();
        if (ch + 2 < nch) issue(ch + 2);
        CP_COMMIT();

        uint32_t stg = smb + (uint32_t)((ch % G_NSTG) * G_STG) * 2;
        uint32_t aB = stg;
        uint32_t bB = stg + (uint32_t)G_TILE * 2;

        #pragma unroll
        for (int ks = 0; ks < 4; ks++) {
            uint32_t ah[2][4], bf[8][2];
            #pragma unroll
            for (int mt = 0; mt < 2; mt++) {
                uint32_t ao = (uint32_t)(((aRow + mt * 16) * AS) + ks * 16 + aCol) * 2;
                ldsm_x4(ah[mt][0], ah[mt][1], ah[mt][2], ah[mt][3], aB + ao);
            }
            #pragma unroll
            for (int q = 0; q < 4; q++) {
                uint32_t bo = (uint32_t)(((bRow + q * 16) * AS) + ks * 16 + bCol) * 2;
                ldsm_x4(bf[2*q][0], bf[2*q][1], bf[2*q+1][0], bf[2*q+1][1], bB + bo);
            }
            #pragma unroll
            for (int nt = 0; nt < 8; nt++) {
                #pragma unroll
                for (int mt = 0; mt < 2; mt++)
                    mma_f16(acc[mt][nt], ah[mt], bf[nt]);
            }
        }
    }

    const float SCALE = 0.18033688f;   // 0.125 * log2(e)
    #pragma unroll
    for (int mt = 0; mt < 2; mt++) {
        int r0 = bm + warp_m + mt * 16 + g;
        #pragma unroll
        for (int nt = 0; nt < 8; nt++) {
            int col = bn + warp_n + nt * 8 + tg * 2;
            float b0 = __ldg(&bias[col]), b1 = __ldg(&bias[col + 1]);
            float v0 = acc[mt][nt][0] + b0, v1 = acc[mt][nt][1] + b1;
            float v2 = acc[mt][nt][2] + b0, v3 = acc[mt][nt][3] + b1;
            if (Cf) {
                *reinterpret_cast<float2*>(&Cf[(size_t)r0 * N + col])
                    = make_float2(v0, v1);
                *reinterpret_cast<float2*>(&Cf[(size_t)(r0 + 8) * N + col])
                    = make_float2(v2, v3);
            } else {
                if (col < scale_lim) { v0 *= SCALE; v1 *= SCALE; v2 *= SCALE; v3 *= SCALE; }
                *reinterpret_cast<uint32_t*>(&Ch[(size_t)r0 * N + col])
                    = pk(__floats2half2_rn(v0, v1));
                *reinterpret_cast<uint32_t*>(&Ch[(size_t)(r0 + 8) * N + col])
                    = pk(__floats2half2_rn(v2, v3));
            }
        }
    }
}

// ---------------------------------------------------------------------------
// Flash attention, cp.async 2-stage K/V pipeline, 2 CTAs/SM.
// S=Q·K (single fp16, K frags via ldmatrix), PV=P·V (single fp16 P; V via
// ldmatrix.trans).  Q pre-scaled by 0.125*log2e -> exp2-domain softmax.
// ---------------------------------------------------------------------------
#define QS 72
#define VS 72
#define KT 64
#define A_QSZ   (128 * QS)
#define A_KVSTG (KT * QS + KT * VS)

__global__ __launch_bounds__(256, 2)
void attn_mma(const __half* __restrict__ qkvh,
              __half* __restrict__ oh)
{
    extern __shared__ __half sm[];
    __half* sQh = sm;                       // [128][QS]

    const int tid  = threadIdx.x;
    const int wid  = tid >> 5;
    const int lane = tid & 31;
    const int g    = lane >> 2;
    const int tg   = lane & 3;
    const int q0 = blockIdx.x * 128;
    const int h  = blockIdx.y;
    const int b  = blockIdx.z;
    const size_t rowbase = (size_t)b * SEQ;

    const uint32_t smb = smem_u32(sm);
    const uint32_t kv_base_u = smb + (uint32_t)A_QSZ * 2;

    const int kRow = (lane & 7) + ((lane >> 4) << 3);
    const int kCol = ((lane >> 3) & 1) * 8;
    const int lr = lane & 7, lq = (lane >> 3) & 1, lh2 = lane >> 4;
    const uint32_t voff0 = (uint32_t)(((lq * 8 + lr) * VS + lh2 * 8) * 2);

    const int l_r = tid >> 3;
    const int l_q = tid & 7;

    auto issue = [&](int kt) {
        uint32_t sb = kv_base_u + (uint32_t)((kt & 1) * A_KVSTG) * 2;
        #pragma unroll
        for (int i = 0; i < 2; i++) {
            int r = l_r + i * 32;
            size_t koff = (rowbase + kt * KT + r) * QKV_N + EMBD + h * DH + l_q * 8;
            size_t voff = koff + EMBD;
            cp16(sb + (uint32_t)(r * QS + l_q * 8) * 2, &qkvh[koff]);
            cp16(sb + (uint32_t)(KT * QS + r * VS + l_q * 8) * 2, &qkvh[voff]);
        }
    };

    issue(0);
    CP_COMMIT();

    // Load Q tile once
    #pragma unroll
    for (int i = 0; i < 4; i++) {
        int u = tid + i * 256, r = u >> 3, q = u & 7;
        size_t off = (rowbase + q0 + r) * QKV_N + h * DH + q * 8;
        *reinterpret_cast<uint4*>(&sQh[r * QS + q * 8]) =
            *reinterpret_cast<const uint4*>(&qkvh[off]);
    }
    __syncthreads();

    uint32_t qh[4][4];
    {
        int r = wid * 16 + (lane & 15);
        int co = (lane >> 4) * 8;
        #pragma unroll
        for (int ks = 0; ks < 4; ks++) {
            uint32_t ao = (uint32_t)(r * QS + ks * 16 + co) * 2;
            ldsm_x4(qh[ks][0], qh[ks][1], qh[ks][2], qh[ks][3], smb + ao);
        }
    }

    float oacc[8][4];
    #pragma unroll
    for (int nt = 0; nt < 8; nt++)
        #pragma unroll
        for (int i = 0; i < 4; i++) oacc[nt][i] = 0.0f;
    float m0 = -1e30f, m1 = -1e30f, l0 = 0.0f, l1 = 0.0f;

    const int nkt = SEQ / KT;
    for (int kt = 0; kt < nkt; kt++) {
        CP_WAIT0();
        __syncthreads();
        if (kt + 1 < nkt) issue(kt + 1);
        CP_COMMIT();

        const uint32_t sK_u = kv_base_u + (uint32_t)((kt & 1) * A_KVSTG) * 2;
        const uint32_t sV_u = sK_u + (uint32_t)(KT * QS) * 2;

        // S = Q K^T (single fp16 MMA; K frags via ldmatrix)
        float sacc[8][4];
        #pragma unroll
        for (int nt = 0; nt < 8; nt++)
            #pragma unroll
            for (int i = 0; i < 4; i++) sacc[nt][i] = 0.0f;
        #pragma unroll
        for (int ks = 0; ks < 4; ks++) {
            uint32_t kf[8][2];
            #pragma unroll
            for (int q = 0; q < 4; q++) {
                uint32_t ko = (uint32_t)(((kRow + q * 16) * QS) + ks * 16 + kCol) * 2;
                ldsm_x4(kf[2*q][0], kf[2*q][1], kf[2*q+1][0], kf[2*q+1][1], sK_u + ko);
            }
            #pragma unroll
            for (int nt = 0; nt < 8; nt++)
                mma_f16(sacc[nt], qh[ks], kf[nt]);
        }

        // Online softmax (log2 domain)
        float mx0 = -1e30f, mx1 = -1e30f;
        #pragma unroll
        for (int nt = 0; nt < 8; nt++) {
            mx0 = fmaxf(mx0, fmaxf(sacc[nt][0], sacc[nt][1]));
            mx1 = fmaxf(mx1, fmaxf(sacc[nt][2], sacc[nt][3]));
        }
        mx0 = fmaxf(mx0, __shfl_xor_sync(0xffffffffu, mx0, 1));
        mx0 = fmaxf(mx0, __shfl_xor_sync(0xffffffffu, mx0, 2));
        mx1 = fmaxf(mx1, __shfl_xor_sync(0xffffffffu, mx1, 1));
        mx1 = fmaxf(mx1, __shfl_xor_sync(0xffffffffu, mx1, 2));
        float nm0 = fmaxf(m0, mx0), nm1 = fmaxf(m1, mx1);
        float a0 = exp2_poly(m0 - nm0), a1 = exp2_poly(m1 - nm1);

        float rs0 = 0.0f, rs1 = 0.0f;
        uint32_t pah[8], pbh[8];
        #pragma unroll
        for (int nt = 0; nt < 8; nt++) {
            float p0 = exp2_poly(sacc[nt][0] - nm0);
            float p1 = exp2_poly(sacc[nt][1] - nm0);
            float p2 = exp2_poly(sacc[nt][2] - nm1);
            float p3 = exp2_poly(sacc[nt][3] - nm1);
            rs0 += p0 + p1; rs1 += p2 + p3;
            pah[nt] = pk(__floats2half2_rn(p0, p1));
            pbh[nt] = pk(__floats2half2_rn(p2, p3));
        }
        rs0 += __shfl_xor_sync(0xffffffffu, rs0, 1);
        rs0 += __shfl_xor_sync(0xffffffffu, rs0, 2);
        rs1 += __shfl_xor_sync(0xffffffffu, rs1, 1);
        rs1 += __shfl_xor_sync(0xffffffffu, rs1, 2);
        l0 = l0 * a0 + rs0;
        l1 = l1 * a1 + rs1;
        m0 = nm0; m1 = nm1;
        #pragma unroll
        for (int nt = 0; nt < 8; nt++) {
            oacc[nt][0] *= a0; oacc[nt][1] *= a0;
            oacc[nt][2] *= a1; oacc[nt][3] *= a1;
        }

        // O += P V  (V fragments via ldmatrix.trans)
        #pragma unroll
        for (int ks = 0; ks < 4; ks++) {
            uint32_t pAh[4] = {pah[2*ks], pbh[2*ks], pah[2*ks+1], pbh[2*ks+1]};
            #pragma unroll
            for (int ntp = 0; ntp < 4; ntp++) {
                uint32_t v0, v1, v2, v3;
                uint32_t addr = sV_u + voff0
                              + (uint32_t)((ks * 16 * VS + ntp * 16) * 2);
                ldsm_x4_t(v0, v1, v2, v3, addr);
                uint32_t vb0[2] = {v0, v1};
                uint32_t vb1[2] = {v2, v3};
                mma_f16(oacc[2*ntp],     pAh, vb0);
                mma_f16(oacc[2*ntp + 1], pAh, vb1);
            }
        }
    }

    // Epilogue: normalize, store fp16
    float inv0 = 1.0f / l0, inv1 = 1.0f / l1;
    int qrow = q0 + wid * 16 + g;
    #pragma unroll
    for (int nt = 0; nt < 8; nt++) {
        int col = h * DH + nt * 8 + tg * 2;
        float v0 = oacc[nt][0] * inv0, v1 = oacc[nt][1] * inv0;
        float v2 = oacc[nt][2] * inv1, v3 = oacc[nt][3] * inv1;
        *reinterpret_cast<uint32_t*>(&oh[(rowbase + qrow) * EMBD + col])
            = pk(__floats2half2_rn(v0, v1));
        *reinterpret_cast<uint32_t*>(&oh[(rowbase + qrow + 8) * EMBD + col])
            = pk(__floats2half2_rn(v2, v3));
    }
}

// ---------------------------------------------------------------------------
// Launch
// ---------------------------------------------------------------------------
extern "C" void kernel_launch(void* const* d_in, const int* in_sizes, int n_in,
                              void* d_out, int out_size)
{
    const float* x     = (const float*)d_in[0];
    const float* W_in  = (const float*)d_in[1];
    const float* b_in  = (const float*)d_in[2];
    const float* W_out = (const float*)d_in[3];
    const float* b_out = (const float*)d_in[4];
    float* out = (float*)d_out;

    __half *xh, *wih, *woh, *qh, *ah;
    cudaGetSymbolAddress((void**)&xh,  g_xh);
    cudaGetSymbolAddress((void**)&wih, g_wih);
    cudaGetSymbolAddress((void**)&woh, g_woh);
    cudaGetSymbolAddress((void**)&qh,  g_qh);
    cudaGetSymbolAddress((void**)&ah,  g_ah);

    const int gemm_smem = G_NSTG * G_STG * (int)sizeof(__half);   // 110,592 B
    const int attn_smem = (A_QSZ + 2 * A_KVSTG) * (int)sizeof(__half);
    cudaFuncSetAttribute(gemm_mma, cudaFuncAttributeMaxDynamicSharedMemorySize, gemm_smem);
    cudaFuncSetAttribute(attn_mma, cudaFuncAttributeMaxDynamicSharedMemorySize, attn_smem);

    {
        int n1 = M_TOT * EMBD;
        cvt_h<<<n1 / 1024, 256>>>(x, xh, n1);
        int n2 = QKV_N * EMBD;
        cvt_h<<<n2 / 1024, 256>>>(W_in, wih, n2);
        int n3 = EMBD * EMBD;
        cvt_h<<<n3 / 1024, 256>>>(W_out, woh, n3);
    }
    // 1) qkv = x @ W_in^T + b_in  -> fp16 (Q cols pre-scaled)
    {
        dim3 grid(QKV_N / 128, M_TOT / 128);
        gemm_mma<<<grid, 256, gemm_smem>>>(xh, wih, b_in,
                                           nullptr, qh,
                                           QKV_N, EMBD, EMBD);
    }
    // 2) attention -> fp16
    {
        dim3 grid(SEQ / 128, NH, BATCH);
        attn_mma<<<grid, 256, attn_smem>>>(qh, ah);
    }
    // 3) out = attn @ W_out^T + b_out  -> fp32
    {
        dim3 grid(EMBD / 128, M_TOT / 128);
        gemm_mma<<<grid, 256, gemm_smem>>>(ah, woh, b_out,
                                           out, nullptr,
                                           EMBD, EMBD, 0);
    }
}